// round 4
// baseline (speedup 1.0000x reference)
#include <cuda_runtime.h>
#include <cuda_bf16.h>
#include <math.h>

typedef unsigned long long ull;

#define MAXN 131072
#define MAXE 262144
#define MAXB 4096

// ---------------- device scratch (no allocs allowed) ----------------
__device__ float g_msum[(size_t)MAXN * 64];
__device__ float g_cnt[MAXN];              // reused as attention e-buffer later
__device__ float g_out[(size_t)MAXN * 64];
__device__ float g_S[MAXB * 192];          // per graph: [0:128]=q_star, [128:192]=hl
__device__ float g_cl[MAXB * 64];
__device__ int   g_seg[MAXB + 1];
__device__ ull   g_WrzT[32 * 128];         // packed pairs [k2][j], combined wih+whh rows 0..127
__device__ ull   g_WinT[32 * 64];          // wih rows 128..191, packed pairs [k2][j2]
__device__ ull   g_WhnT[32 * 64];          // whh rows 128..191
__device__ float g_brz[128], g_binn[64], g_bhn[64];

// ---------------- helpers ----------------
__device__ __forceinline__ ull dup2(float a) {
    ull r; asm("mov.b64 %0, {%1, %1};" : "=l"(r) : "f"(a)); return r;
}
__device__ __forceinline__ ull pack2(float a, float b) {
    ull r; asm("mov.b64 %0, {%1, %2};" : "=l"(r) : "f"(a), "f"(b)); return r;
}
__device__ __forceinline__ ull f2fma(ull a, ull b, ull c) {
    ull d; asm("fma.rn.f32x2 %0, %1, %2, %3;" : "=l"(d) : "l"(a), "l"(b), "l"(c)); return d;
}
__device__ __forceinline__ float2 unpk(ull a) {
    float2 v; asm("mov.b64 {%0, %1}, %2;" : "=f"(v.x), "=f"(v.y) : "l"(a)); return v;
}
__device__ __forceinline__ float sigm(float x) { return 1.0f / (1.0f + __expf(-x)); }

// ---------------- zero scratch ----------------
__global__ void zero_kernel(int N, int B) {
    int idx = blockIdx.x * blockDim.x + threadIdx.x;
    int stride = gridDim.x * blockDim.x;
    int nm = N * 64;
    for (int i = idx; i < nm; i += stride) g_msum[i] = 0.0f;
    for (int i = idx; i < N; i += stride) g_cnt[i] = 0.0f;
    int ns = B * 192;
    for (int i = idx; i < ns; i += stride) g_S[i] = 0.0f;
    int nc = B * 64;
    for (int i = idx; i < nc; i += stride) g_cl[i] = 0.0f;
}

// ---------------- segment offsets (batch sorted) ----------------
__global__ void seg_kernel(const int* __restrict__ batch, int N, int B) {
    int b = blockIdx.x * blockDim.x + threadIdx.x;
    if (b > B) return;
    int lo = 0, hi = N;
    while (lo < hi) { int mid = (lo + hi) >> 1; if (batch[mid] < b) lo = mid + 1; else hi = mid; }
    g_seg[b] = lo;
}

// ---------------- GRU weight prep: packed transposed pairs ----------------
__global__ void gru_prep(const float* __restrict__ wih, const float* __restrict__ whh,
                         const float* __restrict__ bih, const float* __restrict__ bhh) {
    int t = blockIdx.x * blockDim.x + threadIdx.x;
    if (t < 4096) {
        int k2 = t >> 7, j = t & 127;
        g_WrzT[t] = pack2(wih[j * 64 + 2 * k2] + whh[j * 64 + 2 * k2],
                          wih[j * 64 + 2 * k2 + 1] + whh[j * 64 + 2 * k2 + 1]);
    } else if (t < 6144) {                      // FIX: 2048 entries, k2 in [0,32)
        int u = t - 4096;
        int k2 = u >> 6, j2 = u & 63;
        g_WinT[u] = pack2(wih[(128 + j2) * 64 + 2 * k2], wih[(128 + j2) * 64 + 2 * k2 + 1]);
        g_WhnT[u] = pack2(whh[(128 + j2) * 64 + 2 * k2], whh[(128 + j2) * 64 + 2 * k2 + 1]);
    } else if (t < 6272) {
        int u = t - 6144;
        g_brz[u] = bih[u] + bhh[u];
    } else if (t < 6336) {
        int u = t - 6272;
        g_binn[u] = bih[128 + u];
        g_bhn[u]  = bhh[128 + u];
    }
}

// ---------------- edge kernel: fused edge-MLP + Z-GEMM + scatter ----------------
// C[64e x 64h] = Z[64e x 2048k] @ W2[2048k x 64h], Z[e, m*16+d] = relu_hid[e,m]*xsrc[e,d]
// W2 is w_e2 reinterpreted as [2048,64] row-major.
__global__ void __launch_bounds__(128) edge_kernel(
    const float* __restrict__ x, const float* __restrict__ edge_attr,
    const int* __restrict__ edge_index,
    const float* __restrict__ w_e1, const float* __restrict__ b_e1,
    const float* __restrict__ w_e2, const float* __restrict__ b_e2, int E)
{
    __shared__ float Zs[64 * 68];    // [kl][e], stride 68
    __shared__ float Wss[64 * 64];   // [kl][h]
    __shared__ float xsS[16 * 65];   // [d][e]
    __shared__ float eaS[4 * 65];    // [c][e]
    __shared__ int   dstS[64];

    int t = threadIdx.x;
    int e0 = blockIdx.x * 64;

    if (t < 64) {
        int e = e0 + t;
        int s = 0, dd = -1;
        float4 ea = make_float4(0.f, 0.f, 0.f, 0.f);
        if (e < E) {
            s  = edge_index[e];
            dd = edge_index[E + e];
            ea = reinterpret_cast<const float4*>(edge_attr)[e];
        }
        dstS[t] = dd;
        eaS[t] = ea.x; eaS[65 + t] = ea.y; eaS[130 + t] = ea.z; eaS[195 + t] = ea.w;
        const float4* xr = reinterpret_cast<const float4*>(x + (size_t)s * 16);
        #pragma unroll
        for (int q = 0; q < 4; ++q) {
            float4 v = (e < E) ? xr[q] : make_float4(0.f, 0.f, 0.f, 0.f);
            xsS[(q * 4 + 0) * 65 + t] = v.x;
            xsS[(q * 4 + 1) * 65 + t] = v.y;
            xsS[(q * 4 + 2) * 65 + t] = v.z;
            xsS[(q * 4 + 3) * 65 + t] = v.w;
        }
        if (dd >= 0) atomicAdd(&g_cnt[dd], 1.0f);
    }

    int tx = t & 15, ty = t >> 4;     // 4 edges per tx, 8 h per ty
    ull acc[4][4];
    #pragma unroll
    for (int i = 0; i < 4; ++i)
        #pragma unroll
        for (int j = 0; j < 4; ++j) acc[i][j] = 0ull;

    int zrowi = t >> 1;               // Z row within chunk (0..63)
    int half  = (t & 1) * 32;         // which 32 edges this thread forms
    int dloc  = zrowi & 15;
    int mbase = zrowi >> 4;

    for (int kc = 0; kc < 32; ++kc) {
        __syncthreads();
        // stage W2 chunk [64k x 64h] (coalesced, L2-resident)
        {
            const float4* wsrc = reinterpret_cast<const float4*>(w_e2) + kc * 1024;
            float4* wdst = reinterpret_cast<float4*>(Wss);
            #pragma unroll
            for (int i = 0; i < 8; ++i) wdst[t + i * 128] = wsrc[t + i * 128];
        }
        // form Z chunk (recompute hid on the fly)
        {
            int m = kc * 4 + mbase;
            float w10 = w_e1[m], w11 = w_e1[128 + m], w12 = w_e1[256 + m], w13 = w_e1[384 + m];
            float b1m = b_e1[m];
            float4* zrow = reinterpret_cast<float4*>(Zs + zrowi * 68 + half);
            #pragma unroll
            for (int eg = 0; eg < 8; ++eg) {
                float zz[4];
                #pragma unroll
                for (int c = 0; c < 4; ++c) {
                    int e = half + eg * 4 + c;
                    float hv = fmaf(eaS[195 + e], w13, fmaf(eaS[130 + e], w12,
                               fmaf(eaS[65 + e], w11, fmaf(eaS[e], w10, b1m))));
                    hv = fmaxf(hv, 0.0f);
                    zz[c] = hv * xsS[dloc * 65 + e];
                }
                zrow[eg] = make_float4(zz[0], zz[1], zz[2], zz[3]);
            }
        }
        __syncthreads();
        // GEMM micro-kernel: FFMA2
        #pragma unroll 8
        for (int kl = 0; kl < 64; ++kl) {
            float4 a = reinterpret_cast<const float4*>(Zs + kl * 68)[tx];
            const ulonglong2* bp = reinterpret_cast<const ulonglong2*>(Wss + (kl << 6) + (ty << 3));
            ulonglong2 b01 = bp[0];
            ulonglong2 b23 = bp[1];
            ull a0 = dup2(a.x), a1 = dup2(a.y), a2 = dup2(a.z), a3 = dup2(a.w);
            acc[0][0] = f2fma(a0, b01.x, acc[0][0]); acc[0][1] = f2fma(a0, b01.y, acc[0][1]);
            acc[0][2] = f2fma(a0, b23.x, acc[0][2]); acc[0][3] = f2fma(a0, b23.y, acc[0][3]);
            acc[1][0] = f2fma(a1, b01.x, acc[1][0]); acc[1][1] = f2fma(a1, b01.y, acc[1][1]);
            acc[1][2] = f2fma(a1, b23.x, acc[1][2]); acc[1][3] = f2fma(a1, b23.y, acc[1][3]);
            acc[2][0] = f2fma(a2, b01.x, acc[2][0]); acc[2][1] = f2fma(a2, b01.y, acc[2][1]);
            acc[2][2] = f2fma(a2, b23.x, acc[2][2]); acc[2][3] = f2fma(a2, b23.y, acc[2][3]);
            acc[3][0] = f2fma(a3, b01.x, acc[3][0]); acc[3][1] = f2fma(a3, b01.y, acc[3][1]);
            acc[3][2] = f2fma(a3, b23.x, acc[3][2]); acc[3][3] = f2fma(a3, b23.y, acc[3][3]);
        }
    }

    // epilogue: add b_e2 contraction, scatter-add into msum[dst]
    #pragma unroll
    for (int i = 0; i < 4; ++i) {
        int le = tx * 4 + i;
        int dd = dstS[le];
        if (dd < 0) continue;
        float bias[8];
        #pragma unroll
        for (int j = 0; j < 8; ++j) bias[j] = 0.0f;
        #pragma unroll
        for (int d = 0; d < 16; ++d) {
            float xv = xsS[d * 65 + le];
            const float* bptr = b_e2 + d * 64 + (ty << 3);
            #pragma unroll
            for (int j = 0; j < 8; ++j) bias[j] = fmaf(xv, bptr[j], bias[j]);
        }
        float* mrow = g_msum + (size_t)dd * 64 + (ty << 3);
        #pragma unroll
        for (int jp = 0; jp < 4; ++jp) {
            float2 v = unpk(acc[i][jp]);
            atomicAdd(mrow + jp * 2,     v.x + bias[jp * 2]);
            atomicAdd(mrow + jp * 2 + 1, v.y + bias[jp * 2 + 1]);
        }
    }
}

// ---------------- node update: out = relu(msum/max(cnt,1) + x@root + bias) ----------------
__global__ void __launch_bounds__(256) node_kernel(
    const float* __restrict__ x, const float* __restrict__ root,
    const float* __restrict__ conv_bias, int N)
{
    __shared__ float rootS[1024];
    __shared__ float cb[64];
    int t = threadIdx.x;
    for (int i = t; i < 1024; i += 256) rootS[i] = root[i];
    if (t < 64) cb[t] = conv_bias[t];
    __syncthreads();
    int n = blockIdx.x * 4 + (t >> 6);
    int h = t & 63;
    if (n >= N) return;
    const float* xr = x + (size_t)n * 16;
    float acc = cb[h];
    #pragma unroll
    for (int d = 0; d < 16; ++d) acc = fmaf(xr[d], rootS[d * 64 + h], acc);
    float c = fmaxf(g_cnt[n], 1.0f);
    float v = g_msum[(size_t)n * 64 + h] / c + acc;
    g_out[(size_t)n * 64 + h] = fmaxf(v, 0.0f);
}

// ---------------- GRU step (in-place on g_out; input == hidden identity) ----------------
__global__ void __launch_bounds__(128) gru_kernel(int N)
{
    __shared__ ull   hPs[4][32];
    __shared__ float rzS[4][128];
    int t = threadIdx.x;

    ull wA[32], wB[32];
    float bA, bB;
    if (t < 64) {
        #pragma unroll
        for (int k2 = 0; k2 < 32; ++k2) {
            wA[k2] = g_WrzT[k2 * 128 + t];
            wB[k2] = g_WrzT[k2 * 128 + 64 + t];
        }
        bA = g_brz[t]; bB = g_brz[64 + t];
    } else {
        int jj = t - 64;
        #pragma unroll
        for (int k2 = 0; k2 < 32; ++k2) {
            wA[k2] = g_WinT[k2 * 64 + jj];
            wB[k2] = g_WhnT[k2 * 64 + jj];
        }
        bA = g_binn[jj]; bB = g_bhn[jj];
    }

    for (int nb = blockIdx.x * 4; nb < N; nb += gridDim.x * 4) {
        __syncthreads();
        {
            int ln = t >> 5, k2 = t & 31;
            int n = nb + ln;
            if (t < 128 && n < N)
                hPs[ln][k2] = reinterpret_cast<const ull*>(g_out + (size_t)n * 64)[k2];
        }
        __syncthreads();
        ull accA[4] = {0ull, 0ull, 0ull, 0ull};
        ull accB[4] = {0ull, 0ull, 0ull, 0ull};
        #pragma unroll
        for (int k2 = 0; k2 < 32; ++k2) {
            #pragma unroll
            for (int i = 0; i < 4; ++i) {
                ull hv = hPs[i][k2];
                accA[i] = f2fma(wA[k2], hv, accA[i]);
                accB[i] = f2fma(wB[k2], hv, accB[i]);
            }
        }
        if (t < 64) {
            #pragma unroll
            for (int i = 0; i < 4; ++i) {
                float2 va = unpk(accA[i]), vb = unpk(accB[i]);
                rzS[i][t]      = sigm(va.x + va.y + bA);
                rzS[i][64 + t] = sigm(vb.x + vb.y + bB);
            }
        }
        __syncthreads();
        if (t >= 64) {
            int jj = t - 64;
            #pragma unroll
            for (int i = 0; i < 4; ++i) {
                int n = nb + i;
                if (n >= N) continue;
                float2 va = unpk(accA[i]), vb = unpk(accB[i]);
                float inn = va.x + va.y + bA;
                float hn  = vb.x + vb.y + bB;
                float r = rzS[i][jj], z = rzS[i][64 + jj];
                float nv = tanhf(inn + r * hn);
                float2 hp = unpk(hPs[i][jj >> 1]);
                float hold = (jj & 1) ? hp.y : hp.x;
                g_out[(size_t)n * 64 + jj] = (1.0f - z) * nv + z * hold;
            }
        }
    }
}

// ---------------- Set2Set LSTM step (8 graphs / 256-thread block) ----------------
__global__ void __launch_bounds__(256) lstm_kernel(
    const float* __restrict__ wih, const float* __restrict__ whh,
    const float* __restrict__ bih, const float* __restrict__ bhh, int B)
{
    __shared__ float wst[256 * 33];
    __shared__ float qsm[8 * 128];
    __shared__ float hsm[8 * 64];
    __shared__ float gsm[8 * 256];
    int t = threadIdx.x;
    int b0 = blockIdx.x * 8;

    for (int i = t; i < 8 * 128; i += 256) {
        int g = i >> 7, k = i & 127;
        qsm[i] = (b0 + g < B) ? g_S[(b0 + g) * 192 + k] : 0.0f;
    }
    for (int i = t; i < 8 * 64; i += 256) {
        int g = i >> 6, k = i & 63;
        hsm[i] = (b0 + g < B) ? g_S[(b0 + g) * 192 + 128 + k] : 0.0f;
    }

    float acc[8];
    float bsum = bih[t] + bhh[t];
    #pragma unroll
    for (int g = 0; g < 8; ++g) acc[g] = bsum;

    for (int c = 0; c < 4; ++c) {           // wih chunks over 128 k
        __syncthreads();
        for (int i = t; i < 8192; i += 256) {
            int j = i >> 5, kk = i & 31;
            wst[j * 33 + kk] = wih[j * 128 + c * 32 + kk];
        }
        __syncthreads();
        #pragma unroll 8
        for (int kk = 0; kk < 32; ++kk) {
            float w = wst[t * 33 + kk];
            #pragma unroll
            for (int g = 0; g < 8; ++g)
                acc[g] = fmaf(w, qsm[g * 128 + c * 32 + kk], acc[g]);
        }
    }
    for (int c = 0; c < 2; ++c) {           // whh chunks over 64 k
        __syncthreads();
        for (int i = t; i < 8192; i += 256) {
            int j = i >> 5, kk = i & 31;
            wst[j * 33 + kk] = whh[j * 64 + c * 32 + kk];
        }
        __syncthreads();
        #pragma unroll 8
        for (int kk = 0; kk < 32; ++kk) {
            float w = wst[t * 33 + kk];
            #pragma unroll
            for (int g = 0; g < 8; ++g)
                acc[g] = fmaf(w, hsm[g * 64 + c * 32 + kk], acc[g]);
        }
    }

    #pragma unroll
    for (int g = 0; g < 8; ++g) gsm[g * 256 + t] = acc[g];
    __syncthreads();

    for (int i = t; i < 8 * 64; i += 256) {
        int g = i >> 6, hh = i & 63;
        int b = b0 + g;
        if (b >= B) continue;
        float ig = sigm(gsm[g * 256 + hh]);
        float fg = sigm(gsm[g * 256 + 64 + hh]);
        float gg = tanhf(gsm[g * 256 + 128 + hh]);
        float og = sigm(gsm[g * 256 + 192 + hh]);
        float cnew = fg * g_cl[b * 64 + hh] + ig * gg;
        g_cl[b * 64 + hh] = cnew;
        g_S[b * 192 + 128 + hh] = og * tanhf(cnew);   // hl (= q)
    }
}

// ---------------- Set2Set attention step (1 graph / 64-thread block) ----------------
__global__ void __launch_bounds__(64) attn_kernel(int B)
{
    __shared__ float qs[64];
    __shared__ float wm[2], ws[2];
    int t = threadIdx.x, b = blockIdx.x;
    qs[t] = g_S[b * 192 + 128 + t];
    __syncthreads();
    int n0 = g_seg[b], n1 = g_seg[b + 1];
    int w = t >> 5, lid = t & 31;

    // pass 1: e[n] = dot(out[n], q), online max/sum per warp; e-buffer = g_cnt
    float mr = -1e30f, sr = 0.0f;
    for (int n = n0 + w; n < n1; n += 2) {
        const float* orow = g_out + (size_t)n * 64;
        float p = orow[lid] * qs[lid] + orow[32 + lid] * qs[32 + lid];
        #pragma unroll
        for (int off = 16; off; off >>= 1) p += __shfl_xor_sync(0xffffffffu, p, off);
        if (lid == 0) g_cnt[n] = p;
        if (p > mr) { sr *= __expf(mr - p); mr = p; }
        sr += __expf(p - mr);
    }
    if (lid == 0) { wm[w] = mr; ws[w] = sr; }
    __syncthreads();
    float m = fmaxf(wm[0], wm[1]);
    float denom = ws[0] * __expf(wm[0] - m) + ws[1] * __expf(wm[1] - m);

    // pass 2: r_g[t] = sum a_n * out[n][t]
    float rg = 0.0f;
    for (int n = n0; n < n1; ++n) {
        float a = __expf(g_cnt[n] - m);
        rg = fmaf(a, g_out[(size_t)n * 64 + t], rg);
    }
    if (n1 > n0) rg /= denom;
    g_S[b * 192 + t]      = qs[t];   // q_star[0:64] = q
    g_S[b * 192 + 64 + t] = rg;      // q_star[64:128] = r_g
}

// ---------------- readout: y = relu(q_star@fc1 + b) @ fc2 + b2 ----------------
__global__ void __launch_bounds__(64) readout_kernel(
    const float* __restrict__ fc1_w, const float* __restrict__ fc1_b,
    const float* __restrict__ fc2_w, const float* __restrict__ fc2_b,
    float* __restrict__ y, int B)
{
    __shared__ float qsm[8 * 128];
    __shared__ float red[2];
    int t = threadIdx.x;
    int b0 = blockIdx.x * 8;
    for (int i = t; i < 1024; i += 64) {
        int g = i >> 7, k = i & 127;
        qsm[i] = (b0 + g < B) ? g_S[(b0 + g) * 192 + k] : 0.0f;
    }
    __syncthreads();
    float w2 = fc2_w[t];
    float b1 = fc1_b[t];
    for (int g = 0; g < 8; ++g) {
        float a = b1;
        #pragma unroll 8
        for (int k = 0; k < 128; ++k) a = fmaf(qsm[g * 128 + k], fc1_w[k * 64 + t], a);
        a = fmaxf(a, 0.0f);
        float p = a * w2;
        #pragma unroll
        for (int off = 16; off; off >>= 1) p += __shfl_xor_sync(0xffffffffu, p, off);
        if ((t & 31) == 0) red[t >> 5] = p;
        __syncthreads();
        if (t == 0 && b0 + g < B) y[b0 + g] = red[0] + red[1] + fc2_b[0];
        __syncthreads();
    }
}

// ---------------- launch ----------------
extern "C" void kernel_launch(void* const* d_in, const int* in_sizes, int n_in,
                              void* d_out, int out_size)
{
    const float* x         = (const float*)d_in[0];
    const float* edge_attr = (const float*)d_in[1];
    const int*   edge_index= (const int*)  d_in[2];
    const int*   batch     = (const int*)  d_in[3];
    const float* w_e1      = (const float*)d_in[4];
    const float* b_e1      = (const float*)d_in[5];
    const float* w_e2      = (const float*)d_in[6];
    const float* b_e2      = (const float*)d_in[7];
    const float* root      = (const float*)d_in[8];
    const float* conv_bias = (const float*)d_in[9];
    const float* gru_wih   = (const float*)d_in[10];
    const float* gru_whh   = (const float*)d_in[11];
    const float* gru_bih   = (const float*)d_in[12];
    const float* gru_bhh   = (const float*)d_in[13];
    const float* lstm_wih  = (const float*)d_in[14];
    const float* lstm_whh  = (const float*)d_in[15];
    const float* lstm_bih  = (const float*)d_in[16];
    const float* lstm_bhh  = (const float*)d_in[17];
    const float* fc1_w     = (const float*)d_in[18];
    const float* fc1_b     = (const float*)d_in[19];
    const float* fc2_w     = (const float*)d_in[20];
    const float* fc2_b     = (const float*)d_in[21];
    float* y = (float*)d_out;

    int N = in_sizes[0] / 16;
    int E = in_sizes[1] / 4;
    int B = out_size;

    zero_kernel<<<1024, 256>>>(N, B);
    seg_kernel<<<(B + 1 + 127) / 128, 128>>>(batch, N, B);
    gru_prep<<<25, 256>>>(gru_wih, gru_whh, gru_bih, gru_bhh);
    edge_kernel<<<(E + 63) / 64, 128>>>(x, edge_attr, edge_index, w_e1, b_e1, w_e2, b_e2, E);
    node_kernel<<<(N + 3) / 4, 256>>>(x, root, conv_bias, N);
    for (int i = 0; i < 3; ++i) gru_kernel<<<592, 128>>>(N);
    for (int i = 0; i < 3; ++i) {
        lstm_kernel<<<(B + 7) / 8, 256>>>(lstm_wih, lstm_whh, lstm_bih, lstm_bhh, B);
        attn_kernel<<<B, 64>>>(B);
    }
    readout_kernel<<<(B + 7) / 8, 64>>>(fc1_w, fc1_b, fc2_w, fc2_b, y, B);
}

// round 7
// speedup vs baseline: 1.9186x; 1.9186x over previous
#include <cuda_runtime.h>
#include <cuda_bf16.h>
#include <cuda_fp16.h>
#include <math.h>

typedef unsigned long long ull;
typedef unsigned int uint;

#define MAXN 131072
#define MAXE 262144
#define MAXB 4096

// ---------------- device scratch ----------------
__device__ float g_msum[(size_t)MAXN * 64];
__device__ float g_cnt[MAXN];              // reused as attention e-buffer later
__device__ float g_out[(size_t)MAXN * 64];
__device__ float g_S[MAXB * 192];          // per graph: [0:128]=q_star, [128:192]=hl
__device__ float g_cl[MAXB * 64];
__device__ int   g_seg[MAXB + 1];
__device__ ull   g_WrzT[32 * 128];
__device__ ull   g_WinT[32 * 64];
__device__ ull   g_WhnT[32 * 64];
__device__ float g_brz[128], g_binn[64], g_bhn[64];
// fp16 hi/lo split of w_e2, stored as per-chunk smem images (16 chunks x 16384 B)
// chunk nc: n-rows r in [0,64) (r = h), k in [0,128); XOR-16B swizzled row-major [n][k]
__device__ unsigned char g_W2hi[16 * 16384];
__device__ unsigned char g_W2lo[16 * 16384];

// ---------------- helpers ----------------
__device__ __forceinline__ ull pack2(float a, float b) {
    ull r; asm("mov.b64 %0, {%1, %2};" : "=l"(r) : "f"(a), "f"(b)); return r;
}
__device__ __forceinline__ ull f2fma(ull a, ull b, ull c) {
    ull d; asm("fma.rn.f32x2 %0, %1, %2, %3;" : "=l"(d) : "l"(a), "l"(b), "l"(c)); return d;
}
__device__ __forceinline__ float2 unpk(ull a) {
    float2 v; asm("mov.b64 {%0, %1}, %2;" : "=f"(v.x), "=f"(v.y) : "l"(a)); return v;
}
__device__ __forceinline__ float sigm(float x) { return 1.0f / (1.0f + __expf(-x)); }
__device__ __forceinline__ uint smem_u32(const void* p) {
    uint a; asm("{ .reg .u64 t; cvta.to.shared.u64 t, %1; cvt.u32.u64 %0, t; }" : "=r"(a) : "l"(p));
    return a;
}
__device__ __forceinline__ void ldsm4(uint* r, uint addr) {
    asm volatile("ldmatrix.sync.aligned.m8n8.x4.shared.b16 {%0,%1,%2,%3}, [%4];"
        : "=r"(r[0]), "=r"(r[1]), "=r"(r[2]), "=r"(r[3]) : "r"(addr));
}
__device__ __forceinline__ void mma16816(float* d, const uint* a, const uint* b) {
    asm volatile("mma.sync.aligned.m16n8k16.row.col.f32.f16.f16.f32 "
        "{%0,%1,%2,%3}, {%4,%5,%6,%7}, {%8,%9}, {%0,%1,%2,%3};"
        : "+f"(d[0]), "+f"(d[1]), "+f"(d[2]), "+f"(d[3])
        : "r"(a[0]), "r"(a[1]), "r"(a[2]), "r"(a[3]), "r"(b[0]), "r"(b[1]));
}
__device__ __forceinline__ void cp16(uint dst, const void* src) {
    asm volatile("cp.async.ca.shared.global [%0], [%1], 16;" :: "r"(dst), "l"(src));
}

// ---------------- zero scratch ----------------
__global__ void zero_kernel(int N, int B) {
    int idx = blockIdx.x * blockDim.x + threadIdx.x;
    int stride = gridDim.x * blockDim.x;
    int nm = N * 64;
    for (int i = idx; i < nm; i += stride) g_msum[i] = 0.0f;
    for (int i = idx; i < N; i += stride) g_cnt[i] = 0.0f;
    int ns = B * 192;
    for (int i = idx; i < ns; i += stride) g_S[i] = 0.0f;
    int nc = B * 64;
    for (int i = idx; i < nc; i += stride) g_cl[i] = 0.0f;
}

// ---------------- segment offsets ----------------
__global__ void seg_kernel(const int* __restrict__ batch, int N, int B) {
    int b = blockIdx.x * blockDim.x + threadIdx.x;
    if (b > B) return;
    int lo = 0, hi = N;
    while (lo < hi) { int mid = (lo + hi) >> 1; if (batch[mid] < b) lo = mid + 1; else hi = mid; }
    g_seg[b] = lo;
}

// ---------------- GRU weight prep ----------------
__global__ void gru_prep(const float* __restrict__ wih, const float* __restrict__ whh,
                         const float* __restrict__ bih, const float* __restrict__ bhh) {
    int t = blockIdx.x * blockDim.x + threadIdx.x;
    if (t < 4096) {
        int k2 = t >> 7, j = t & 127;
        g_WrzT[t] = pack2(wih[j * 64 + 2 * k2] + whh[j * 64 + 2 * k2],
                          wih[j * 64 + 2 * k2 + 1] + whh[j * 64 + 2 * k2 + 1]);
    } else if (t < 6144) {
        int u = t - 4096;
        int k2 = u >> 6, j2 = u & 63;
        g_WinT[u] = pack2(wih[(128 + j2) * 64 + 2 * k2], wih[(128 + j2) * 64 + 2 * k2 + 1]);
        g_WhnT[u] = pack2(whh[(128 + j2) * 64 + 2 * k2], whh[(128 + j2) * 64 + 2 * k2 + 1]);
    } else if (t < 6272) {
        int u = t - 6144;
        g_brz[u] = bih[u] + bhh[u];
    } else if (t < 6336) {
        int u = t - 6272;
        g_binn[u] = bih[128 + u];
        g_bhn[u]  = bhh[128 + u];
    }
}

// ---------------- w_e2 -> fp16 hi/lo, XOR-swizzled [n][k] chunk images ----------------
__global__ void w2_prep(const float* __restrict__ w_e2) {
    int idx = blockIdx.x * blockDim.x + threadIdx.x;
    if (idx >= 128 * 1024) return;
    int m = idx >> 10, j = idx & 1023;     // m = k, j = d*64+h
    float v = w_e2[idx];
    __half hi = __float2half_rn(v);
    __half lo = __float2half_rn(v - __half2float(hi));
    int nc = j >> 6, r = j & 63;           // chunk, n-row (=h)
    int c = m >> 3;                        // 16B chunk along k
    int off = r * 256 + ((c ^ (r & 7)) << 4) + (m & 7) * 2;
    *(__half*)(g_W2hi + nc * 16384 + off) = hi;
    *(__half*)(g_W2lo + nc * 16384 + off) = lo;
}

// ---------------- edge kernel v3: HMMA (mma.sync fp16, 2-pass B-split) ----------------
// per CTA: 128 edges (M=128). A = hid fp16 [128m x 128k] in smem (XOR-16B swizzle).
// loop nc 0..15: D = A @ B_nc [128k x 64n]  (B = Bhi + Blo, two mma passes)
//               msg[e,h] += x[e,nc] * (D[e,h] + b_e2[nc*64+h])
#define O_A   0          // 32768
#define O_B   32768      // 2 x 32768 (hi 16384 + lo 16384 per buffer)
#define O_XT  98304      // 8192  (xT [16][128] f32)
#define O_B2  106496     // 4096  (b_e2 1024 f32)
#define O_DST 110592     // 512
#define EK3_SMEM 111104

__global__ void __launch_bounds__(256, 2) edge_kernel3(
    const float* __restrict__ x, const float* __restrict__ edge_attr,
    const int* __restrict__ edge_index,
    const float* __restrict__ w_e1, const float* __restrict__ b_e1,
    const float* __restrict__ b_e2, int E)
{
    extern __shared__ char sm[];
    uint smb = smem_u32(sm);
    float* xT  = (float*)(sm + O_XT);
    float* b2S = (float*)(sm + O_B2);
    int*  dstS = (int*)(sm + O_DST);

    int t = threadIdx.x;
    int wid = t >> 5, lane = t & 31;
    int mw = wid & 3, nw = wid >> 2;       // warp tile: rows mw*32, cols nw*32
    int e0 = blockIdx.x * 128;

    // prefetch B chunk 0 (cp.async, 32 KB)
    {
        uint dst = smb + O_B + t * 16;
        const char* sh = (const char*)g_W2hi + t * 16;
        const char* sl = (const char*)g_W2lo + t * 16;
        #pragma unroll
        for (int i = 0; i < 4; ++i) cp16(dst + i * 4096, sh + i * 4096);
        #pragma unroll
        for (int i = 0; i < 4; ++i) cp16(dst + 16384 + i * 4096, sl + i * 4096);
        asm volatile("cp.async.commit_group;");
    }

    // stage b_e2
    for (int i = t; i < 1024; i += 256) b2S[i] = b_e2[i];

    // load edge data (threads < 128 own one edge row)
    if (t < 128) {
        int e = e0 + t;
        int dd = -1;
        if (e < E) {
            int s = edge_index[e];
            dd = edge_index[E + e];
            const float4* xr = reinterpret_cast<const float4*>(x + (size_t)s * 16);
            #pragma unroll
            for (int q = 0; q < 4; ++q) {
                float4 v = xr[q];
                xT[(q * 4 + 0) * 128 + t] = v.x;
                xT[(q * 4 + 1) * 128 + t] = v.y;
                xT[(q * 4 + 2) * 128 + t] = v.z;
                xT[(q * 4 + 3) * 128 + t] = v.w;
            }
            atomicAdd(&g_cnt[dd], 1.0f);
        } else {
            #pragma unroll
            for (int q = 0; q < 16; ++q) xT[q * 128 + t] = 0.0f;
        }
        dstS[t] = dd;
    }

    // form A = fp16(hid): thread pair (2 per row), each half = 8 chunks of 8 k
    {
        int row = t >> 1;
        int cbase = (t & 1) * 8;
        int e = e0 + row;
        float ea0 = 0.f, ea1 = 0.f, ea2 = 0.f, ea3 = 0.f;
        if (e < E) {
            float4 ea = reinterpret_cast<const float4*>(edge_attr)[e];
            ea0 = ea.x; ea1 = ea.y; ea2 = ea.z; ea3 = ea.w;
        }
        #pragma unroll
        for (int c = cbase; c < cbase + 8; ++c) {
            uint h4[4];
            #pragma unroll
            for (int p = 0; p < 4; ++p) {
                int k0 = c * 8 + p * 2;
                float2 w0 = __ldg((const float2*)(w_e1 + k0));
                float2 w1 = __ldg((const float2*)(w_e1 + 128 + k0));
                float2 w2 = __ldg((const float2*)(w_e1 + 256 + k0));
                float2 w3 = __ldg((const float2*)(w_e1 + 384 + k0));
                float2 bb = __ldg((const float2*)(b_e1 + k0));
                float h0 = fmaf(ea3, w3.x, fmaf(ea2, w2.x, fmaf(ea1, w1.x, fmaf(ea0, w0.x, bb.x))));
                float h1 = fmaf(ea3, w3.y, fmaf(ea2, w2.y, fmaf(ea1, w1.y, fmaf(ea0, w0.y, bb.y))));
                __half2 hh = __floats2half2_rn(fmaxf(h0, 0.0f), fmaxf(h1, 0.0f));
                h4[p] = *reinterpret_cast<uint*>(&hh);
            }
            int off = row * 256 + ((c ^ (row & 7)) << 4);
            *(uint4*)(sm + O_A + off) = make_uint4(h4[0], h4[1], h4[2], h4[3]);
        }
    }

    float macc[2][4][4];
    #pragma unroll
    for (int a = 0; a < 2; ++a)
        #pragma unroll
        for (int b = 0; b < 4; ++b)
            #pragma unroll
            for (int r = 0; r < 4; ++r) macc[a][b][r] = 0.0f;

    uint smA = smb + O_A;

    for (int nc = 0; nc < 16; ++nc) {
        asm volatile("cp.async.wait_group 0;" ::: "memory");
        __syncthreads();
        uint smBbuf = smb + O_B + (nc & 1) * 32768;

        // prefetch next chunk into other buffer
        if (nc < 15) {
            uint dst = smb + O_B + ((nc + 1) & 1) * 32768 + t * 16;
            const char* sh = (const char*)g_W2hi + (nc + 1) * 16384 + t * 16;
            const char* sl = (const char*)g_W2lo + (nc + 1) * 16384 + t * 16;
            #pragma unroll
            for (int i = 0; i < 4; ++i) cp16(dst + i * 4096, sh + i * 4096);
            #pragma unroll
            for (int i = 0; i < 4; ++i) cp16(dst + 16384 + i * 4096, sl + i * 4096);
            asm volatile("cp.async.commit_group;");
        }

        float dacc[2][4][4];
        #pragma unroll
        for (int a = 0; a < 2; ++a)
            #pragma unroll
            for (int b = 0; b < 4; ++b)
                #pragma unroll
                for (int r = 0; r < 4; ++r) dacc[a][b][r] = 0.0f;

        #pragma unroll
        for (int kt = 0; kt < 8; ++kt) {
            uint a0[4], a1[4];
            {
                int mi = lane >> 3;
                int arow = mw * 32 + (lane & 7) + (mi & 1) * 8;
                int ac = 2 * kt + (mi >> 1);
                uint addr = smA + arow * 256 + ((ac ^ (arow & 7)) << 4);
                ldsm4(a0, addr);
                ldsm4(a1, addr + 16 * 256);
            }
            uint bh[2][4], bl[2][4];
            {
                int mi = lane >> 3;
                int nrow = nw * 32 + (mi >> 1) * 8 + (lane & 7);
                int bc = 2 * kt + (mi & 1);
                uint aH = smBbuf + nrow * 256 + ((bc ^ (nrow & 7)) << 4);
                ldsm4(bh[0], aH);
                ldsm4(bh[1], aH + 4096);
                ldsm4(bl[0], aH + 16384);
                ldsm4(bl[1], aH + 16384 + 4096);
            }
            #pragma unroll
            for (int mt = 0; mt < 2; ++mt) {
                const uint* av = mt ? a1 : a0;
                #pragma unroll
                for (int ng = 0; ng < 2; ++ng) {
                    #pragma unroll
                    for (int s = 0; s < 2; ++s) {
                        int nt = ng * 2 + s;
                        mma16816(dacc[mt][nt], av, &bh[ng][s * 2]);
                        mma16816(dacc[mt][nt], av, &bl[ng][s * 2]);
                    }
                }
            }
        }

        // epilogue: msg += x[e,nc] * (D + b_e2)
        {
            int rb = mw * 32 + (lane >> 2);
            float xv00 = xT[nc * 128 + rb];
            float xv01 = xT[nc * 128 + rb + 8];
            float xv10 = xT[nc * 128 + rb + 16];
            float xv11 = xT[nc * 128 + rb + 24];
            #pragma unroll
            for (int mt = 0; mt < 2; ++mt) {
                float xa = mt ? xv10 : xv00;
                float xb = mt ? xv11 : xv01;
                #pragma unroll
                for (int nt = 0; nt < 4; ++nt) {
                    int col = nw * 32 + nt * 8 + 2 * (lane & 3);
                    float b0v = b2S[nc * 64 + col];
                    float b1v = b2S[nc * 64 + col + 1];
                    macc[mt][nt][0] = fmaf(xa, dacc[mt][nt][0] + b0v, macc[mt][nt][0]);
                    macc[mt][nt][1] = fmaf(xa, dacc[mt][nt][1] + b1v, macc[mt][nt][1]);
                    macc[mt][nt][2] = fmaf(xb, dacc[mt][nt][2] + b0v, macc[mt][nt][2]);
                    macc[mt][nt][3] = fmaf(xb, dacc[mt][nt][3] + b1v, macc[mt][nt][3]);
                }
            }
        }
    }

    // scatter-add to msum[dst]
    #pragma unroll
    for (int mt = 0; mt < 2; ++mt) {
        #pragma unroll
        for (int half = 0; half < 2; ++half) {
            int row = mw * 32 + mt * 16 + (lane >> 2) + half * 8;
            int dd = dstS[row];
            if (dd < 0) continue;
            float* mr = g_msum + (size_t)dd * 64;
            #pragma unroll
            for (int nt = 0; nt < 4; ++nt) {
                int col = nw * 32 + nt * 8 + 2 * (lane & 3);
                atomicAdd(mr + col,     macc[mt][nt][half * 2]);
                atomicAdd(mr + col + 1, macc[mt][nt][half * 2 + 1]);
            }
        }
    }
}

// ---------------- node update ----------------
__global__ void __launch_bounds__(256) node_kernel(
    const float* __restrict__ x, const float* __restrict__ root,
    const float* __restrict__ conv_bias, int N)
{
    __shared__ float rootS[1024];
    __shared__ float cb[64];
    int t = threadIdx.x;
    for (int i = t; i < 1024; i += 256) rootS[i] = root[i];
    if (t < 64) cb[t] = conv_bias[t];
    __syncthreads();
    int n = blockIdx.x * 4 + (t >> 6);
    int h = t & 63;
    if (n >= N) return;
    const float* xr = x + (size_t)n * 16;
    float acc = cb[h];
    #pragma unroll
    for (int d = 0; d < 16; ++d) acc = fmaf(xr[d], rootS[d * 64 + h], acc);
    float c = fmaxf(g_cnt[n], 1.0f);
    float v = g_msum[(size_t)n * 64 + h] / c + acc;
    g_out[(size_t)n * 64 + h] = fmaxf(v, 0.0f);
}

// ---------------- GRU step ----------------
__global__ void __launch_bounds__(128) gru_kernel(int N)
{
    __shared__ ull   hPs[4][32];
    __shared__ float rzS[4][128];
    int t = threadIdx.x;

    ull wA[32], wB[32];
    float bA, bB;
    if (t < 64) {
        #pragma unroll
        for (int k2 = 0; k2 < 32; ++k2) {
            wA[k2] = g_WrzT[k2 * 128 + t];
            wB[k2] = g_WrzT[k2 * 128 + 64 + t];
        }
        bA = g_brz[t]; bB = g_brz[64 + t];
    } else {
        int jj = t - 64;
        #pragma unroll
        for (int k2 = 0; k2 < 32; ++k2) {
            wA[k2] = g_WinT[k2 * 64 + jj];
            wB[k2] = g_WhnT[k2 * 64 + jj];
        }
        bA = g_binn[jj]; bB = g_bhn[jj];
    }

    for (int nb = blockIdx.x * 4; nb < N; nb += gridDim.x * 4) {
        __syncthreads();
        {
            int ln = t >> 5, k2 = t & 31;
            int n = nb + ln;
            if (t < 128 && n < N)
                hPs[ln][k2] = reinterpret_cast<const ull*>(g_out + (size_t)n * 64)[k2];
        }
        __syncthreads();
        ull accA[4] = {0ull, 0ull, 0ull, 0ull};
        ull accB[4] = {0ull, 0ull, 0ull, 0ull};
        #pragma unroll
        for (int k2 = 0; k2 < 32; ++k2) {
            #pragma unroll
            for (int i = 0; i < 4; ++i) {
                ull hv = hPs[i][k2];
                accA[i] = f2fma(wA[k2], hv, accA[i]);
                accB[i] = f2fma(wB[k2], hv, accB[i]);
            }
        }
        if (t < 64) {
            #pragma unroll
            for (int i = 0; i < 4; ++i) {
                float2 va = unpk(accA[i]), vb = unpk(accB[i]);
                rzS[i][t]      = sigm(va.x + va.y + bA);
                rzS[i][64 + t] = sigm(vb.x + vb.y + bB);
            }
        }
        __syncthreads();
        if (t >= 64) {
            int jj = t - 64;
            #pragma unroll
            for (int i = 0; i < 4; ++i) {
                int n = nb + i;
                if (n >= N) continue;
                float2 va = unpk(accA[i]), vb = unpk(accB[i]);
                float inn = va.x + va.y + bA;
                float hn  = vb.x + vb.y + bB;
                float r = rzS[i][jj], z = rzS[i][64 + jj];
                float nv = tanhf(inn + r * hn);
                float2 hp = unpk(hPs[i][jj >> 1]);
                float hold = (jj & 1) ? hp.y : hp.x;
                g_out[(size_t)n * 64 + jj] = (1.0f - z) * nv + z * hold;
            }
        }
    }
}

// ---------------- Set2Set LSTM step ----------------
__global__ void __launch_bounds__(256) lstm_kernel(
    const float* __restrict__ wih, const float* __restrict__ whh,
    const float* __restrict__ bih, const float* __restrict__ bhh, int B)
{
    __shared__ float wst[256 * 33];
    __shared__ float qsm[8 * 128];
    __shared__ float hsm[8 * 64];
    __shared__ float gsm[8 * 256];
    int t = threadIdx.x;
    int b0 = blockIdx.x * 8;

    for (int i = t; i < 8 * 128; i += 256) {
        int g = i >> 7, k = i & 127;
        qsm[i] = (b0 + g < B) ? g_S[(b0 + g) * 192 + k] : 0.0f;
    }
    for (int i = t; i < 8 * 64; i += 256) {
        int g = i >> 6, k = i & 63;
        hsm[i] = (b0 + g < B) ? g_S[(b0 + g) * 192 + 128 + k] : 0.0f;
    }

    float acc[8];
    float bsum = bih[t] + bhh[t];
    #pragma unroll
    for (int g = 0; g < 8; ++g) acc[g] = bsum;

    for (int c = 0; c < 4; ++c) {
        __syncthreads();
        for (int i = t; i < 8192; i += 256) {
            int j = i >> 5, kk = i & 31;
            wst[j * 33 + kk] = wih[j * 128 + c * 32 + kk];
        }
        __syncthreads();
        #pragma unroll 8
        for (int kk = 0; kk < 32; ++kk) {
            float w = wst[t * 33 + kk];
            #pragma unroll
            for (int g = 0; g < 8; ++g)
                acc[g] = fmaf(w, qsm[g * 128 + c * 32 + kk], acc[g]);
        }
    }
    for (int c = 0; c < 2; ++c) {
        __syncthreads();
        for (int i = t; i < 8192; i += 256) {
            int j = i >> 5, kk = i & 31;
            wst[j * 33 + kk] = whh[j * 64 + c * 32 + kk];
        }
        __syncthreads();
        #pragma unroll 8
        for (int kk = 0; kk < 32; ++kk) {
            float w = wst[t * 33 + kk];
            #pragma unroll
            for (int g = 0; g < 8; ++g)
                acc[g] = fmaf(w, hsm[g * 64 + c * 32 + kk], acc[g]);
        }
    }

    #pragma unroll
    for (int g = 0; g < 8; ++g) gsm[g * 256 + t] = acc[g];
    __syncthreads();

    for (int i = t; i < 8 * 64; i += 256) {
        int g = i >> 6, hh = i & 63;
        int b = b0 + g;
        if (b >= B) continue;
        float ig = sigm(gsm[g * 256 + hh]);
        float fg = sigm(gsm[g * 256 + 64 + hh]);
        float gg = tanhf(gsm[g * 256 + 128 + hh]);
        float og = sigm(gsm[g * 256 + 192 + hh]);
        float cnew = fg * g_cl[b * 64 + hh] + ig * gg;
        g_cl[b * 64 + hh] = cnew;
        g_S[b * 192 + 128 + hh] = og * tanhf(cnew);
    }
}

// ---------------- Set2Set attention step ----------------
__global__ void __launch_bounds__(64) attn_kernel(int B)
{
    __shared__ float qs[64];
    __shared__ float wm[2], ws[2];
    int t = threadIdx.x, b = blockIdx.x;
    qs[t] = g_S[b * 192 + 128 + t];
    __syncthreads();
    int n0 = g_seg[b], n1 = g_seg[b + 1];
    int w = t >> 5, lid = t & 31;

    float mr = -1e30f, sr = 0.0f;
    for (int n = n0 + w; n < n1; n += 2) {
        const float* orow = g_out + (size_t)n * 64;
        float p = orow[lid] * qs[lid] + orow[32 + lid] * qs[32 + lid];
        #pragma unroll
        for (int off = 16; off; off >>= 1) p += __shfl_xor_sync(0xffffffffu, p, off);
        if (lid == 0) g_cnt[n] = p;
        if (p > mr) { sr *= __expf(mr - p); mr = p; }
        sr += __expf(p - mr);
    }
    if (lid == 0) { wm[w] = mr; ws[w] = sr; }
    __syncthreads();
    float m = fmaxf(wm[0], wm[1]);
    float denom = ws[0] * __expf(wm[0] - m) + ws[1] * __expf(wm[1] - m);

    float rg = 0.0f;
    for (int n = n0; n < n1; ++n) {
        float a = __expf(g_cnt[n] - m);
        rg = fmaf(a, g_out[(size_t)n * 64 + t], rg);
    }
    if (n1 > n0) rg /= denom;
    g_S[b * 192 + t]      = qs[t];
    g_S[b * 192 + 64 + t] = rg;
}

// ---------------- readout ----------------
__global__ void __launch_bounds__(64) readout_kernel(
    const float* __restrict__ fc1_w, const float* __restrict__ fc1_b,
    const float* __restrict__ fc2_w, const float* __restrict__ fc2_b,
    float* __restrict__ y, int B)
{
    __shared__ float qsm[8 * 128];
    __shared__ float red[2];
    int t = threadIdx.x;
    int b0 = blockIdx.x * 8;
    for (int i = t; i < 1024; i += 64) {
        int g = i >> 7, k = i & 127;
        qsm[i] = (b0 + g < B) ? g_S[(b0 + g) * 192 + k] : 0.0f;
    }
    __syncthreads();
    float w2 = fc2_w[t];
    float b1 = fc1_b[t];
    for (int g = 0; g < 8; ++g) {
        float a = b1;
        #pragma unroll 8
        for (int k = 0; k < 128; ++k) a = fmaf(qsm[g * 128 + k], fc1_w[k * 64 + t], a);
        a = fmaxf(a, 0.0f);
        float p = a * w2;
        #pragma unroll
        for (int off = 16; off; off >>= 1) p += __shfl_xor_sync(0xffffffffu, p, off);
        if ((t & 31) == 0) red[t >> 5] = p;
        __syncthreads();
        if (t == 0 && b0 + g < B) y[b0 + g] = red[0] + red[1] + fc2_b[0];
        __syncthreads();
    }
}

// ---------------- launch ----------------
extern "C" void kernel_launch(void* const* d_in, const int* in_sizes, int n_in,
                              void* d_out, int out_size)
{
    const float* x         = (const float*)d_in[0];
    const float* edge_attr = (const float*)d_in[1];
    const int*   edge_index= (const int*)  d_in[2];
    const int*   batch     = (const int*)  d_in[3];
    const float* w_e1      = (const float*)d_in[4];
    const float* b_e1      = (const float*)d_in[5];
    const float* w_e2      = (const float*)d_in[6];
    const float* b_e2      = (const float*)d_in[7];
    const float* root      = (const float*)d_in[8];
    const float* conv_bias = (const float*)d_in[9];
    const float* gru_wih   = (const float*)d_in[10];
    const float* gru_whh   = (const float*)d_in[11];
    const float* gru_bih   = (const float*)d_in[12];
    const float* gru_bhh   = (const float*)d_in[13];
    const float* lstm_wih  = (const float*)d_in[14];
    const float* lstm_whh  = (const float*)d_in[15];
    const float* lstm_bih  = (const float*)d_in[16];
    const float* lstm_bhh  = (const float*)d_in[17];
    const float* fc1_w     = (const float*)d_in[18];
    const float* fc1_b     = (const float*)d_in[19];
    const float* fc2_w     = (const float*)d_in[20];
    const float* fc2_b     = (const float*)d_in[21];
    float* y = (float*)d_out;

    int N = in_sizes[0] / 16;
    int E = in_sizes[1] / 4;
    int B = out_size;

    static int smem_set = 0;
    if (!smem_set) {
        cudaFuncSetAttribute(edge_kernel3, cudaFuncAttributeMaxDynamicSharedMemorySize, EK3_SMEM);
        smem_set = 1;
    }

    zero_kernel<<<1024, 256>>>(N, B);
    seg_kernel<<<(B + 1 + 127) / 128, 128>>>(batch, N, B);
    gru_prep<<<25, 256>>>(gru_wih, gru_whh, gru_bih, gru_bhh);
    w2_prep<<<512, 256>>>(w_e2);
    edge_kernel3<<<(E + 127) / 128, 256, EK3_SMEM>>>(x, edge_attr, edge_index, w_e1, b_e1, b_e2, E);
    node_kernel<<<(N + 3) / 4, 256>>>(x, root, conv_bias, N);
    for (int i = 0; i < 3; ++i) gru_kernel<<<592, 128>>>(N);
    for (int i = 0; i < 3; ++i) {
        lstm_kernel<<<(B + 7) / 8, 256>>>(lstm_wih, lstm_whh, lstm_bih, lstm_bhh, B);
        attn_kernel<<<B, 64>>>(B);
    }
    readout_kernel<<<(B + 7) / 8, 64>>>(fc1_w, fc1_b, fc2_w, fc2_b, y, B);
}

// round 8
// speedup vs baseline: 3.1756x; 1.6551x over previous
#include <cuda_runtime.h>
#include <cuda_bf16.h>
#include <cuda_fp16.h>
#include <math.h>

typedef unsigned long long ull;
typedef unsigned int uint;

#define MAXN 131072
#define MAXE 262144
#define MAXB 4096

// ---------------- device scratch ----------------
__device__ float g_msum[(size_t)MAXN * 64];
__device__ float g_cnt[MAXN];              // reused as attention e-buffer later
__device__ float g_out[(size_t)MAXN * 64];
__device__ float g_S[MAXB * 192];          // per graph: [0:128]=q_star, [128:192]=hl
__device__ float g_cl[MAXB * 64];
__device__ int   g_seg[MAXB + 1];
// edge GEMM: fp16 w_e2 (single), per-chunk smem images (16 chunks x 16384 B)
__device__ unsigned char g_W2hi[16 * 16384];
// GRU GEMM: Wg fp16 hi/lo smem images [256 rows x 128 B], interleaved gate cols
__device__ unsigned char g_GBhi[32768];
__device__ unsigned char g_GBlo[32768];
__device__ float g_gbias[256];

// ---------------- helpers ----------------
__device__ __forceinline__ float sigm(float x) { return 1.0f / (1.0f + __expf(-x)); }
__device__ __forceinline__ uint smem_u32(const void* p) {
    uint a; asm("{ .reg .u64 t; cvta.to.shared.u64 t, %1; cvt.u32.u64 %0, t; }" : "=r"(a) : "l"(p));
    return a;
}
__device__ __forceinline__ void ldsm4(uint* r, uint addr) {
    asm volatile("ldmatrix.sync.aligned.m8n8.x4.shared.b16 {%0,%1,%2,%3}, [%4];"
        : "=r"(r[0]), "=r"(r[1]), "=r"(r[2]), "=r"(r[3]) : "r"(addr));
}
__device__ __forceinline__ void mma16816(float* d, const uint* a, const uint* b) {
    asm volatile("mma.sync.aligned.m16n8k16.row.col.f32.f16.f16.f32 "
        "{%0,%1,%2,%3}, {%4,%5,%6,%7}, {%8,%9}, {%0,%1,%2,%3};"
        : "+f"(d[0]), "+f"(d[1]), "+f"(d[2]), "+f"(d[3])
        : "r"(a[0]), "r"(a[1]), "r"(a[2]), "r"(a[3]), "r"(b[0]), "r"(b[1]));
}
__device__ __forceinline__ void cp16(uint dst, const void* src) {
    asm volatile("cp.async.ca.shared.global [%0], [%1], 16;" :: "r"(dst), "l"(src));
}

// ---------------- zero scratch ----------------
__global__ void zero_kernel(int N, int B) {
    int idx = blockIdx.x * blockDim.x + threadIdx.x;
    int stride = gridDim.x * blockDim.x;
    int nm = N * 64;
    for (int i = idx; i < nm; i += stride) g_msum[i] = 0.0f;
    for (int i = idx; i < N; i += stride) g_cnt[i] = 0.0f;
    int ns = B * 192;
    for (int i = idx; i < ns; i += stride) g_S[i] = 0.0f;
    int nc = B * 64;
    for (int i = idx; i < nc; i += stride) g_cl[i] = 0.0f;
}

// ---------------- segment offsets ----------------
__global__ void seg_kernel(const int* __restrict__ batch, int N, int B) {
    int b = blockIdx.x * blockDim.x + threadIdx.x;
    if (b > B) return;
    int lo = 0, hi = N;
    while (lo < hi) { int mid = (lo + hi) >> 1; if (batch[mid] < b) lo = mid + 1; else hi = mid; }
    g_seg[b] = lo;
}

// ---------------- GRU weight prep: Wg fp16 hi/lo images, interleaved cols ----------------
// col c = 4*jj + comp: comp0 = rz_r (wih+whh row jj), comp1 = rz_z (row 64+jj),
//                      comp2 = inn (wih row 128+jj), comp3 = hn (whh row 128+jj)
__global__ void gru_prep(const float* __restrict__ wih, const float* __restrict__ whh,
                         const float* __restrict__ bih, const float* __restrict__ bhh) {
    int idx = blockIdx.x * blockDim.x + threadIdx.x;
    if (idx < 16384) {
        int c = idx >> 6, k = idx & 63;
        int jj = c >> 2, comp = c & 3;
        float v;
        if (comp == 0)      v = wih[jj * 64 + k] + whh[jj * 64 + k];
        else if (comp == 1) v = wih[(64 + jj) * 64 + k] + whh[(64 + jj) * 64 + k];
        else if (comp == 2) v = wih[(128 + jj) * 64 + k];
        else                v = whh[(128 + jj) * 64 + k];
        __half hi = __float2half_rn(v);
        __half lo = __float2half_rn(v - __half2float(hi));
        int off = c * 128 + (((k >> 3) ^ (c & 7)) << 4) + (k & 7) * 2;
        *(__half*)(g_GBhi + off) = hi;
        *(__half*)(g_GBlo + off) = lo;
    } else if (idx < 16640) {
        int c = idx - 16384;
        int jj = c >> 2, comp = c & 3;
        float v;
        if (comp == 0)      v = bih[jj] + bhh[jj];
        else if (comp == 1) v = bih[64 + jj] + bhh[64 + jj];
        else if (comp == 2) v = bih[128 + jj];
        else                v = bhh[128 + jj];
        g_gbias[c] = v;
    }
}

// ---------------- w_e2 -> fp16 (single), XOR-swizzled [n][k] chunk images ----------------
__global__ void w2_prep(const float* __restrict__ w_e2) {
    int idx = blockIdx.x * blockDim.x + threadIdx.x;
    if (idx >= 128 * 1024) return;
    int m = idx >> 10, j = idx & 1023;     // m = k, j = d*64+h
    __half hi = __float2half_rn(w_e2[idx]);
    int nc = j >> 6, r = j & 63;           // chunk, n-row (=h)
    int c = m >> 3;
    int off = r * 256 + ((c ^ (r & 7)) << 4) + (m & 7) * 2;
    *(__half*)(g_W2hi + nc * 16384 + off) = hi;
}

// ---------------- edge kernel: HMMA (single-pass fp16) ----------------
#define O_A   0          // 32768 (A hid fp16, 128 rows x 256 B)
#define O_B   32768      // 2 x 16384 double buffer
#define O_XT  65536      // 8192  (xT [16][128] f32)
#define O_B2  73728      // 4096  (b_e2 1024 f32)
#define O_DST 77824      // 512
#define EK3_SMEM 78336

__global__ void __launch_bounds__(256, 2) edge_kernel3(
    const float* __restrict__ x, const float* __restrict__ edge_attr,
    const int* __restrict__ edge_index,
    const float* __restrict__ w_e1, const float* __restrict__ b_e1,
    const float* __restrict__ b_e2, int E)
{
    extern __shared__ char sm[];
    uint smb = smem_u32(sm);
    float* xT  = (float*)(sm + O_XT);
    float* b2S = (float*)(sm + O_B2);
    int*  dstS = (int*)(sm + O_DST);

    int t = threadIdx.x;
    int wid = t >> 5, lane = t & 31;
    int mw = wid & 3, nw = wid >> 2;
    int e0 = blockIdx.x * 128;

    // prefetch B chunk 0 (16 KB)
    {
        uint dst = smb + O_B + t * 16;
        const char* sh = (const char*)g_W2hi + t * 16;
        #pragma unroll
        for (int i = 0; i < 4; ++i) cp16(dst + i * 4096, sh + i * 4096);
        asm volatile("cp.async.commit_group;");
    }

    for (int i = t; i < 1024; i += 256) b2S[i] = b_e2[i];

    if (t < 128) {
        int e = e0 + t;
        int dd = -1;
        if (e < E) {
            int s = edge_index[e];
            dd = edge_index[E + e];
            const float4* xr = reinterpret_cast<const float4*>(x + (size_t)s * 16);
            #pragma unroll
            for (int q = 0; q < 4; ++q) {
                float4 v = xr[q];
                xT[(q * 4 + 0) * 128 + t] = v.x;
                xT[(q * 4 + 1) * 128 + t] = v.y;
                xT[(q * 4 + 2) * 128 + t] = v.z;
                xT[(q * 4 + 3) * 128 + t] = v.w;
            }
            atomicAdd(&g_cnt[dd], 1.0f);
        } else {
            #pragma unroll
            for (int q = 0; q < 16; ++q) xT[q * 128 + t] = 0.0f;
        }
        dstS[t] = dd;
    }

    // form A = fp16(hid)
    {
        int row = t >> 1;
        int cbase = (t & 1) * 8;
        int e = e0 + row;
        float ea0 = 0.f, ea1 = 0.f, ea2 = 0.f, ea3 = 0.f;
        if (e < E) {
            float4 ea = reinterpret_cast<const float4*>(edge_attr)[e];
            ea0 = ea.x; ea1 = ea.y; ea2 = ea.z; ea3 = ea.w;
        }
        #pragma unroll
        for (int c = cbase; c < cbase + 8; ++c) {
            uint h4[4];
            #pragma unroll
            for (int p = 0; p < 4; ++p) {
                int k0 = c * 8 + p * 2;
                float2 w0 = __ldg((const float2*)(w_e1 + k0));
                float2 w1 = __ldg((const float2*)(w_e1 + 128 + k0));
                float2 w2 = __ldg((const float2*)(w_e1 + 256 + k0));
                float2 w3 = __ldg((const float2*)(w_e1 + 384 + k0));
                float2 bb = __ldg((const float2*)(b_e1 + k0));
                float h0 = fmaf(ea3, w3.x, fmaf(ea2, w2.x, fmaf(ea1, w1.x, fmaf(ea0, w0.x, bb.x))));
                float h1 = fmaf(ea3, w3.y, fmaf(ea2, w2.y, fmaf(ea1, w1.y, fmaf(ea0, w0.y, bb.y))));
                __half2 hh = __floats2half2_rn(fmaxf(h0, 0.0f), fmaxf(h1, 0.0f));
                h4[p] = *reinterpret_cast<uint*>(&hh);
            }
            int off = row * 256 + ((c ^ (row & 7)) << 4);
            *(uint4*)(sm + O_A + off) = make_uint4(h4[0], h4[1], h4[2], h4[3]);
        }
    }

    float macc[2][4][4];
    #pragma unroll
    for (int a = 0; a < 2; ++a)
        #pragma unroll
        for (int b = 0; b < 4; ++b)
            #pragma unroll
            for (int r = 0; r < 4; ++r) macc[a][b][r] = 0.0f;

    uint smA = smb + O_A;

    for (int nc = 0; nc < 16; ++nc) {
        asm volatile("cp.async.wait_group 0;" ::: "memory");
        __syncthreads();
        uint smBbuf = smb + O_B + (nc & 1) * 16384;

        if (nc < 15) {
            uint dst = smb + O_B + ((nc + 1) & 1) * 16384 + t * 16;
            const char* sh = (const char*)g_W2hi + (nc + 1) * 16384 + t * 16;
            #pragma unroll
            for (int i = 0; i < 4; ++i) cp16(dst + i * 4096, sh + i * 4096);
            asm volatile("cp.async.commit_group;");
        }

        float dacc[2][4][4];
        #pragma unroll
        for (int a = 0; a < 2; ++a)
            #pragma unroll
            for (int b = 0; b < 4; ++b)
                #pragma unroll
                for (int r = 0; r < 4; ++r) dacc[a][b][r] = 0.0f;

        #pragma unroll
        for (int kt = 0; kt < 8; ++kt) {
            uint a0[4], a1[4];
            {
                int mi = lane >> 3;
                int arow = mw * 32 + (lane & 7) + (mi & 1) * 8;
                int ac = 2 * kt + (mi >> 1);
                uint addr = smA + arow * 256 + ((ac ^ (arow & 7)) << 4);
                ldsm4(a0, addr);
                ldsm4(a1, addr + 16 * 256);
            }
            uint bh[2][4];
            {
                int mi = lane >> 3;
                int nrow = nw * 32 + (mi >> 1) * 8 + (lane & 7);
                int bc = 2 * kt + (mi & 1);
                uint aH = smBbuf + nrow * 256 + ((bc ^ (nrow & 7)) << 4);
                ldsm4(bh[0], aH);
                ldsm4(bh[1], aH + 4096);
            }
            #pragma unroll
            for (int mt = 0; mt < 2; ++mt) {
                const uint* av = mt ? a1 : a0;
                #pragma unroll
                for (int ng = 0; ng < 2; ++ng) {
                    #pragma unroll
                    for (int s = 0; s < 2; ++s)
                        mma16816(dacc[mt][ng * 2 + s], av, &bh[ng][s * 2]);
                }
            }
        }

        // epilogue: msg += x[e,nc] * (D + b_e2)
        {
            int rb = mw * 32 + (lane >> 2);
            float xv00 = xT[nc * 128 + rb];
            float xv01 = xT[nc * 128 + rb + 8];
            float xv10 = xT[nc * 128 + rb + 16];
            float xv11 = xT[nc * 128 + rb + 24];
            #pragma unroll
            for (int mt = 0; mt < 2; ++mt) {
                float xa = mt ? xv10 : xv00;
                float xb = mt ? xv11 : xv01;
                #pragma unroll
                for (int nt = 0; nt < 4; ++nt) {
                    int col = nw * 32 + nt * 8 + 2 * (lane & 3);
                    float b0v = b2S[nc * 64 + col];
                    float b1v = b2S[nc * 64 + col + 1];
                    macc[mt][nt][0] = fmaf(xa, dacc[mt][nt][0] + b0v, macc[mt][nt][0]);
                    macc[mt][nt][1] = fmaf(xa, dacc[mt][nt][1] + b1v, macc[mt][nt][1]);
                    macc[mt][nt][2] = fmaf(xb, dacc[mt][nt][2] + b0v, macc[mt][nt][2]);
                    macc[mt][nt][3] = fmaf(xb, dacc[mt][nt][3] + b1v, macc[mt][nt][3]);
                }
            }
        }
    }

    #pragma unroll
    for (int mt = 0; mt < 2; ++mt) {
        #pragma unroll
        for (int half = 0; half < 2; ++half) {
            int row = mw * 32 + mt * 16 + (lane >> 2) + half * 8;
            int dd = dstS[row];
            if (dd < 0) continue;
            float* mr = g_msum + (size_t)dd * 64;
            #pragma unroll
            for (int nt = 0; nt < 4; ++nt) {
                int col = nw * 32 + nt * 8 + 2 * (lane & 3);
                atomicAdd(mr + col,     macc[mt][nt][half * 2]);
                atomicAdd(mr + col + 1, macc[mt][nt][half * 2 + 1]);
            }
        }
    }
}

// ---------------- node update ----------------
__global__ void __launch_bounds__(256) node_kernel(
    const float* __restrict__ x, const float* __restrict__ root,
    const float* __restrict__ conv_bias, int N)
{
    __shared__ float rootS[1024];
    __shared__ float cb[64];
    int t = threadIdx.x;
    for (int i = t; i < 1024; i += 256) rootS[i] = root[i];
    if (t < 64) cb[t] = conv_bias[t];
    __syncthreads();
    int n = blockIdx.x * 4 + (t >> 6);
    int h = t & 63;
    if (n >= N) return;
    const float* xr = x + (size_t)n * 16;
    float acc = cb[h];
    #pragma unroll
    for (int d = 0; d < 16; ++d) acc = fmaf(xr[d], rootS[d * 64 + h], acc);
    float c = fmaxf(g_cnt[n], 1.0f);
    float v = g_msum[(size_t)n * 64 + h] / c + acc;
    g_out[(size_t)n * 64 + h] = fmaxf(v, 0.0f);
}

// ---------------- GRU step via HMMA: gates = h @ Wg (3-pass split) ----------------
// CTA = 64 nodes. Warp grid: 4 m-warps (16 rows) x 2 n-halves (128 cols).
// skewed h' smem overlays A region after GEMM.
#define G_HS   0        // 64 x 65 f32 = 16640
#define G_AHI  16640    // 64 x 128 B
#define G_ALO  24832
#define G_BHI  33024    // 256 x 128 B
#define G_BLO  65792
#define G_BIAS 98560    // 256 f32
#define GRU_SMEM 99584
#define HP_IDX(r, j) ((r) * 64 + (((j) + (r) * 4) & 63))

__global__ void __launch_bounds__(256, 2) gru_mma_kernel(int N)
{
    extern __shared__ char sm2[];
    uint smb = smem_u32(sm2);
    float* hS    = (float*)(sm2 + G_HS);
    float* biasS = (float*)(sm2 + G_BIAS);
    float* hpS   = (float*)(sm2 + G_AHI);   // overlay after GEMM

    int t = threadIdx.x, wid = t >> 5, lane = t & 31;
    int n0 = blockIdx.x * 64;

    // stage B (hi+lo, 64 KB)
    {
        const uint4* sh = (const uint4*)g_GBhi;
        const uint4* sl = (const uint4*)g_GBlo;
        uint4* dh = (uint4*)(sm2 + G_BHI);
        uint4* dl = (uint4*)(sm2 + G_BLO);
        #pragma unroll
        for (int i = 0; i < 8; ++i) { dh[t + i * 256] = sh[t + i * 256]; dl[t + i * 256] = sl[t + i * 256]; }
    }
    biasS[t] = g_gbias[t];

    // load h, keep fp32 copy, convert to fp16 hi/lo A tiles
    {
        int r = t >> 2, q = t & 3;
        float vv[16];
        if (n0 + r < N) {
            const float4* src = (const float4*)(g_out + (size_t)(n0 + r) * 64 + q * 16);
            #pragma unroll
            for (int i = 0; i < 4; ++i) {
                float4 v = src[i];
                vv[i * 4] = v.x; vv[i * 4 + 1] = v.y; vv[i * 4 + 2] = v.z; vv[i * 4 + 3] = v.w;
            }
        } else {
            #pragma unroll
            for (int i = 0; i < 16; ++i) vv[i] = 0.0f;
        }
        float* hd = hS + r * 65 + q * 16;
        #pragma unroll
        for (int i = 0; i < 16; ++i) hd[i] = vv[i];
        #pragma unroll
        for (int c2 = 0; c2 < 2; ++c2) {
            uint hi4[4], lo4[4];
            #pragma unroll
            for (int p = 0; p < 4; ++p) {
                float a0 = vv[c2 * 8 + p * 2], a1 = vv[c2 * 8 + p * 2 + 1];
                __half2 hh = __floats2half2_rn(a0, a1);
                __half2 ll = __floats2half2_rn(a0 - __half2float(__low2half(hh)),
                                               a1 - __half2float(__high2half(hh)));
                hi4[p] = *reinterpret_cast<uint*>(&hh);
                lo4[p] = *reinterpret_cast<uint*>(&ll);
            }
            int cc = q * 2 + c2;
            int off = r * 128 + ((cc ^ (r & 7)) << 4);
            *(uint4*)(sm2 + G_AHI + off) = make_uint4(hi4[0], hi4[1], hi4[2], hi4[3]);
            *(uint4*)(sm2 + G_ALO + off) = make_uint4(lo4[0], lo4[1], lo4[2], lo4[3]);
        }
    }
    __syncthreads();

    int mw = wid & 3, nh = wid >> 2;
    int mi = lane >> 3;
    float acc[16][4];
    #pragma unroll
    for (int i = 0; i < 16; ++i)
        #pragma unroll
        for (int j = 0; j < 4; ++j) acc[i][j] = 0.0f;

    uint smAhi = smb + G_AHI, smAlo = smb + G_ALO;
    uint smBh = smb + G_BHI, smBl = smb + G_BLO;

    #pragma unroll
    for (int kt = 0; kt < 4; ++kt) {
        uint ahi[4], alo[4];
        {
            int arow = mw * 16 + (lane & 7) + (mi & 1) * 8;
            int ac = 2 * kt + (mi >> 1);
            uint aoff = (uint)(arow * 128 + ((ac ^ (arow & 7)) << 4));
            ldsm4(ahi, smAhi + aoff);
            ldsm4(alo, smAlo + aoff);
        }
        #pragma unroll
        for (int g = 0; g < 8; ++g) {
            uint bh[4], bl[4];
            int nrow = nh * 128 + g * 16 + (mi >> 1) * 8 + (lane & 7);
            int bc = 2 * kt + (mi & 1);
            uint boff = (uint)(nrow * 128 + ((bc ^ (nrow & 7)) << 4));
            ldsm4(bh, smBh + boff);
            ldsm4(bl, smBl + boff);
            mma16816(acc[2 * g],     ahi, bh);
            mma16816(acc[2 * g],     alo, bh);
            mma16816(acc[2 * g],     ahi, bl);
            mma16816(acc[2 * g + 1], ahi, bh + 2);
            mma16816(acc[2 * g + 1], alo, bh + 2);
            mma16816(acc[2 * g + 1], ahi, bl + 2);
        }
    }
    __syncthreads();   // all A reads done -> safe to overlay h'

    int r0 = mw * 16 + (lane >> 2);
    #pragma unroll
    for (int tt = 0; tt < 16; ++tt) {
        float v00 = acc[tt][0], v01 = acc[tt][1], v10 = acc[tt][2], v11 = acc[tt][3];
        float p00 = __shfl_xor_sync(0xffffffffu, v00, 1);
        float p01 = __shfl_xor_sync(0xffffffffu, v01, 1);
        float p10 = __shfl_xor_sync(0xffffffffu, v10, 1);
        float p11 = __shfl_xor_sync(0xffffffffu, v11, 1);
        if (!(lane & 1)) {
            int c0 = nh * 128 + tt * 8 + 2 * (lane & 3);
            int jj = c0 >> 2;
            float br = biasS[c0], bz = biasS[c0 + 1], bi = biasS[c0 + 2], bn = biasS[c0 + 3];
            {
                float r = sigm(v00 + br), z = sigm(v01 + bz);
                float nv = tanhf((p00 + bi) + r * (p01 + bn));
                float hold = hS[r0 * 65 + jj];
                hpS[HP_IDX(r0, jj)] = (1.0f - z) * nv + z * hold;
            }
            {
                float r = sigm(v10 + br), z = sigm(v11 + bz);
                float nv = tanhf((p10 + bi) + r * (p11 + bn));
                float hold = hS[(r0 + 8) * 65 + jj];
                hpS[HP_IDX(r0 + 8, jj)] = (1.0f - z) * nv + z * hold;
            }
        }
    }
    __syncthreads();

    // coalesced writeback
    {
        int r = t >> 2, q = t & 3;
        if (n0 + r < N) {
            float4* dst = (float4*)(g_out + (size_t)(n0 + r) * 64 + q * 16);
            #pragma unroll
            for (int i = 0; i < 4; ++i) {
                float4 v;
                v.x = hpS[HP_IDX(r, q * 16 + i * 4)];
                v.y = hpS[HP_IDX(r, q * 16 + i * 4 + 1)];
                v.z = hpS[HP_IDX(r, q * 16 + i * 4 + 2)];
                v.w = hpS[HP_IDX(r, q * 16 + i * 4 + 3)];
                dst[i] = v;
            }
        }
    }
}

// ---------------- Set2Set LSTM step ----------------
__global__ void __launch_bounds__(256) lstm_kernel(
    const float* __restrict__ wih, const float* __restrict__ whh,
    const float* __restrict__ bih, const float* __restrict__ bhh, int B)
{
    __shared__ float wst[256 * 33];
    __shared__ float qsm[8 * 128];
    __shared__ float hsm[8 * 64];
    __shared__ float gsm[8 * 256];
    int t = threadIdx.x;
    int b0 = blockIdx.x * 8;

    for (int i = t; i < 8 * 128; i += 256) {
        int g = i >> 7, k = i & 127;
        qsm[i] = (b0 + g < B) ? g_S[(b0 + g) * 192 + k] : 0.0f;
    }
    for (int i = t; i < 8 * 64; i += 256) {
        int g = i >> 6, k = i & 63;
        hsm[i] = (b0 + g < B) ? g_S[(b0 + g) * 192 + 128 + k] : 0.0f;
    }

    float acc[8];
    float bsum = bih[t] + bhh[t];
    #pragma unroll
    for (int g = 0; g < 8; ++g) acc[g] = bsum;

    for (int c = 0; c < 4; ++c) {
        __syncthreads();
        for (int i = t; i < 8192; i += 256) {
            int j = i >> 5, kk = i & 31;
            wst[j * 33 + kk] = wih[j * 128 + c * 32 + kk];
        }
        __syncthreads();
        #pragma unroll 8
        for (int kk = 0; kk < 32; ++kk) {
            float w = wst[t * 33 + kk];
            #pragma unroll
            for (int g = 0; g < 8; ++g)
                acc[g] = fmaf(w, qsm[g * 128 + c * 32 + kk], acc[g]);
        }
    }
    for (int c = 0; c < 2; ++c) {
        __syncthreads();
        for (int i = t; i < 8192; i += 256) {
            int j = i >> 5, kk = i & 31;
            wst[j * 33 + kk] = whh[j * 64 + c * 32 + kk];
        }
        __syncthreads();
        #pragma unroll 8
        for (int kk = 0; kk < 32; ++kk) {
            float w = wst[t * 33 + kk];
            #pragma unroll
            for (int g = 0; g < 8; ++g)
                acc[g] = fmaf(w, hsm[g * 64 + c * 32 + kk], acc[g]);
        }
    }

    #pragma unroll
    for (int g = 0; g < 8; ++g) gsm[g * 256 + t] = acc[g];
    __syncthreads();

    for (int i = t; i < 8 * 64; i += 256) {
        int g = i >> 6, hh = i & 63;
        int b = b0 + g;
        if (b >= B) continue;
        float ig = sigm(gsm[g * 256 + hh]);
        float fg = sigm(gsm[g * 256 + 64 + hh]);
        float gg = tanhf(gsm[g * 256 + 128 + hh]);
        float og = sigm(gsm[g * 256 + 192 + hh]);
        float cnew = fg * g_cl[b * 64 + hh] + ig * gg;
        g_cl[b * 64 + hh] = cnew;
        g_S[b * 192 + 128 + hh] = og * tanhf(cnew);
    }
}

// ---------------- Set2Set attention step (128 threads / graph) ----------------
__global__ void __launch_bounds__(128) attn_kernel(int B)
{
    __shared__ float qs[64];
    __shared__ float wm[4], ws[4];
    __shared__ float rgS[64];
    int t = threadIdx.x, b = blockIdx.x;
    if (t < 64) qs[t] = g_S[b * 192 + 128 + t];
    __syncthreads();
    int n0 = g_seg[b], n1 = g_seg[b + 1];
    int w = t >> 5, lid = t & 31;

    // pass 1: e[n] = dot(out[n], q), 4 warps interleaved; e-buffer = g_cnt
    float mr = -1e30f, sr = 0.0f;
    for (int n = n0 + w; n < n1; n += 4) {
        const float* orow = g_out + (size_t)n * 64;
        float p = orow[lid] * qs[lid] + orow[32 + lid] * qs[32 + lid];
        #pragma unroll
        for (int off = 16; off; off >>= 1) p += __shfl_xor_sync(0xffffffffu, p, off);
        if (lid == 0) g_cnt[n] = p;
        if (p > mr) { sr *= __expf(mr - p); mr = p; }
        sr += __expf(p - mr);
    }
    if (lid == 0) { wm[w] = mr; ws[w] = sr; }
    __syncthreads();
    float m = fmaxf(fmaxf(wm[0], wm[1]), fmaxf(wm[2], wm[3]));
    float denom = ws[0] * __expf(wm[0] - m) + ws[1] * __expf(wm[1] - m)
                + ws[2] * __expf(wm[2] - m) + ws[3] * __expf(wm[3] - m);

    // pass 2: two node-halves
    int col = t & 63, half = t >> 6;
    float rg = 0.0f;
    for (int n = n0 + half; n < n1; n += 2)
        rg = fmaf(__expf(g_cnt[n] - m), g_out[(size_t)n * 64 + col], rg);
    if (half) rgS[col] = rg;
    __syncthreads();
    if (!half) {
        rg += rgS[col];
        if (n1 > n0) rg /= denom;
        g_S[b * 192 + col]      = qs[col];
        g_S[b * 192 + 64 + col] = rg;
    }
}

// ---------------- readout ----------------
__global__ void __launch_bounds__(64) readout_kernel(
    const float* __restrict__ fc1_w, const float* __restrict__ fc1_b,
    const float* __restrict__ fc2_w, const float* __restrict__ fc2_b,
    float* __restrict__ y, int B)
{
    __shared__ float qsm[8 * 128];
    __shared__ float red[2];
    int t = threadIdx.x;
    int b0 = blockIdx.x * 8;
    for (int i = t; i < 1024; i += 64) {
        int g = i >> 7, k = i & 127;
        qsm[i] = (b0 + g < B) ? g_S[(b0 + g) * 192 + k] : 0.0f;
    }
    __syncthreads();
    float w2 = fc2_w[t];
    float b1 = fc1_b[t];
    for (int g = 0; g < 8; ++g) {
        float a = b1;
        #pragma unroll 8
        for (int k = 0; k < 128; ++k) a = fmaf(qsm[g * 128 + k], fc1_w[k * 64 + t], a);
        a = fmaxf(a, 0.0f);
        float p = a * w2;
        #pragma unroll
        for (int off = 16; off; off >>= 1) p += __shfl_xor_sync(0xffffffffu, p, off);
        if ((t & 31) == 0) red[t >> 5] = p;
        __syncthreads();
        if (t == 0 && b0 + g < B) y[b0 + g] = red[0] + red[1] + fc2_b[0];
        __syncthreads();
    }
}

// ---------------- launch ----------------
extern "C" void kernel_launch(void* const* d_in, const int* in_sizes, int n_in,
                              void* d_out, int out_size)
{
    const float* x         = (const float*)d_in[0];
    const float* edge_attr = (const float*)d_in[1];
    const int*   edge_index= (const int*)  d_in[2];
    const int*   batch     = (const int*)  d_in[3];
    const float* w_e1      = (const float*)d_in[4];
    const float* b_e1      = (const float*)d_in[5];
    const float* w_e2      = (const float*)d_in[6];
    const float* b_e2      = (const float*)d_in[7];
    const float* root      = (const float*)d_in[8];
    const float* conv_bias = (const float*)d_in[9];
    const float* gru_wih   = (const float*)d_in[10];
    const float* gru_whh   = (const float*)d_in[11];
    const float* gru_bih   = (const float*)d_in[12];
    const float* gru_bhh   = (const float*)d_in[13];
    const float* lstm_wih  = (const float*)d_in[14];
    const float* lstm_whh  = (const float*)d_in[15];
    const float* lstm_bih  = (const float*)d_in[16];
    const float* lstm_bhh  = (const float*)d_in[17];
    const float* fc1_w     = (const float*)d_in[18];
    const float* fc1_b     = (const float*)d_in[19];
    const float* fc2_w     = (const float*)d_in[20];
    const float* fc2_b     = (const float*)d_in[21];
    float* y = (float*)d_out;

    int N = in_sizes[0] / 16;
    int E = in_sizes[1] / 4;
    int B = out_size;

    static int smem_set = 0;
    if (!smem_set) {
        cudaFuncSetAttribute(edge_kernel3, cudaFuncAttributeMaxDynamicSharedMemorySize, EK3_SMEM);
        cudaFuncSetAttribute(gru_mma_kernel, cudaFuncAttributeMaxDynamicSharedMemorySize, GRU_SMEM);
        smem_set = 1;
    }

    zero_kernel<<<1024, 256>>>(N, B);
    seg_kernel<<<(B + 1 + 127) / 128, 128>>>(batch, N, B);
    gru_prep<<<65, 256>>>(gru_wih, gru_whh, gru_bih, gru_bhh);
    w2_prep<<<512, 256>>>(w_e2);
    edge_kernel3<<<(E + 127) / 128, 256, EK3_SMEM>>>(x, edge_attr, edge_index, w_e1, b_e1, b_e2, E);
    node_kernel<<<(N + 3) / 4, 256>>>(x, root, conv_bias, N);
    for (int i = 0; i < 3; ++i) gru_mma_kernel<<<(N + 63) / 64, 256, GRU_SMEM>>>(N);
    for (int i = 0; i < 3; ++i) {
        lstm_kernel<<<(B + 7) / 8, 256>>>(lstm_wih, lstm_whh, lstm_bih, lstm_bhh, B);
        attn_kernel<<<B, 128>>>(B);
    }
    readout_kernel<<<(B + 7) / 8, 64>>>(fc1_w, fc1_b, fc2_w, fc2_b, y, B);
}

// round 9
// speedup vs baseline: 3.3791x; 1.0641x over previous
#include <cuda_runtime.h>
#include <cuda_bf16.h>
#include <cuda_fp16.h>
#include <math.h>

typedef unsigned long long ull;
typedef unsigned int uint;

#define MAXN 131072
#define MAXE 262144
#define MAXB 4096

// ---------------- device scratch ----------------
__device__ float g_msum[(size_t)MAXN * 64];
__device__ float g_cnt[MAXN];              // reused as attention e-buffer later
__device__ float g_out[(size_t)MAXN * 64];
__device__ float g_S[MAXB * 192];          // per graph: [0:128]=q_star, [128:192]=hl
__device__ float g_cl[MAXB * 64];
__device__ int   g_seg[MAXB + 1];
// edge GEMM: fp16 w_e2 (single), per-chunk smem images (16 chunks x 16384 B)
__device__ unsigned char g_W2hi[16 * 16384];
// GRU GEMM: Wg fp16 hi/lo smem images [256 rows x 128 B], interleaved gate cols
__device__ unsigned char g_GBhi[32768];
__device__ unsigned char g_GBlo[32768];
__device__ float g_gbias[256];

// ---------------- helpers ----------------
__device__ __forceinline__ float sigm(float x) { return 1.0f / (1.0f + __expf(-x)); }
__device__ __forceinline__ uint smem_u32(const void* p) {
    uint a; asm("{ .reg .u64 t; cvta.to.shared.u64 t, %1; cvt.u32.u64 %0, t; }" : "=r"(a) : "l"(p));
    return a;
}
__device__ __forceinline__ void ldsm4(uint* r, uint addr) {
    asm volatile("ldmatrix.sync.aligned.m8n8.x4.shared.b16 {%0,%1,%2,%3}, [%4];"
        : "=r"(r[0]), "=r"(r[1]), "=r"(r[2]), "=r"(r[3]) : "r"(addr));
}
__device__ __forceinline__ void mma16816(float* d, const uint* a, const uint* b) {
    asm volatile("mma.sync.aligned.m16n8k16.row.col.f32.f16.f16.f32 "
        "{%0,%1,%2,%3}, {%4,%5,%6,%7}, {%8,%9}, {%0,%1,%2,%3};"
        : "+f"(d[0]), "+f"(d[1]), "+f"(d[2]), "+f"(d[3])
        : "r"(a[0]), "r"(a[1]), "r"(a[2]), "r"(a[3]), "r"(b[0]), "r"(b[1]));
}
__device__ __forceinline__ void cp16(uint dst, const void* src) {
    asm volatile("cp.async.ca.shared.global [%0], [%1], 16;" :: "r"(dst), "l"(src));
}
__device__ __forceinline__ void red2(float* p, float a, float b) {
    asm volatile("red.global.add.v2.f32 [%0], {%1, %2};" :: "l"(p), "f"(a), "f"(b) : "memory");
}

// ---------------- zero scratch ----------------
__global__ void zero_kernel(int N, int B) {
    int idx = blockIdx.x * blockDim.x + threadIdx.x;
    int stride = gridDim.x * blockDim.x;
    float4 z4 = make_float4(0.f, 0.f, 0.f, 0.f);
    int nm4 = N * 16;
    float4* m4 = (float4*)g_msum;
    for (int i = idx; i < nm4; i += stride) m4[i] = z4;
    for (int i = idx; i < N; i += stride) g_cnt[i] = 0.0f;
    int ns = B * 192;
    for (int i = idx; i < ns; i += stride) g_S[i] = 0.0f;
    int nc = B * 64;
    for (int i = idx; i < nc; i += stride) g_cl[i] = 0.0f;
}

// ---------------- segment offsets ----------------
__global__ void seg_kernel(const int* __restrict__ batch, int N, int B) {
    int b = blockIdx.x * blockDim.x + threadIdx.x;
    if (b > B) return;
    int lo = 0, hi = N;
    while (lo < hi) { int mid = (lo + hi) >> 1; if (batch[mid] < b) lo = mid + 1; else hi = mid; }
    g_seg[b] = lo;
}

// ---------------- GRU weight prep: Wg fp16 hi/lo images, interleaved cols ----------------
// col c = 4*jj + comp: comp0 = rz_r (wih+whh row jj), comp1 = rz_z (row 64+jj),
//                      comp2 = inn (wih row 128+jj), comp3 = hn (whh row 128+jj)
__global__ void gru_prep(const float* __restrict__ wih, const float* __restrict__ whh,
                         const float* __restrict__ bih, const float* __restrict__ bhh) {
    int idx = blockIdx.x * blockDim.x + threadIdx.x;
    if (idx < 16384) {
        int c = idx >> 6, k = idx & 63;
        int jj = c >> 2, comp = c & 3;
        float v;
        if (comp == 0)      v = wih[jj * 64 + k] + whh[jj * 64 + k];
        else if (comp == 1) v = wih[(64 + jj) * 64 + k] + whh[(64 + jj) * 64 + k];
        else if (comp == 2) v = wih[(128 + jj) * 64 + k];
        else                v = whh[(128 + jj) * 64 + k];
        __half hi = __float2half_rn(v);
        __half lo = __float2half_rn(v - __half2float(hi));
        int off = c * 128 + (((k >> 3) ^ (c & 7)) << 4) + (k & 7) * 2;
        *(__half*)(g_GBhi + off) = hi;
        *(__half*)(g_GBlo + off) = lo;
    } else if (idx < 16640) {
        int c = idx - 16384;
        int jj = c >> 2, comp = c & 3;
        float v;
        if (comp == 0)      v = bih[jj] + bhh[jj];
        else if (comp == 1) v = bih[64 + jj] + bhh[64 + jj];
        else if (comp == 2) v = bih[128 + jj];
        else                v = bhh[128 + jj];
        g_gbias[c] = v;
    }
}

// ---------------- w_e2 -> fp16 (single), XOR-swizzled [n][k] chunk images ----------------
__global__ void w2_prep(const float* __restrict__ w_e2) {
    int idx = blockIdx.x * blockDim.x + threadIdx.x;
    if (idx >= 128 * 1024) return;
    int m = idx >> 10, j = idx & 1023;     // m = k, j = d*64+h
    __half hi = __float2half_rn(w_e2[idx]);
    int nc = j >> 6, r = j & 63;           // chunk, n-row (=h)
    int c = m >> 3;
    int off = r * 256 + ((c ^ (r & 7)) << 4) + (m & 7) * 2;
    *(__half*)(g_W2hi + nc * 16384 + off) = hi;
}

// ---------------- edge kernel: HMMA (single-pass fp16) ----------------
#define O_A   0          // 32768 (A hid fp16, 128 rows x 256 B)
#define O_B   32768      // 2 x 16384 double buffer
#define O_XT  65536      // 8192  (xT [16][128] f32)
#define O_B2  73728      // 4096  (b_e2 1024 f32)
#define O_DST 77824      // 512
#define EK3_SMEM 78336

__global__ void __launch_bounds__(256, 2) edge_kernel3(
    const float* __restrict__ x, const float* __restrict__ edge_attr,
    const int* __restrict__ edge_index,
    const float* __restrict__ w_e1, const float* __restrict__ b_e1,
    const float* __restrict__ b_e2, int E)
{
    extern __shared__ char sm[];
    uint smb = smem_u32(sm);
    float* xT  = (float*)(sm + O_XT);
    float* b2S = (float*)(sm + O_B2);
    int*  dstS = (int*)(sm + O_DST);

    int t = threadIdx.x;
    int wid = t >> 5, lane = t & 31;
    int mw = wid & 3, nw = wid >> 2;
    int e0 = blockIdx.x * 128;

    // prefetch B chunk 0 (16 KB)
    {
        uint dst = smb + O_B + t * 16;
        const char* sh = (const char*)g_W2hi + t * 16;
        #pragma unroll
        for (int i = 0; i < 4; ++i) cp16(dst + i * 4096, sh + i * 4096);
        asm volatile("cp.async.commit_group;");
    }

    for (int i = t; i < 1024; i += 256) b2S[i] = b_e2[i];

    if (t < 128) {
        int e = e0 + t;
        int dd = -1;
        if (e < E) {
            int s = edge_index[e];
            dd = edge_index[E + e];
            const float4* xr = reinterpret_cast<const float4*>(x + (size_t)s * 16);
            #pragma unroll
            for (int q = 0; q < 4; ++q) {
                float4 v = xr[q];
                xT[(q * 4 + 0) * 128 + t] = v.x;
                xT[(q * 4 + 1) * 128 + t] = v.y;
                xT[(q * 4 + 2) * 128 + t] = v.z;
                xT[(q * 4 + 3) * 128 + t] = v.w;
            }
            atomicAdd(&g_cnt[dd], 1.0f);
        } else {
            #pragma unroll
            for (int q = 0; q < 16; ++q) xT[q * 128 + t] = 0.0f;
        }
        dstS[t] = dd;
    }

    // form A = fp16(hid)
    {
        int row = t >> 1;
        int cbase = (t & 1) * 8;
        int e = e0 + row;
        float ea0 = 0.f, ea1 = 0.f, ea2 = 0.f, ea3 = 0.f;
        if (e < E) {
            float4 ea = reinterpret_cast<const float4*>(edge_attr)[e];
            ea0 = ea.x; ea1 = ea.y; ea2 = ea.z; ea3 = ea.w;
        }
        #pragma unroll
        for (int c = cbase; c < cbase + 8; ++c) {
            uint h4[4];
            #pragma unroll
            for (int p = 0; p < 4; ++p) {
                int k0 = c * 8 + p * 2;
                float2 w0 = __ldg((const float2*)(w_e1 + k0));
                float2 w1 = __ldg((const float2*)(w_e1 + 128 + k0));
                float2 w2 = __ldg((const float2*)(w_e1 + 256 + k0));
                float2 w3 = __ldg((const float2*)(w_e1 + 384 + k0));
                float2 bb = __ldg((const float2*)(b_e1 + k0));
                float h0 = fmaf(ea3, w3.x, fmaf(ea2, w2.x, fmaf(ea1, w1.x, fmaf(ea0, w0.x, bb.x))));
                float h1 = fmaf(ea3, w3.y, fmaf(ea2, w2.y, fmaf(ea1, w1.y, fmaf(ea0, w0.y, bb.y))));
                __half2 hh = __floats2half2_rn(fmaxf(h0, 0.0f), fmaxf(h1, 0.0f));
                h4[p] = *reinterpret_cast<uint*>(&hh);
            }
            int off = row * 256 + ((c ^ (row & 7)) << 4);
            *(uint4*)(sm + O_A + off) = make_uint4(h4[0], h4[1], h4[2], h4[3]);
        }
    }

    float macc[2][4][4];
    #pragma unroll
    for (int a = 0; a < 2; ++a)
        #pragma unroll
        for (int b = 0; b < 4; ++b)
            #pragma unroll
            for (int r = 0; r < 4; ++r) macc[a][b][r] = 0.0f;

    uint smA = smb + O_A;

    for (int nc = 0; nc < 16; ++nc) {
        asm volatile("cp.async.wait_group 0;" ::: "memory");
        __syncthreads();
        uint smBbuf = smb + O_B + (nc & 1) * 16384;

        if (nc < 15) {
            uint dst = smb + O_B + ((nc + 1) & 1) * 16384 + t * 16;
            const char* sh = (const char*)g_W2hi + (nc + 1) * 16384 + t * 16;
            #pragma unroll
            for (int i = 0; i < 4; ++i) cp16(dst + i * 4096, sh + i * 4096);
            asm volatile("cp.async.commit_group;");
        }

        float dacc[2][4][4];
        #pragma unroll
        for (int a = 0; a < 2; ++a)
            #pragma unroll
            for (int b = 0; b < 4; ++b)
                #pragma unroll
                for (int r = 0; r < 4; ++r) dacc[a][b][r] = 0.0f;

        #pragma unroll
        for (int kt = 0; kt < 8; ++kt) {
            uint a0[4], a1[4];
            {
                int mi = lane >> 3;
                int arow = mw * 32 + (lane & 7) + (mi & 1) * 8;
                int ac = 2 * kt + (mi >> 1);
                uint addr = smA + arow * 256 + ((ac ^ (arow & 7)) << 4);
                ldsm4(a0, addr);
                ldsm4(a1, addr + 16 * 256);
            }
            uint bh[2][4];
            {
                int mi = lane >> 3;
                int nrow = nw * 32 + (mi >> 1) * 8 + (lane & 7);
                int bc = 2 * kt + (mi & 1);
                uint aH = smBbuf + nrow * 256 + ((bc ^ (nrow & 7)) << 4);
                ldsm4(bh[0], aH);
                ldsm4(bh[1], aH + 4096);
            }
            #pragma unroll
            for (int mt = 0; mt < 2; ++mt) {
                const uint* av = mt ? a1 : a0;
                #pragma unroll
                for (int ng = 0; ng < 2; ++ng) {
                    #pragma unroll
                    for (int s = 0; s < 2; ++s)
                        mma16816(dacc[mt][ng * 2 + s], av, &bh[ng][s * 2]);
                }
            }
        }

        // epilogue: msg += x[e,nc] * (D + b_e2)
        {
            int rb = mw * 32 + (lane >> 2);
            float xv00 = xT[nc * 128 + rb];
            float xv01 = xT[nc * 128 + rb + 8];
            float xv10 = xT[nc * 128 + rb + 16];
            float xv11 = xT[nc * 128 + rb + 24];
            #pragma unroll
            for (int mt = 0; mt < 2; ++mt) {
                float xa = mt ? xv10 : xv00;
                float xb = mt ? xv11 : xv01;
                #pragma unroll
                for (int nt = 0; nt < 4; ++nt) {
                    int col = nw * 32 + nt * 8 + 2 * (lane & 3);
                    float b0v = b2S[nc * 64 + col];
                    float b1v = b2S[nc * 64 + col + 1];
                    macc[mt][nt][0] = fmaf(xa, dacc[mt][nt][0] + b0v, macc[mt][nt][0]);
                    macc[mt][nt][1] = fmaf(xa, dacc[mt][nt][1] + b1v, macc[mt][nt][1]);
                    macc[mt][nt][2] = fmaf(xb, dacc[mt][nt][2] + b0v, macc[mt][nt][2]);
                    macc[mt][nt][3] = fmaf(xb, dacc[mt][nt][3] + b1v, macc[mt][nt][3]);
                }
            }
        }
    }

    // scatter: vectorized reductions (red.v2)
    #pragma unroll
    for (int mt = 0; mt < 2; ++mt) {
        #pragma unroll
        for (int half = 0; half < 2; ++half) {
            int row = mw * 32 + mt * 16 + (lane >> 2) + half * 8;
            int dd = dstS[row];
            if (dd < 0) continue;
            float* mr = g_msum + (size_t)dd * 64;
            #pragma unroll
            for (int nt = 0; nt < 4; ++nt) {
                int col = nw * 32 + nt * 8 + 2 * (lane & 3);
                red2(mr + col, macc[mt][nt][half * 2], macc[mt][nt][half * 2 + 1]);
            }
        }
    }
}

// ---------------- node update ----------------
__global__ void __launch_bounds__(256) node_kernel(
    const float* __restrict__ x, const float* __restrict__ root,
    const float* __restrict__ conv_bias, int N)
{
    __shared__ float rootS[1024];
    __shared__ float cb[64];
    int t = threadIdx.x;
    for (int i = t; i < 1024; i += 256) rootS[i] = root[i];
    if (t < 64) cb[t] = conv_bias[t];
    __syncthreads();
    int n = blockIdx.x * 4 + (t >> 6);
    int h = t & 63;
    if (n >= N) return;
    const float* xr = x + (size_t)n * 16;
    float acc = cb[h];
    #pragma unroll
    for (int d = 0; d < 16; ++d) acc = fmaf(xr[d], rootS[d * 64 + h], acc);
    float c = fmaxf(g_cnt[n], 1.0f);
    float v = g_msum[(size_t)n * 64 + h] / c + acc;
    g_out[(size_t)n * 64 + h] = fmaxf(v, 0.0f);
}

// ---------------- GRU x3 fused via HMMA: gates = h @ Wg (3-pass split) ----------------
// CTA = 64 nodes, 3 GRU steps in one launch. Warp grid: 4 m x 2 n-halves.
#define G_HS   0        // 64 x 65 f32 = 16640
#define G_AHI  16640    // 64 x 128 B = 8192
#define G_ALO  24832    // 8192
#define G_BHI  33024    // 256 x 128 B = 32768
#define G_BLO  65792    // 32768
#define G_BIAS 98560    // 256 f32
#define GRU_SMEM 99584

__global__ void __launch_bounds__(256, 2) gru_mma_kernel(int N)
{
    extern __shared__ char sm2[];
    uint smb = smem_u32(sm2);
    float* hS    = (float*)(sm2 + G_HS);
    float* biasS = (float*)(sm2 + G_BIAS);

    int t = threadIdx.x, wid = t >> 5, lane = t & 31;
    int n0 = blockIdx.x * 64;

    // stage B (hi+lo, 64 KB)
    {
        const uint4* sh = (const uint4*)g_GBhi;
        const uint4* sl = (const uint4*)g_GBlo;
        uint4* dh = (uint4*)(sm2 + G_BHI);
        uint4* dl = (uint4*)(sm2 + G_BLO);
        #pragma unroll
        for (int i = 0; i < 8; ++i) { dh[t + i * 256] = sh[t + i * 256]; dl[t + i * 256] = sl[t + i * 256]; }
    }
    biasS[t] = g_gbias[t];

    // coalesced load h -> hS
    #pragma unroll
    for (int j = 0; j < 16; ++j) {
        int idx = j * 256 + t;
        int r = idx >> 6, c = idx & 63;
        int n = n0 + r;
        hS[r * 65 + c] = (n < N) ? g_out[(size_t)n * 64 + c] : 0.0f;
    }
    __syncthreads();

    int mw = wid & 3, nh = wid >> 2;
    int mi = lane >> 3;
    uint smAhi = smb + G_AHI, smAlo = smb + G_ALO;
    uint smBh = smb + G_BHI, smBl = smb + G_BLO;
    int r0 = mw * 16 + (lane >> 2);

    for (int step = 0; step < 3; ++step) {
        // convert hS -> fp16 hi/lo A tiles (thread r = t>>2 covers cols q*16..+16)
        {
            int r = t >> 2, q = t & 3;
            const float* hr = hS + r * 65 + q * 16;
            #pragma unroll
            for (int c2 = 0; c2 < 2; ++c2) {
                uint hi4[4], lo4[4];
                #pragma unroll
                for (int p = 0; p < 4; ++p) {
                    float a0 = hr[c2 * 8 + p * 2], a1 = hr[c2 * 8 + p * 2 + 1];
                    __half2 hh = __floats2half2_rn(a0, a1);
                    __half2 ll = __floats2half2_rn(a0 - __half2float(__low2half(hh)),
                                                   a1 - __half2float(__high2half(hh)));
                    hi4[p] = *reinterpret_cast<uint*>(&hh);
                    lo4[p] = *reinterpret_cast<uint*>(&ll);
                }
                int cc = q * 2 + c2;
                int off = r * 128 + ((cc ^ (r & 7)) << 4);
                *(uint4*)(sm2 + G_AHI + off) = make_uint4(hi4[0], hi4[1], hi4[2], hi4[3]);
                *(uint4*)(sm2 + G_ALO + off) = make_uint4(lo4[0], lo4[1], lo4[2], lo4[3]);
            }
        }
        __syncthreads();

        float acc[16][4];
        #pragma unroll
        for (int i = 0; i < 16; ++i)
            #pragma unroll
            for (int j = 0; j < 4; ++j) acc[i][j] = 0.0f;

        #pragma unroll
        for (int kt = 0; kt < 4; ++kt) {
            uint ahi[4], alo[4];
            {
                int arow = mw * 16 + (lane & 7) + (mi & 1) * 8;
                int ac = 2 * kt + (mi >> 1);
                uint aoff = (uint)(arow * 128 + ((ac ^ (arow & 7)) << 4));
                ldsm4(ahi, smAhi + aoff);
                ldsm4(alo, smAlo + aoff);
            }
            #pragma unroll
            for (int g = 0; g < 8; ++g) {
                uint bh[4], bl[4];
                int nrow = nh * 128 + g * 16 + (mi >> 1) * 8 + (lane & 7);
                int bc = 2 * kt + (mi & 1);
                uint boff = (uint)(nrow * 128 + ((bc ^ (nrow & 7)) << 4));
                ldsm4(bh, smBh + boff);
                ldsm4(bl, smBl + boff);
                mma16816(acc[2 * g],     ahi, bh);
                mma16816(acc[2 * g],     alo, bh);
                mma16816(acc[2 * g],     ahi, bl);
                mma16816(acc[2 * g + 1], ahi, bh + 2);
                mma16816(acc[2 * g + 1], alo, bh + 2);
                mma16816(acc[2 * g + 1], ahi, bl + 2);
            }
        }
        __syncthreads();   // all A/h reads done before h' overwrite

        #pragma unroll
        for (int tt = 0; tt < 16; ++tt) {
            float v00 = acc[tt][0], v01 = acc[tt][1], v10 = acc[tt][2], v11 = acc[tt][3];
            float p00 = __shfl_xor_sync(0xffffffffu, v00, 1);
            float p01 = __shfl_xor_sync(0xffffffffu, v01, 1);
            float p10 = __shfl_xor_sync(0xffffffffu, v10, 1);
            float p11 = __shfl_xor_sync(0xffffffffu, v11, 1);
            if (!(lane & 1)) {
                int c0 = nh * 128 + tt * 8 + 2 * (lane & 3);
                int jj = c0 >> 2;
                float br = biasS[c0], bz = biasS[c0 + 1], bi = biasS[c0 + 2], bn = biasS[c0 + 3];
                {
                    float r = sigm(v00 + br), z = sigm(v01 + bz);
                    float nv = tanhf((p00 + bi) + r * (p01 + bn));
                    float hold = hS[r0 * 65 + jj];
                    hS[r0 * 65 + jj] = (1.0f - z) * nv + z * hold;
                }
                {
                    float r = sigm(v10 + br), z = sigm(v11 + bz);
                    float nv = tanhf((p10 + bi) + r * (p11 + bn));
                    float hold = hS[(r0 + 8) * 65 + jj];
                    hS[(r0 + 8) * 65 + jj] = (1.0f - z) * nv + z * hold;
                }
            }
        }
        __syncthreads();
    }

    // coalesced writeback
    #pragma unroll
    for (int j = 0; j < 16; ++j) {
        int idx = j * 256 + t;
        int r = idx >> 6, c = idx & 63;
        int n = n0 + r;
        if (n < N) g_out[(size_t)n * 64 + c] = hS[r * 65 + c];
    }
}

// ---------------- Set2Set LSTM step ----------------
__global__ void __launch_bounds__(256) lstm_kernel(
    const float* __restrict__ wih, const float* __restrict__ whh,
    const float* __restrict__ bih, const float* __restrict__ bhh, int B)
{
    __shared__ float wst[256 * 33];
    __shared__ float qsm[8 * 128];
    __shared__ float hsm[8 * 64];
    __shared__ float gsm[8 * 256];
    int t = threadIdx.x;
    int b0 = blockIdx.x * 8;

    for (int i = t; i < 8 * 128; i += 256) {
        int g = i >> 7, k = i & 127;
        qsm[i] = (b0 + g < B) ? g_S[(b0 + g) * 192 + k] : 0.0f;
    }
    for (int i = t; i < 8 * 64; i += 256) {
        int g = i >> 6, k = i & 63;
        hsm[i] = (b0 + g < B) ? g_S[(b0 + g) * 192 + 128 + k] : 0.0f;
    }

    float acc[8];
    float bsum = bih[t] + bhh[t];
    #pragma unroll
    for (int g = 0; g < 8; ++g) acc[g] = bsum;

    for (int c = 0; c < 4; ++c) {
        __syncthreads();
        for (int i = t; i < 8192; i += 256) {
            int j = i >> 5, kk = i & 31;
            wst[j * 33 + kk] = wih[j * 128 + c * 32 + kk];
        }
        __syncthreads();
        #pragma unroll 8
        for (int kk = 0; kk < 32; ++kk) {
            float w = wst[t * 33 + kk];
            #pragma unroll
            for (int g = 0; g < 8; ++g)
                acc[g] = fmaf(w, qsm[g * 128 + c * 32 + kk], acc[g]);
        }
    }
    for (int c = 0; c < 2; ++c) {
        __syncthreads();
        for (int i = t; i < 8192; i += 256) {
            int j = i >> 5, kk = i & 31;
            wst[j * 33 + kk] = whh[j * 64 + c * 32 + kk];
        }
        __syncthreads();
        #pragma unroll 8
        for (int kk = 0; kk < 32; ++kk) {
            float w = wst[t * 33 + kk];
            #pragma unroll
            for (int g = 0; g < 8; ++g)
                acc[g] = fmaf(w, hsm[g * 64 + c * 32 + kk], acc[g]);
        }
    }

    #pragma unroll
    for (int g = 0; g < 8; ++g) gsm[g * 256 + t] = acc[g];
    __syncthreads();

    for (int i = t; i < 8 * 64; i += 256) {
        int g = i >> 6, hh = i & 63;
        int b = b0 + g;
        if (b >= B) continue;
        float ig = sigm(gsm[g * 256 + hh]);
        float fg = sigm(gsm[g * 256 + 64 + hh]);
        float gg = tanhf(gsm[g * 256 + 128 + hh]);
        float og = sigm(gsm[g * 256 + 192 + hh]);
        float cnew = fg * g_cl[b * 64 + hh] + ig * gg;
        g_cl[b * 64 + hh] = cnew;
        g_S[b * 192 + 128 + hh] = og * tanhf(cnew);
    }
}

// ---------------- Set2Set attention step (128 threads / graph) ----------------
__global__ void __launch_bounds__(128) attn_kernel(int B)
{
    __shared__ float qs[64];
    __shared__ float wm[4], ws[4];
    __shared__ float rgS[64];
    int t = threadIdx.x, b = blockIdx.x;
    if (t < 64) qs[t] = g_S[b * 192 + 128 + t];
    __syncthreads();
    int n0 = g_seg[b], n1 = g_seg[b + 1];
    int w = t >> 5, lid = t & 31;

    float mr = -1e30f, sr = 0.0f;
    for (int n = n0 + w; n < n1; n += 4) {
        const float* orow = g_out + (size_t)n * 64;
        float p = orow[lid] * qs[lid] + orow[32 + lid] * qs[32 + lid];
        #pragma unroll
        for (int off = 16; off; off >>= 1) p += __shfl_xor_sync(0xffffffffu, p, off);
        if (lid == 0) g_cnt[n] = p;
        if (p > mr) { sr *= __expf(mr - p); mr = p; }
        sr += __expf(p - mr);
    }
    if (lid == 0) { wm[w] = mr; ws[w] = sr; }
    __syncthreads();
    float m = fmaxf(fmaxf(wm[0], wm[1]), fmaxf(wm[2], wm[3]));
    float denom = ws[0] * __expf(wm[0] - m) + ws[1] * __expf(wm[1] - m)
                + ws[2] * __expf(wm[2] - m) + ws[3] * __expf(wm[3] - m);

    int col = t & 63, half = t >> 6;
    float rg = 0.0f;
    for (int n = n0 + half; n < n1; n += 2)
        rg = fmaf(__expf(g_cnt[n] - m), g_out[(size_t)n * 64 + col], rg);
    if (half) rgS[col] = rg;
    __syncthreads();
    if (!half) {
        rg += rgS[col];
        if (n1 > n0) rg /= denom;
        g_S[b * 192 + col]      = qs[col];
        g_S[b * 192 + 64 + col] = rg;
    }
}

// ---------------- readout ----------------
__global__ void __launch_bounds__(64) readout_kernel(
    const float* __restrict__ fc1_w, const float* __restrict__ fc1_b,
    const float* __restrict__ fc2_w, const float* __restrict__ fc2_b,
    float* __restrict__ y, int B)
{
    __shared__ float qsm[8 * 128];
    __shared__ float red[2];
    int t = threadIdx.x;
    int b0 = blockIdx.x * 8;
    for (int i = t; i < 1024; i += 64) {
        int g = i >> 7, k = i & 127;
        qsm[i] = (b0 + g < B) ? g_S[(b0 + g) * 192 + k] : 0.0f;
    }
    __syncthreads();
    float w2 = fc2_w[t];
    float b1 = fc1_b[t];
    for (int g = 0; g < 8; ++g) {
        float a = b1;
        #pragma unroll 8
        for (int k = 0; k < 128; ++k) a = fmaf(qsm[g * 128 + k], fc1_w[k * 64 + t], a);
        a = fmaxf(a, 0.0f);
        float p = a * w2;
        #pragma unroll
        for (int off = 16; off; off >>= 1) p += __shfl_xor_sync(0xffffffffu, p, off);
        if ((t & 31) == 0) red[t >> 5] = p;
        __syncthreads();
        if (t == 0 && b0 + g < B) y[b0 + g] = red[0] + red[1] + fc2_b[0];
        __syncthreads();
    }
}

// ---------------- launch ----------------
extern "C" void kernel_launch(void* const* d_in, const int* in_sizes, int n_in,
                              void* d_out, int out_size)
{
    const float* x         = (const float*)d_in[0];
    const float* edge_attr = (const float*)d_in[1];
    const int*   edge_index= (const int*)  d_in[2];
    const int*   batch     = (const int*)  d_in[3];
    const float* w_e1      = (const float*)d_in[4];
    const float* b_e1      = (const float*)d_in[5];
    const float* w_e2      = (const float*)d_in[6];
    const float* b_e2      = (const float*)d_in[7];
    const float* root      = (const float*)d_in[8];
    const float* conv_bias = (const float*)d_in[9];
    const float* gru_wih   = (const float*)d_in[10];
    const float* gru_whh   = (const float*)d_in[11];
    const float* gru_bih   = (const float*)d_in[12];
    const float* gru_bhh   = (const float*)d_in[13];
    const float* lstm_wih  = (const float*)d_in[14];
    const float* lstm_whh  = (const float*)d_in[15];
    const float* lstm_bih  = (const float*)d_in[16];
    const float* lstm_bhh  = (const float*)d_in[17];
    const float* fc1_w     = (const float*)d_in[18];
    const float* fc1_b     = (const float*)d_in[19];
    const float* fc2_w     = (const float*)d_in[20];
    const float* fc2_b     = (const float*)d_in[21];
    float* y = (float*)d_out;

    int N = in_sizes[0] / 16;
    int E = in_sizes[1] / 4;
    int B = out_size;

    static int smem_set = 0;
    if (!smem_set) {
        cudaFuncSetAttribute(edge_kernel3, cudaFuncAttributeMaxDynamicSharedMemorySize, EK3_SMEM);
        cudaFuncSetAttribute(gru_mma_kernel, cudaFuncAttributeMaxDynamicSharedMemorySize, GRU_SMEM);
        smem_set = 1;
    }

    // NOTE: edge_kernel3 is deliberately the 4th launch (ncu capture window).
    zero_kernel<<<1024, 256>>>(N, B);
    seg_kernel<<<(B + 1 + 127) / 128, 128>>>(batch, N, B);
    w2_prep<<<512, 256>>>(w_e2);
    edge_kernel3<<<(E + 127) / 128, 256, EK3_SMEM>>>(x, edge_attr, edge_index, w_e1, b_e1, b_e2, E);
    node_kernel<<<(N + 3) / 4, 256>>>(x, root, conv_bias, N);
    gru_prep<<<65, 256>>>(gru_wih, gru_whh, gru_bih, gru_bhh);
    gru_mma_kernel<<<(N + 63) / 64, 256, GRU_SMEM>>>(N);
    for (int i = 0; i < 3; ++i) {
        lstm_kernel<<<(B + 7) / 8, 256>>>(lstm_wih, lstm_whh, lstm_bih, lstm_bhh, B);
        attn_kernel<<<B, 128>>>(B);
    }
    readout_kernel<<<(B + 7) / 8, 64>>>(fc1_w, fc1_b, fc2_w, fc2_b, y, B);
}

// round 10
// speedup vs baseline: 3.5214x; 1.0421x over previous
#include <cuda_runtime.h>
#include <cuda_bf16.h>
#include <cuda_fp16.h>
#include <math.h>

typedef unsigned long long ull;
typedef unsigned int uint;

#define MAXN 131072
#define MAXE 262144
#define MAXB 4096

// ---------------- device scratch ----------------
__device__ float g_msum[(size_t)MAXN * 64];
__device__ float g_cnt[MAXN];              // reused as attention e-buffer later
__device__ float g_out[(size_t)MAXN * 64];
__device__ float g_S[MAXB * 192];          // per graph: [0:128]=q_star, [128:192]=hl
__device__ float g_cl[MAXB * 64];
__device__ int   g_seg[MAXB + 1];
// edge GEMM: fp16 w_e2 (single), per-chunk smem images (16 chunks x 16384 B)
__device__ unsigned char g_W2hi[16 * 16384];
// GRU GEMM: Wg fp16 hi/lo smem images [256 rows x 128 B], interleaved gate cols
__device__ unsigned char g_GBhi[32768];
__device__ unsigned char g_GBlo[32768];
__device__ float g_gbias[256];

// ---------------- helpers ----------------
__device__ __forceinline__ float sigm(float x) { return 1.0f / (1.0f + __expf(-x)); }
__device__ __forceinline__ uint smem_u32(const void* p) {
    uint a; asm("{ .reg .u64 t; cvta.to.shared.u64 t, %1; cvt.u32.u64 %0, t; }" : "=r"(a) : "l"(p));
    return a;
}
__device__ __forceinline__ void ldsm4(uint* r, uint addr) {
    asm volatile("ldmatrix.sync.aligned.m8n8.x4.shared.b16 {%0,%1,%2,%3}, [%4];"
        : "=r"(r[0]), "=r"(r[1]), "=r"(r[2]), "=r"(r[3]) : "r"(addr));
}
__device__ __forceinline__ void mma16816(float* d, const uint* a, const uint* b) {
    asm volatile("mma.sync.aligned.m16n8k16.row.col.f32.f16.f16.f32 "
        "{%0,%1,%2,%3}, {%4,%5,%6,%7}, {%8,%9}, {%0,%1,%2,%3};"
        : "+f"(d[0]), "+f"(d[1]), "+f"(d[2]), "+f"(d[3])
        : "r"(a[0]), "r"(a[1]), "r"(a[2]), "r"(a[3]), "r"(b[0]), "r"(b[1]));
}
__device__ __forceinline__ void cp16(uint dst, const void* src) {
    asm volatile("cp.async.ca.shared.global [%0], [%1], 16;" :: "r"(dst), "l"(src));
}
__device__ __forceinline__ void red2(float* p, float a, float b) {
    asm volatile("red.global.add.v2.f32 [%0], {%1, %2};" :: "l"(p), "f"(a), "f"(b) : "memory");
}

// ---------------- zero scratch ----------------
__global__ void zero_kernel(int N, int B) {
    int idx = blockIdx.x * blockDim.x + threadIdx.x;
    int stride = gridDim.x * blockDim.x;
    float4 z4 = make_float4(0.f, 0.f, 0.f, 0.f);
    int nm4 = N * 16;
    float4* m4 = (float4*)g_msum;
    for (int i = idx; i < nm4; i += stride) m4[i] = z4;
    for (int i = idx; i < N; i += stride) g_cnt[i] = 0.0f;
    int ns = B * 192;
    for (int i = idx; i < ns; i += stride) g_S[i] = 0.0f;
    int nc = B * 64;
    for (int i = idx; i < nc; i += stride) g_cl[i] = 0.0f;
}

// ---------------- segment offsets ----------------
__global__ void seg_kernel(const int* __restrict__ batch, int N, int B) {
    int b = blockIdx.x * blockDim.x + threadIdx.x;
    if (b > B) return;
    int lo = 0, hi = N;
    while (lo < hi) { int mid = (lo + hi) >> 1; if (batch[mid] < b) lo = mid + 1; else hi = mid; }
    g_seg[b] = lo;
}

// ---------------- merged prep: w_e2 fp16 images + GRU weight images ----------------
// blocks [0,512): w_e2; blocks [512,577): GRU Wg + bias
__global__ void prep_kernel(const float* __restrict__ w_e2,
                            const float* __restrict__ wih, const float* __restrict__ whh,
                            const float* __restrict__ bih, const float* __restrict__ bhh) {
    int bid = blockIdx.x;
    if (bid < 512) {
        int idx = bid * 256 + threadIdx.x;
        int m = idx >> 10, j = idx & 1023;     // m = k, j = d*64+h
        __half hi = __float2half_rn(w_e2[idx]);
        int nc = j >> 6, r = j & 63;
        int c = m >> 3;
        int off = r * 256 + ((c ^ (r & 7)) << 4) + (m & 7) * 2;
        *(__half*)(g_W2hi + nc * 16384 + off) = hi;
    } else {
        int idx = (bid - 512) * 256 + threadIdx.x;
        if (idx < 16384) {
            int c = idx >> 6, k = idx & 63;
            int jj = c >> 2, comp = c & 3;
            float v;
            if (comp == 0)      v = wih[jj * 64 + k] + whh[jj * 64 + k];
            else if (comp == 1) v = wih[(64 + jj) * 64 + k] + whh[(64 + jj) * 64 + k];
            else if (comp == 2) v = wih[(128 + jj) * 64 + k];
            else                v = whh[(128 + jj) * 64 + k];
            __half hi = __float2half_rn(v);
            __half lo = __float2half_rn(v - __half2float(hi));
            int off = c * 128 + (((k >> 3) ^ (c & 7)) << 4) + (k & 7) * 2;
            *(__half*)(g_GBhi + off) = hi;
            *(__half*)(g_GBlo + off) = lo;
        } else if (idx < 16640) {
            int c = idx - 16384;
            int jj = c >> 2, comp = c & 3;
            float v;
            if (comp == 0)      v = bih[jj] + bhh[jj];
            else if (comp == 1) v = bih[64 + jj] + bhh[64 + jj];
            else if (comp == 2) v = bih[128 + jj];
            else                v = bhh[128 + jj];
            g_gbias[c] = v;
        }
    }
}

// ---------------- edge kernel: HMMA (single-pass fp16) ----------------
#define O_A   0          // 32768 (A hid fp16, 128 rows x 256 B)
#define O_B   32768      // 2 x 16384 double buffer
#define O_XT  65536      // 8192  (xT [16][128] f32)
#define O_B2  73728      // 4096  (b_e2 1024 f32)
#define O_DST 77824      // 512
#define EK3_SMEM 78336

__global__ void __launch_bounds__(256, 2) edge_kernel3(
    const float* __restrict__ x, const float* __restrict__ edge_attr,
    const int* __restrict__ edge_index,
    const float* __restrict__ w_e1, const float* __restrict__ b_e1,
    const float* __restrict__ b_e2, int E)
{
    extern __shared__ char sm[];
    uint smb = smem_u32(sm);
    float* xT  = (float*)(sm + O_XT);
    float* b2S = (float*)(sm + O_B2);
    int*  dstS = (int*)(sm + O_DST);

    int t = threadIdx.x;
    int wid = t >> 5, lane = t & 31;
    int mw = wid & 3, nw = wid >> 2;
    int e0 = blockIdx.x * 128;

    // prefetch B chunk 0 (16 KB)
    {
        uint dst = smb + O_B + t * 16;
        const char* sh = (const char*)g_W2hi + t * 16;
        #pragma unroll
        for (int i = 0; i < 4; ++i) cp16(dst + i * 4096, sh + i * 4096);
        asm volatile("cp.async.commit_group;");
    }

    for (int i = t; i < 1024; i += 256) b2S[i] = b_e2[i];

    if (t < 128) {
        int e = e0 + t;
        int dd = -1;
        if (e < E) {
            int s = edge_index[e];
            dd = edge_index[E + e];
            const float4* xr = reinterpret_cast<const float4*>(x + (size_t)s * 16);
            #pragma unroll
            for (int q = 0; q < 4; ++q) {
                float4 v = xr[q];
                xT[(q * 4 + 0) * 128 + t] = v.x;
                xT[(q * 4 + 1) * 128 + t] = v.y;
                xT[(q * 4 + 2) * 128 + t] = v.z;
                xT[(q * 4 + 3) * 128 + t] = v.w;
            }
            atomicAdd(&g_cnt[dd], 1.0f);
        } else {
            #pragma unroll
            for (int q = 0; q < 16; ++q) xT[q * 128 + t] = 0.0f;
        }
        dstS[t] = dd;
    }

    // form A = fp16(hid)
    {
        int row = t >> 1;
        int cbase = (t & 1) * 8;
        int e = e0 + row;
        float ea0 = 0.f, ea1 = 0.f, ea2 = 0.f, ea3 = 0.f;
        if (e < E) {
            float4 ea = reinterpret_cast<const float4*>(edge_attr)[e];
            ea0 = ea.x; ea1 = ea.y; ea2 = ea.z; ea3 = ea.w;
        }
        #pragma unroll
        for (int c = cbase; c < cbase + 8; ++c) {
            uint h4[4];
            #pragma unroll
            for (int p = 0; p < 4; ++p) {
                int k0 = c * 8 + p * 2;
                float2 w0 = __ldg((const float2*)(w_e1 + k0));
                float2 w1 = __ldg((const float2*)(w_e1 + 128 + k0));
                float2 w2 = __ldg((const float2*)(w_e1 + 256 + k0));
                float2 w3 = __ldg((const float2*)(w_e1 + 384 + k0));
                float2 bb = __ldg((const float2*)(b_e1 + k0));
                float h0 = fmaf(ea3, w3.x, fmaf(ea2, w2.x, fmaf(ea1, w1.x, fmaf(ea0, w0.x, bb.x))));
                float h1 = fmaf(ea3, w3.y, fmaf(ea2, w2.y, fmaf(ea1, w1.y, fmaf(ea0, w0.y, bb.y))));
                __half2 hh = __floats2half2_rn(fmaxf(h0, 0.0f), fmaxf(h1, 0.0f));
                h4[p] = *reinterpret_cast<uint*>(&hh);
            }
            int off = row * 256 + ((c ^ (row & 7)) << 4);
            *(uint4*)(sm + O_A + off) = make_uint4(h4[0], h4[1], h4[2], h4[3]);
        }
    }

    float macc[2][4][4];
    #pragma unroll
    for (int a = 0; a < 2; ++a)
        #pragma unroll
        for (int b = 0; b < 4; ++b)
            #pragma unroll
            for (int r = 0; r < 4; ++r) macc[a][b][r] = 0.0f;

    uint smA = smb + O_A;

    for (int nc = 0; nc < 16; ++nc) {
        asm volatile("cp.async.wait_group 0;" ::: "memory");
        __syncthreads();
        uint smBbuf = smb + O_B + (nc & 1) * 16384;

        if (nc < 15) {
            uint dst = smb + O_B + ((nc + 1) & 1) * 16384 + t * 16;
            const char* sh = (const char*)g_W2hi + (nc + 1) * 16384 + t * 16;
            #pragma unroll
            for (int i = 0; i < 4; ++i) cp16(dst + i * 4096, sh + i * 4096);
            asm volatile("cp.async.commit_group;");
        }

        float dacc[2][4][4];
        #pragma unroll
        for (int a = 0; a < 2; ++a)
            #pragma unroll
            for (int b = 0; b < 4; ++b)
                #pragma unroll
                for (int r = 0; r < 4; ++r) dacc[a][b][r] = 0.0f;

        #pragma unroll
        for (int kt = 0; kt < 8; ++kt) {
            uint a0[4], a1[4];
            {
                int mi = lane >> 3;
                int arow = mw * 32 + (lane & 7) + (mi & 1) * 8;
                int ac = 2 * kt + (mi >> 1);
                uint addr = smA + arow * 256 + ((ac ^ (arow & 7)) << 4);
                ldsm4(a0, addr);
                ldsm4(a1, addr + 16 * 256);
            }
            uint bh[2][4];
            {
                int mi = lane >> 3;
                int nrow = nw * 32 + (mi >> 1) * 8 + (lane & 7);
                int bc = 2 * kt + (mi & 1);
                uint aH = smBbuf + nrow * 256 + ((bc ^ (nrow & 7)) << 4);
                ldsm4(bh[0], aH);
                ldsm4(bh[1], aH + 4096);
            }
            #pragma unroll
            for (int mt = 0; mt < 2; ++mt) {
                const uint* av = mt ? a1 : a0;
                #pragma unroll
                for (int ng = 0; ng < 2; ++ng) {
                    #pragma unroll
                    for (int s = 0; s < 2; ++s)
                        mma16816(dacc[mt][ng * 2 + s], av, &bh[ng][s * 2]);
                }
            }
        }

        // epilogue: msg += x[e,nc] * (D + b_e2)
        {
            int rb = mw * 32 + (lane >> 2);
            float xv00 = xT[nc * 128 + rb];
            float xv01 = xT[nc * 128 + rb + 8];
            float xv10 = xT[nc * 128 + rb + 16];
            float xv11 = xT[nc * 128 + rb + 24];
            #pragma unroll
            for (int mt = 0; mt < 2; ++mt) {
                float xa = mt ? xv10 : xv00;
                float xb = mt ? xv11 : xv01;
                #pragma unroll
                for (int nt = 0; nt < 4; ++nt) {
                    int col = nw * 32 + nt * 8 + 2 * (lane & 3);
                    float b0v = b2S[nc * 64 + col];
                    float b1v = b2S[nc * 64 + col + 1];
                    macc[mt][nt][0] = fmaf(xa, dacc[mt][nt][0] + b0v, macc[mt][nt][0]);
                    macc[mt][nt][1] = fmaf(xa, dacc[mt][nt][1] + b1v, macc[mt][nt][1]);
                    macc[mt][nt][2] = fmaf(xb, dacc[mt][nt][2] + b0v, macc[mt][nt][2]);
                    macc[mt][nt][3] = fmaf(xb, dacc[mt][nt][3] + b1v, macc[mt][nt][3]);
                }
            }
        }
    }

    // scatter: vectorized reductions (red.v2)
    #pragma unroll
    for (int mt = 0; mt < 2; ++mt) {
        #pragma unroll
        for (int half = 0; half < 2; ++half) {
            int row = mw * 32 + mt * 16 + (lane >> 2) + half * 8;
            int dd = dstS[row];
            if (dd < 0) continue;
            float* mr = g_msum + (size_t)dd * 64;
            #pragma unroll
            for (int nt = 0; nt < 4; ++nt) {
                int col = nw * 32 + nt * 8 + 2 * (lane & 3);
                red2(mr + col, macc[mt][nt][half * 2], macc[mt][nt][half * 2 + 1]);
            }
        }
    }
}

// ---------------- fused node + GRU x3 via HMMA (2-pass W-split, 2m x 4n grid) ----------------
#define G_HS   0        // 64 x 65 f32 = 16640 (col 64 = cnt)
#define G_AHI  16640    // 8192 (overlay: root 4096 + xS 4096 during node phase)
#define G_BHI  24832    // 32768
#define G_BLO  57600    // 32768
#define G_BIAS 90368    // 1024
#define GRU_SMEM 91392

__global__ void __launch_bounds__(256, 2) gru_node_kernel(
    const float* __restrict__ x, const float* __restrict__ root,
    const float* __restrict__ conv_bias, int N)
{
    extern __shared__ char sm2[];
    uint smb = smem_u32(sm2);
    float* hS    = (float*)(sm2 + G_HS);
    float* biasS = (float*)(sm2 + G_BIAS);
    float* rootS = (float*)(sm2 + G_AHI);          // node-phase overlay
    float* xS    = (float*)(sm2 + G_AHI + 4096);

    int t = threadIdx.x, wid = t >> 5, lane = t & 31;
    int n0 = blockIdx.x * 64;

    // stage B (hi+lo, 64 KB)
    {
        const uint4* sh = (const uint4*)g_GBhi;
        const uint4* sl = (const uint4*)g_GBlo;
        uint4* dh = (uint4*)(sm2 + G_BHI);
        uint4* dl = (uint4*)(sm2 + G_BLO);
        #pragma unroll
        for (int i = 0; i < 8; ++i) { dh[t + i * 256] = sh[t + i * 256]; dl[t + i * 256] = sl[t + i * 256]; }
    }
    biasS[t] = g_gbias[t];

    // node-phase staging
    for (int i = t; i < 1024; i += 256) rootS[i] = root[i];
    for (int i = t; i < 1024; i += 256) {
        int r = i >> 4, d = i & 15;
        int n = n0 + r;
        xS[i] = (n < N) ? x[(size_t)n * 16 + d] : 0.0f;
    }
    if (t < 64) {
        int n = n0 + t;
        hS[t * 65 + 64] = (n < N) ? fmaxf(g_cnt[n], 1.0f) : 1.0f;
    }
    __syncthreads();

    // node update: hS = relu(msum/cnt + x@root + conv_bias)
    {
        float cbv = __ldg(conv_bias + (t & 63));
        #pragma unroll
        for (int j = 0; j < 16; ++j) {
            int idx = j * 256 + t;
            int r = idx >> 6, c = idx & 63;
            int n = n0 + r;
            float v = 0.0f;
            if (n < N) {
                float acc = cbv;
                const float* xr = xS + r * 16;
                #pragma unroll
                for (int d = 0; d < 16; ++d) acc = fmaf(xr[d], rootS[d * 64 + c], acc);
                v = fmaxf(g_msum[(size_t)n * 64 + c] / hS[r * 65 + 64] + acc, 0.0f);
            }
            hS[r * 65 + c] = v;
        }
    }
    __syncthreads();

    int mw = wid & 1, nh = wid >> 1;
    int mi = lane >> 3;
    uint smAhi = smb + G_AHI;
    uint smBh = smb + G_BHI, smBl = smb + G_BLO;

    for (int step = 0; step < 3; ++step) {
        // convert hS -> fp16 A (hi only)
        {
            int r = t >> 2, q = t & 3;
            const float* hr = hS + r * 65 + q * 16;
            #pragma unroll
            for (int c2 = 0; c2 < 2; ++c2) {
                uint hi4[4];
                #pragma unroll
                for (int p = 0; p < 4; ++p) {
                    __half2 hh = __floats2half2_rn(hr[c2 * 8 + p * 2], hr[c2 * 8 + p * 2 + 1]);
                    hi4[p] = *reinterpret_cast<uint*>(&hh);
                }
                int cc = q * 2 + c2;
                int off = r * 128 + ((cc ^ (r & 7)) << 4);
                *(uint4*)(sm2 + G_AHI + off) = make_uint4(hi4[0], hi4[1], hi4[2], hi4[3]);
            }
        }
        __syncthreads();

        float acc[16][4];
        #pragma unroll
        for (int i = 0; i < 16; ++i)
            #pragma unroll
            for (int j = 0; j < 4; ++j) acc[i][j] = 0.0f;

        #pragma unroll
        for (int kt = 0; kt < 4; ++kt) {
            uint a0[4], a1[4];
            {
                int arow = mw * 32 + (lane & 7) + (mi & 1) * 8;
                int ac = 2 * kt + (mi >> 1);
                uint aoff = (uint)(arow * 128 + ((ac ^ (arow & 7)) << 4));
                ldsm4(a0, smAhi + aoff);
                ldsm4(a1, smAhi + aoff + 16 * 128);
            }
            #pragma unroll
            for (int g2 = 0; g2 < 4; ++g2) {
                uint bh[4], bl[4];
                int nrow = nh * 64 + g2 * 16 + (mi >> 1) * 8 + (lane & 7);
                int bc = 2 * kt + (mi & 1);
                uint boff = (uint)(nrow * 128 + ((bc ^ (nrow & 7)) << 4));
                ldsm4(bh, smBh + boff);
                ldsm4(bl, smBl + boff);
                // acc index: mt*8 + nt  (nt = g2*2 + s)
                mma16816(acc[0 * 8 + g2 * 2],     a0, bh);
                mma16816(acc[0 * 8 + g2 * 2],     a0, bl);
                mma16816(acc[0 * 8 + g2 * 2 + 1], a0, bh + 2);
                mma16816(acc[0 * 8 + g2 * 2 + 1], a0, bl + 2);
                mma16816(acc[1 * 8 + g2 * 2],     a1, bh);
                mma16816(acc[1 * 8 + g2 * 2],     a1, bl);
                mma16816(acc[1 * 8 + g2 * 2 + 1], a1, bh + 2);
                mma16816(acc[1 * 8 + g2 * 2 + 1], a1, bl + 2);
            }
        }
        __syncthreads();   // A reads complete before next conversion; hS stable for hold reads

        // gates -> h' (in place in hS)
        #pragma unroll
        for (int mt = 0; mt < 2; ++mt) {
            #pragma unroll
            for (int nt = 0; nt < 8; ++nt) {
                float v0 = acc[mt * 8 + nt][0], v1 = acc[mt * 8 + nt][1];
                float v2 = acc[mt * 8 + nt][2], v3 = acc[mt * 8 + nt][3];
                float p0 = __shfl_xor_sync(0xffffffffu, v0, 1);
                float p1 = __shfl_xor_sync(0xffffffffu, v1, 1);
                float p2 = __shfl_xor_sync(0xffffffffu, v2, 1);
                float p3 = __shfl_xor_sync(0xffffffffu, v3, 1);
                if (!(lane & 1)) {
                    int c0 = nh * 64 + nt * 8 + 2 * (lane & 3);
                    int jj = c0 >> 2;
                    float br = biasS[c0], bz = biasS[c0 + 1], bi = biasS[c0 + 2], bn = biasS[c0 + 3];
                    int ra = mw * 32 + mt * 16 + (lane >> 2);
                    {
                        float r = sigm(v0 + br), z = sigm(v1 + bz);
                        float nv = tanhf((p0 + bi) + r * (p1 + bn));
                        float hold = hS[ra * 65 + jj];
                        hS[ra * 65 + jj] = (1.0f - z) * nv + z * hold;
                    }
                    {
                        float r = sigm(v2 + br), z = sigm(v3 + bz);
                        float nv = tanhf((p2 + bi) + r * (p3 + bn));
                        float hold = hS[(ra + 8) * 65 + jj];
                        hS[(ra + 8) * 65 + jj] = (1.0f - z) * nv + z * hold;
                    }
                }
            }
        }
        __syncthreads();
    }

    // coalesced writeback
    #pragma unroll
    for (int j = 0; j < 16; ++j) {
        int idx = j * 256 + t;
        int r = idx >> 6, c = idx & 63;
        int n = n0 + r;
        if (n < N) g_out[(size_t)n * 64 + c] = hS[r * 65 + c];
    }
}

// ---------------- Set2Set LSTM step ----------------
__global__ void __launch_bounds__(256) lstm_kernel(
    const float* __restrict__ wih, const float* __restrict__ whh,
    const float* __restrict__ bih, const float* __restrict__ bhh, int B)
{
    __shared__ float wst[256 * 33];
    __shared__ float qsm[8 * 128];
    __shared__ float hsm[8 * 64];
    __shared__ float gsm[8 * 256];
    int t = threadIdx.x;
    int b0 = blockIdx.x * 8;

    for (int i = t; i < 8 * 128; i += 256) {
        int g = i >> 7, k = i & 127;
        qsm[i] = (b0 + g < B) ? g_S[(b0 + g) * 192 + k] : 0.0f;
    }
    for (int i = t; i < 8 * 64; i += 256) {
        int g = i >> 6, k = i & 63;
        hsm[i] = (b0 + g < B) ? g_S[(b0 + g) * 192 + 128 + k] : 0.0f;
    }

    float acc[8];
    float bsum = bih[t] + bhh[t];
    #pragma unroll
    for (int g = 0; g < 8; ++g) acc[g] = bsum;

    for (int c = 0; c < 4; ++c) {
        __syncthreads();
        for (int i = t; i < 8192; i += 256) {
            int j = i >> 5, kk = i & 31;
            wst[j * 33 + kk] = wih[j * 128 + c * 32 + kk];
        }
        __syncthreads();
        #pragma unroll 8
        for (int kk = 0; kk < 32; ++kk) {
            float w = wst[t * 33 + kk];
            #pragma unroll
            for (int g = 0; g < 8; ++g)
                acc[g] = fmaf(w, qsm[g * 128 + c * 32 + kk], acc[g]);
        }
    }
    for (int c = 0; c < 2; ++c) {
        __syncthreads();
        for (int i = t; i < 8192; i += 256) {
            int j = i >> 5, kk = i & 31;
            wst[j * 33 + kk] = whh[j * 64 + c * 32 + kk];
        }
        __syncthreads();
        #pragma unroll 8
        for (int kk = 0; kk < 32; ++kk) {
            float w = wst[t * 33 + kk];
            #pragma unroll
            for (int g = 0; g < 8; ++g)
                acc[g] = fmaf(w, hsm[g * 64 + c * 32 + kk], acc[g]);
        }
    }

    #pragma unroll
    for (int g = 0; g < 8; ++g) gsm[g * 256 + t] = acc[g];
    __syncthreads();

    for (int i = t; i < 8 * 64; i += 256) {
        int g = i >> 6, hh = i & 63;
        int b = b0 + g;
        if (b >= B) continue;
        float ig = sigm(gsm[g * 256 + hh]);
        float fg = sigm(gsm[g * 256 + 64 + hh]);
        float gg = tanhf(gsm[g * 256 + 128 + hh]);
        float og = sigm(gsm[g * 256 + 192 + hh]);
        float cnew = fg * g_cl[b * 64 + hh] + ig * gg;
        g_cl[b * 64 + hh] = cnew;
        g_S[b * 192 + 128 + hh] = og * tanhf(cnew);
    }
}

// ---------------- Set2Set attention step (128 threads / graph) ----------------
__global__ void __launch_bounds__(128) attn_kernel(int B)
{
    __shared__ float qs[64];
    __shared__ float wm[4], ws[4];
    __shared__ float rgS[64];
    int t = threadIdx.x, b = blockIdx.x;
    if (t < 64) qs[t] = g_S[b * 192 + 128 + t];
    __syncthreads();
    int n0 = g_seg[b], n1 = g_seg[b + 1];
    int w = t >> 5, lid = t & 31;

    float mr = -1e30f, sr = 0.0f;
    for (int n = n0 + w; n < n1; n += 4) {
        const float* orow = g_out + (size_t)n * 64;
        float p = orow[lid] * qs[lid] + orow[32 + lid] * qs[32 + lid];
        #pragma unroll
        for (int off = 16; off; off >>= 1) p += __shfl_xor_sync(0xffffffffu, p, off);
        if (lid == 0) g_cnt[n] = p;
        if (p > mr) { sr *= __expf(mr - p); mr = p; }
        sr += __expf(p - mr);
    }
    if (lid == 0) { wm[w] = mr; ws[w] = sr; }
    __syncthreads();
    float m = fmaxf(fmaxf(wm[0], wm[1]), fmaxf(wm[2], wm[3]));
    float denom = ws[0] * __expf(wm[0] - m) + ws[1] * __expf(wm[1] - m)
                + ws[2] * __expf(wm[2] - m) + ws[3] * __expf(wm[3] - m);

    int col = t & 63, half = t >> 6;
    float rg = 0.0f;
    for (int n = n0 + half; n < n1; n += 2)
        rg = fmaf(__expf(g_cnt[n] - m), g_out[(size_t)n * 64 + col], rg);
    if (half) rgS[col] = rg;
    __syncthreads();
    if (!half) {
        rg += rgS[col];
        if (n1 > n0) rg /= denom;
        g_S[b * 192 + col]      = qs[col];
        g_S[b * 192 + 64 + col] = rg;
    }
}

// ---------------- readout ----------------
__global__ void __launch_bounds__(64) readout_kernel(
    const float* __restrict__ fc1_w, const float* __restrict__ fc1_b,
    const float* __restrict__ fc2_w, const float* __restrict__ fc2_b,
    float* __restrict__ y, int B)
{
    __shared__ float qsm[8 * 128];
    __shared__ float red[2];
    int t = threadIdx.x;
    int b0 = blockIdx.x * 8;
    for (int i = t; i < 1024; i += 64) {
        int g = i >> 7, k = i & 127;
        qsm[i] = (b0 + g < B) ? g_S[(b0 + g) * 192 + k] : 0.0f;
    }
    __syncthreads();
    float w2 = fc2_w[t];
    float b1 = fc1_b[t];
    for (int g = 0; g < 8; ++g) {
        float a = b1;
        #pragma unroll 8
        for (int k = 0; k < 128; ++k) a = fmaf(qsm[g * 128 + k], fc1_w[k * 64 + t], a);
        a = fmaxf(a, 0.0f);
        float p = a * w2;
        #pragma unroll
        for (int off = 16; off; off >>= 1) p += __shfl_xor_sync(0xffffffffu, p, off);
        if ((t & 31) == 0) red[t >> 5] = p;
        __syncthreads();
        if (t == 0 && b0 + g < B) y[b0 + g] = red[0] + red[1] + fc2_b[0];
        __syncthreads();
    }
}

// ---------------- launch ----------------
extern "C" void kernel_launch(void* const* d_in, const int* in_sizes, int n_in,
                              void* d_out, int out_size)
{
    const float* x         = (const float*)d_in[0];
    const float* edge_attr = (const float*)d_in[1];
    const int*   edge_index= (const int*)  d_in[2];
    const int*   batch     = (const int*)  d_in[3];
    const float* w_e1      = (const float*)d_in[4];
    const float* b_e1      = (const float*)d_in[5];
    const float* w_e2      = (const float*)d_in[6];
    const float* b_e2      = (const float*)d_in[7];
    const float* root      = (const float*)d_in[8];
    const float* conv_bias = (const float*)d_in[9];
    const float* gru_wih   = (const float*)d_in[10];
    const float* gru_whh   = (const float*)d_in[11];
    const float* gru_bih   = (const float*)d_in[12];
    const float* gru_bhh   = (const float*)d_in[13];
    const float* lstm_wih  = (const float*)d_in[14];
    const float* lstm_whh  = (const float*)d_in[15];
    const float* lstm_bih  = (const float*)d_in[16];
    const float* lstm_bhh  = (const float*)d_in[17];
    const float* fc1_w     = (const float*)d_in[18];
    const float* fc1_b     = (const float*)d_in[19];
    const float* fc2_w     = (const float*)d_in[20];
    const float* fc2_b     = (const float*)d_in[21];
    float* y = (float*)d_out;

    int N = in_sizes[0] / 16;
    int E = in_sizes[1] / 4;
    int B = out_size;

    static int smem_set = 0;
    if (!smem_set) {
        cudaFuncSetAttribute(edge_kernel3, cudaFuncAttributeMaxDynamicSharedMemorySize, EK3_SMEM);
        cudaFuncSetAttribute(gru_node_kernel, cudaFuncAttributeMaxDynamicSharedMemorySize, GRU_SMEM);
        smem_set = 1;
    }

    // gru_node_kernel is deliberately the 4th launch (ncu capture window).
    prep_kernel<<<577, 256>>>(w_e2, gru_wih, gru_whh, gru_bih, gru_bhh);
    zero_kernel<<<1024, 256>>>(N, B);
    edge_kernel3<<<(E + 127) / 128, 256, EK3_SMEM>>>(x, edge_attr, edge_index, w_e1, b_e1, b_e2, E);
    gru_node_kernel<<<(N + 63) / 64, 256, GRU_SMEM>>>(x, root, conv_bias, N);
    seg_kernel<<<(B + 1 + 127) / 128, 128>>>(batch, N, B);
    for (int i = 0; i < 3; ++i) {
        lstm_kernel<<<(B + 7) / 8, 256>>>(lstm_wih, lstm_whh, lstm_bih, lstm_bhh, B);
        attn_kernel<<<B, 128>>>(B);
    }
    readout_kernel<<<(B + 7) / 8, 64>>>(fc1_w, fc1_b, fc2_w, fc2_b, y, B);
}

// round 11
// speedup vs baseline: 4.2262x; 1.2001x over previous
#include <cuda_runtime.h>
#include <cuda_bf16.h>
#include <cuda_fp16.h>
#include <math.h>

typedef unsigned long long ull;
typedef unsigned int uint;

#define MAXN 131072
#define MAXE 262144
#define MAXB 4096

// ---------------- device scratch ----------------
__device__ float g_msum[(size_t)MAXN * 64];
__device__ float g_cnt[MAXN];              // reused as attention e-buffer later
__device__ float g_out[(size_t)MAXN * 64];
__device__ float g_S[MAXB * 192];          // per graph: [0:128]=q_star, [128:192]=hl
__device__ float g_cl[MAXB * 64];
__device__ int   g_seg[MAXB + 1];
// edge GEMM: fp16 w_e2 (single), per-chunk smem images (16 chunks x 16384 B)
__device__ unsigned char g_W2hi[16 * 16384];
// GRU GEMM: Wg fp16 hi/lo smem images [256 rows x 128 B], epilogue-friendly col order
__device__ unsigned char g_GBhi[32768];
__device__ unsigned char g_GBlo[32768];
__device__ float g_gbias[256];

// ---------------- helpers ----------------
__device__ __forceinline__ float fast_sigm(float x) {
    x = fminf(fmaxf(x, -30.0f), 30.0f);
    return __fdividef(1.0f, 1.0f + __expf(-x));
}
__device__ __forceinline__ float fast_tanh(float x) {
    x = fminf(fmaxf(x, -15.0f), 15.0f);
    float t = __expf(2.0f * x);
    return 1.0f - __fdividef(2.0f, 1.0f + t);
}
__device__ __forceinline__ uint smem_u32(const void* p) {
    uint a; asm("{ .reg .u64 t; cvta.to.shared.u64 t, %1; cvt.u32.u64 %0, t; }" : "=r"(a) : "l"(p));
    return a;
}
__device__ __forceinline__ void ldsm4(uint* r, uint addr) {
    asm volatile("ldmatrix.sync.aligned.m8n8.x4.shared.b16 {%0,%1,%2,%3}, [%4];"
        : "=r"(r[0]), "=r"(r[1]), "=r"(r[2]), "=r"(r[3]) : "r"(addr));
}
__device__ __forceinline__ void mma16816(float* d, const uint* a, const uint* b) {
    asm volatile("mma.sync.aligned.m16n8k16.row.col.f32.f16.f16.f32 "
        "{%0,%1,%2,%3}, {%4,%5,%6,%7}, {%8,%9}, {%0,%1,%2,%3};"
        : "+f"(d[0]), "+f"(d[1]), "+f"(d[2]), "+f"(d[3])
        : "r"(a[0]), "r"(a[1]), "r"(a[2]), "r"(a[3]), "r"(b[0]), "r"(b[1]));
}
__device__ __forceinline__ void cp16(uint dst, const void* src) {
    asm volatile("cp.async.ca.shared.global [%0], [%1], 16;" :: "r"(dst), "l"(src));
}
__device__ __forceinline__ void red2(float* p, float a, float b) {
    asm volatile("red.global.add.v2.f32 [%0], {%1, %2};" :: "l"(p), "f"(a), "f"(b) : "memory");
}

// ---------------- zero scratch ----------------
__global__ void zero_kernel(int N, int B) {
    int idx = blockIdx.x * blockDim.x + threadIdx.x;
    int stride = gridDim.x * blockDim.x;
    float4 z4 = make_float4(0.f, 0.f, 0.f, 0.f);
    int nm4 = N * 16;
    float4* m4 = (float4*)g_msum;
    for (int i = idx; i < nm4; i += stride) m4[i] = z4;
    for (int i = idx; i < N; i += stride) g_cnt[i] = 0.0f;
    int ns = B * 192;
    for (int i = idx; i < ns; i += stride) g_S[i] = 0.0f;
    int nc = B * 64;
    for (int i = idx; i < nc; i += stride) g_cl[i] = 0.0f;
}

// ---------------- segment offsets ----------------
__global__ void seg_kernel(const int* __restrict__ batch, int N, int B) {
    int b = blockIdx.x * blockDim.x + threadIdx.x;
    if (b > B) return;
    int lo = 0, hi = N;
    while (lo < hi) { int mid = (lo + hi) >> 1; if (batch[mid] < b) lo = mid + 1; else hi = mid; }
    g_seg[b] = lo;
}

// ---------------- merged prep ----------------
// GRU col mapping (epilogue-friendly): col c -> (j, gate):
//   w=c>>6, rem=c&63, half=rem>>5, within=rem&31, tile=within>>3, colin=within&7
//   j = w*16 + tile*4 + (colin>>1); gate = half*2 + (colin&1)  [0=r,1=z,2=inn,3=hn]
__device__ __forceinline__ void gru_col_decode(int c, int& j, int& gate) {
    int w = c >> 6, rem = c & 63;
    int half = rem >> 5, within = rem & 31;
    int tile = within >> 3, colin = within & 7;
    j = w * 16 + tile * 4 + (colin >> 1);
    gate = half * 2 + (colin & 1);
}

__global__ void prep_kernel(const float* __restrict__ w_e2,
                            const float* __restrict__ wih, const float* __restrict__ whh,
                            const float* __restrict__ bih, const float* __restrict__ bhh) {
    int bid = blockIdx.x;
    if (bid < 512) {
        int idx = bid * 256 + threadIdx.x;
        int m = idx >> 10, j = idx & 1023;     // m = k, j = d*64+h
        __half hi = __float2half_rn(w_e2[idx]);
        int nc = j >> 6, r = j & 63;
        int c = m >> 3;
        int off = r * 256 + ((c ^ (r & 7)) << 4) + (m & 7) * 2;
        *(__half*)(g_W2hi + nc * 16384 + off) = hi;
    } else {
        int idx = (bid - 512) * 256 + threadIdx.x;
        if (idx < 16384) {
            int c = idx >> 6, k = idx & 63;
            int j, gate;
            gru_col_decode(c, j, gate);
            float v;
            if (gate == 0)      v = wih[j * 64 + k] + whh[j * 64 + k];
            else if (gate == 1) v = wih[(64 + j) * 64 + k] + whh[(64 + j) * 64 + k];
            else if (gate == 2) v = wih[(128 + j) * 64 + k];
            else                v = whh[(128 + j) * 64 + k];
            __half hi = __float2half_rn(v);
            __half lo = __float2half_rn(v - __half2float(hi));
            int off = c * 128 + (((k >> 3) ^ (c & 7)) << 4) + (k & 7) * 2;
            *(__half*)(g_GBhi + off) = hi;
            *(__half*)(g_GBlo + off) = lo;
        } else if (idx < 16640) {
            int c = idx - 16384;
            int j, gate;
            gru_col_decode(c, j, gate);
            float v;
            if (gate == 0)      v = bih[j] + bhh[j];
            else if (gate == 1) v = bih[64 + j] + bhh[64 + j];
            else if (gate == 2) v = bih[128 + j];
            else                v = bhh[128 + j];
            g_gbias[c] = v;
        }
    }
}

// ---------------- edge kernel: HMMA (single-pass fp16) ----------------
#define O_A   0          // 32768 (A hid fp16, 128 rows x 256 B)
#define O_B   32768      // 2 x 16384 double buffer
#define O_XT  65536      // 8192  (xT [16][128] f32)
#define O_B2  73728      // 4096  (b_e2 1024 f32)
#define O_DST 77824      // 512
#define EK3_SMEM 78336

__global__ void __launch_bounds__(256, 2) edge_kernel3(
    const float* __restrict__ x, const float* __restrict__ edge_attr,
    const int* __restrict__ edge_index,
    const float* __restrict__ w_e1, const float* __restrict__ b_e1,
    const float* __restrict__ b_e2, int E)
{
    extern __shared__ char sm[];
    uint smb = smem_u32(sm);
    float* xT  = (float*)(sm + O_XT);
    float* b2S = (float*)(sm + O_B2);
    int*  dstS = (int*)(sm + O_DST);

    int t = threadIdx.x;
    int wid = t >> 5, lane = t & 31;
    int mw = wid & 3, nw = wid >> 2;
    int e0 = blockIdx.x * 128;

    // prefetch B chunk 0 (16 KB)
    {
        uint dst = smb + O_B + t * 16;
        const char* sh = (const char*)g_W2hi + t * 16;
        #pragma unroll
        for (int i = 0; i < 4; ++i) cp16(dst + i * 4096, sh + i * 4096);
        asm volatile("cp.async.commit_group;");
    }

    for (int i = t; i < 1024; i += 256) b2S[i] = b_e2[i];

    if (t < 128) {
        int e = e0 + t;
        int dd = -1;
        if (e < E) {
            int s = edge_index[e];
            dd = edge_index[E + e];
            const float4* xr = reinterpret_cast<const float4*>(x + (size_t)s * 16);
            #pragma unroll
            for (int q = 0; q < 4; ++q) {
                float4 v = xr[q];
                xT[(q * 4 + 0) * 128 + t] = v.x;
                xT[(q * 4 + 1) * 128 + t] = v.y;
                xT[(q * 4 + 2) * 128 + t] = v.z;
                xT[(q * 4 + 3) * 128 + t] = v.w;
            }
            atomicAdd(&g_cnt[dd], 1.0f);
        } else {
            #pragma unroll
            for (int q = 0; q < 16; ++q) xT[q * 128 + t] = 0.0f;
        }
        dstS[t] = dd;
    }

    // form A = fp16(hid)
    {
        int row = t >> 1;
        int cbase = (t & 1) * 8;
        int e = e0 + row;
        float ea0 = 0.f, ea1 = 0.f, ea2 = 0.f, ea3 = 0.f;
        if (e < E) {
            float4 ea = reinterpret_cast<const float4*>(edge_attr)[e];
            ea0 = ea.x; ea1 = ea.y; ea2 = ea.z; ea3 = ea.w;
        }
        #pragma unroll
        for (int c = cbase; c < cbase + 8; ++c) {
            uint h4[4];
            #pragma unroll
            for (int p = 0; p < 4; ++p) {
                int k0 = c * 8 + p * 2;
                float2 w0 = __ldg((const float2*)(w_e1 + k0));
                float2 w1 = __ldg((const float2*)(w_e1 + 128 + k0));
                float2 w2 = __ldg((const float2*)(w_e1 + 256 + k0));
                float2 w3 = __ldg((const float2*)(w_e1 + 384 + k0));
                float2 bb = __ldg((const float2*)(b_e1 + k0));
                float h0 = fmaf(ea3, w3.x, fmaf(ea2, w2.x, fmaf(ea1, w1.x, fmaf(ea0, w0.x, bb.x))));
                float h1 = fmaf(ea3, w3.y, fmaf(ea2, w2.y, fmaf(ea1, w1.y, fmaf(ea0, w0.y, bb.y))));
                __half2 hh = __floats2half2_rn(fmaxf(h0, 0.0f), fmaxf(h1, 0.0f));
                h4[p] = *reinterpret_cast<uint*>(&hh);
            }
            int off = row * 256 + ((c ^ (row & 7)) << 4);
            *(uint4*)(sm + O_A + off) = make_uint4(h4[0], h4[1], h4[2], h4[3]);
        }
    }

    float macc[2][4][4];
    #pragma unroll
    for (int a = 0; a < 2; ++a)
        #pragma unroll
        for (int b = 0; b < 4; ++b)
            #pragma unroll
            for (int r = 0; r < 4; ++r) macc[a][b][r] = 0.0f;

    uint smA = smb + O_A;

    for (int nc = 0; nc < 16; ++nc) {
        asm volatile("cp.async.wait_group 0;" ::: "memory");
        __syncthreads();
        uint smBbuf = smb + O_B + (nc & 1) * 16384;

        if (nc < 15) {
            uint dst = smb + O_B + ((nc + 1) & 1) * 16384 + t * 16;
            const char* sh = (const char*)g_W2hi + (nc + 1) * 16384 + t * 16;
            #pragma unroll
            for (int i = 0; i < 4; ++i) cp16(dst + i * 4096, sh + i * 4096);
            asm volatile("cp.async.commit_group;");
        }

        float dacc[2][4][4];
        #pragma unroll
        for (int a = 0; a < 2; ++a)
            #pragma unroll
            for (int b = 0; b < 4; ++b)
                #pragma unroll
                for (int r = 0; r < 4; ++r) dacc[a][b][r] = 0.0f;

        #pragma unroll
        for (int kt = 0; kt < 8; ++kt) {
            uint a0[4], a1[4];
            {
                int mi = lane >> 3;
                int arow = mw * 32 + (lane & 7) + (mi & 1) * 8;
                int ac = 2 * kt + (mi >> 1);
                uint addr = smA + arow * 256 + ((ac ^ (arow & 7)) << 4);
                ldsm4(a0, addr);
                ldsm4(a1, addr + 16 * 256);
            }
            uint bh[2][4];
            {
                int mi = lane >> 3;
                int nrow = nw * 32 + (mi >> 1) * 8 + (lane & 7);
                int bc = 2 * kt + (mi & 1);
                uint aH = smBbuf + nrow * 256 + ((bc ^ (nrow & 7)) << 4);
                ldsm4(bh[0], aH);
                ldsm4(bh[1], aH + 4096);
            }
            #pragma unroll
            for (int mt = 0; mt < 2; ++mt) {
                const uint* av = mt ? a1 : a0;
                #pragma unroll
                for (int ng = 0; ng < 2; ++ng) {
                    #pragma unroll
                    for (int s = 0; s < 2; ++s)
                        mma16816(dacc[mt][ng * 2 + s], av, &bh[ng][s * 2]);
                }
            }
        }

        // epilogue: msg += x[e,nc] * (D + b_e2)
        {
            int rb = mw * 32 + (lane >> 2);
            float xv00 = xT[nc * 128 + rb];
            float xv01 = xT[nc * 128 + rb + 8];
            float xv10 = xT[nc * 128 + rb + 16];
            float xv11 = xT[nc * 128 + rb + 24];
            #pragma unroll
            for (int mt = 0; mt < 2; ++mt) {
                float xa = mt ? xv10 : xv00;
                float xb = mt ? xv11 : xv01;
                #pragma unroll
                for (int nt = 0; nt < 4; ++nt) {
                    int col = nw * 32 + nt * 8 + 2 * (lane & 3);
                    float b0v = b2S[nc * 64 + col];
                    float b1v = b2S[nc * 64 + col + 1];
                    macc[mt][nt][0] = fmaf(xa, dacc[mt][nt][0] + b0v, macc[mt][nt][0]);
                    macc[mt][nt][1] = fmaf(xa, dacc[mt][nt][1] + b1v, macc[mt][nt][1]);
                    macc[mt][nt][2] = fmaf(xb, dacc[mt][nt][2] + b0v, macc[mt][nt][2]);
                    macc[mt][nt][3] = fmaf(xb, dacc[mt][nt][3] + b1v, macc[mt][nt][3]);
                }
            }
        }
    }

    // scatter: vectorized reductions (red.v2)
    #pragma unroll
    for (int mt = 0; mt < 2; ++mt) {
        #pragma unroll
        for (int half = 0; half < 2; ++half) {
            int row = mw * 32 + mt * 16 + (lane >> 2) + half * 8;
            int dd = dstS[row];
            if (dd < 0) continue;
            float* mr = g_msum + (size_t)dd * 64;
            #pragma unroll
            for (int nt = 0; nt < 4; ++nt) {
                int col = nw * 32 + nt * 8 + 2 * (lane & 3);
                red2(mr + col, macc[mt][nt][half * 2], macc[mt][nt][half * 2 + 1]);
            }
        }
    }
}

// ---------------- fused node + GRU x3 via HMMA (2-pass W-split, 2m x 4n grid) ----------------
#define G_HS   0        // 64 x 65 f32 = 16640 (col 64 = cnt)
#define G_AHI  16640    // 8192 (overlay: root 4096 + xS 4096 during node phase)
#define G_BHI  24832    // 32768
#define G_BLO  57600    // 32768
#define G_BIAS 90368    // 1024
#define GRU_SMEM 91392

__global__ void __launch_bounds__(256, 2) gru_node_kernel(
    const float* __restrict__ x, const float* __restrict__ root,
    const float* __restrict__ conv_bias, int N)
{
    extern __shared__ char sm2[];
    uint smb = smem_u32(sm2);
    float* hS    = (float*)(sm2 + G_HS);
    float* biasS = (float*)(sm2 + G_BIAS);
    float* rootS = (float*)(sm2 + G_AHI);          // node-phase overlay
    float* xS    = (float*)(sm2 + G_AHI + 4096);

    int t = threadIdx.x, wid = t >> 5, lane = t & 31;
    int n0 = blockIdx.x * 64;

    // stage B (hi+lo, 64 KB) asynchronously — overlaps node phase
    {
        uint dh = smb + G_BHI + t * 16;
        uint dl = smb + G_BLO + t * 16;
        const char* sh = (const char*)g_GBhi + t * 16;
        const char* sl = (const char*)g_GBlo + t * 16;
        #pragma unroll
        for (int i = 0; i < 8; ++i) cp16(dh + i * 4096, sh + i * 4096);
        #pragma unroll
        for (int i = 0; i < 8; ++i) cp16(dl + i * 4096, sl + i * 4096);
        asm volatile("cp.async.commit_group;");
    }
    biasS[t] = g_gbias[t];

    // node-phase staging
    for (int i = t; i < 1024; i += 256) rootS[i] = root[i];
    for (int i = t; i < 1024; i += 256) {
        int r = i >> 4, d = i & 15;
        int n = n0 + r;
        xS[i] = (n < N) ? x[(size_t)n * 16 + d] : 0.0f;
    }
    if (t < 64) {
        int n = n0 + t;
        hS[t * 65 + 64] = (n < N) ? fmaxf(g_cnt[n], 1.0f) : 1.0f;
    }
    __syncthreads();

    // node update: hS = relu(msum/cnt + x@root + conv_bias)
    {
        float cbv = __ldg(conv_bias + (t & 63));
        #pragma unroll
        for (int j = 0; j < 16; ++j) {
            int idx = j * 256 + t;
            int r = idx >> 6, c = idx & 63;
            int n = n0 + r;
            float v = 0.0f;
            if (n < N) {
                float acc = cbv;
                const float* xr = xS + r * 16;
                #pragma unroll
                for (int d = 0; d < 16; ++d) acc = fmaf(xr[d], rootS[d * 64 + c], acc);
                v = fmaxf(g_msum[(size_t)n * 64 + c] / hS[r * 65 + 64] + acc, 0.0f);
            }
            hS[r * 65 + c] = v;
        }
    }
    asm volatile("cp.async.wait_group 0;" ::: "memory");
    __syncthreads();

    int mw = wid & 1, nh = wid >> 1;
    int mi = lane >> 3;
    uint smAhi = smb + G_AHI;
    uint smBh = smb + G_BHI, smBl = smb + G_BLO;

    for (int step = 0; step < 3; ++step) {
        // convert hS -> fp16 A (hi only)
        {
            int r = t >> 2, q = t & 3;
            const float* hr = hS + r * 65 + q * 16;
            #pragma unroll
            for (int c2 = 0; c2 < 2; ++c2) {
                uint hi4[4];
                #pragma unroll
                for (int p = 0; p < 4; ++p) {
                    __half2 hh = __floats2half2_rn(hr[c2 * 8 + p * 2], hr[c2 * 8 + p * 2 + 1]);
                    hi4[p] = *reinterpret_cast<uint*>(&hh);
                }
                int cc = q * 2 + c2;
                int off = r * 128 + ((cc ^ (r & 7)) << 4);
                *(uint4*)(sm2 + G_AHI + off) = make_uint4(hi4[0], hi4[1], hi4[2], hi4[3]);
            }
        }
        __syncthreads();

        float acc[16][4];
        #pragma unroll
        for (int i = 0; i < 16; ++i)
            #pragma unroll
            for (int j = 0; j < 4; ++j) acc[i][j] = 0.0f;

        #pragma unroll
        for (int kt = 0; kt < 4; ++kt) {
            uint a0[4], a1[4];
            {
                int arow = mw * 32 + (lane & 7) + (mi & 1) * 8;
                int ac = 2 * kt + (mi >> 1);
                uint aoff = (uint)(arow * 128 + ((ac ^ (arow & 7)) << 4));
                ldsm4(a0, smAhi + aoff);
                ldsm4(a1, smAhi + aoff + 16 * 128);
            }
            #pragma unroll
            for (int g2 = 0; g2 < 4; ++g2) {
                uint bh[4], bl[4];
                int nrow = nh * 64 + g2 * 16 + (mi >> 1) * 8 + (lane & 7);
                int bc = 2 * kt + (mi & 1);
                uint boff = (uint)(nrow * 128 + ((bc ^ (nrow & 7)) << 4));
                ldsm4(bh, smBh + boff);
                ldsm4(bl, smBl + boff);
                mma16816(acc[0 * 8 + g2 * 2],     a0, bh);
                mma16816(acc[0 * 8 + g2 * 2],     a0, bl);
                mma16816(acc[0 * 8 + g2 * 2 + 1], a0, bh + 2);
                mma16816(acc[0 * 8 + g2 * 2 + 1], a0, bl + 2);
                mma16816(acc[1 * 8 + g2 * 2],     a1, bh);
                mma16816(acc[1 * 8 + g2 * 2],     a1, bl);
                mma16816(acc[1 * 8 + g2 * 2 + 1], a1, bh + 2);
                mma16816(acc[1 * 8 + g2 * 2 + 1], a1, bl + 2);
            }
        }
        __syncthreads();   // A reads complete before h' overwrite

        // gates -> h' (no shuffles: rz tiles 0..3 pair with inhn tiles 4..7, same lane/j)
        {
            int qj = lane & 3;
            int rb = lane >> 2;
            #pragma unroll
            for (int mt = 0; mt < 2; ++mt) {
                #pragma unroll
                for (int tp = 0; tp < 4; ++tp) {
                    float* aRZ = acc[mt * 8 + tp];
                    float* aNH = acc[mt * 8 + tp + 4];
                    int cb = nh * 64 + tp * 8 + 2 * qj;
                    float br = biasS[cb],      bz = biasS[cb + 1];
                    float bi = biasS[cb + 32], bn = biasS[cb + 33];
                    int j = nh * 16 + tp * 4 + qj;
                    int ra = mw * 32 + mt * 16 + rb;
                    {
                        float r = fast_sigm(aRZ[0] + br), z = fast_sigm(aRZ[1] + bz);
                        float nv = fast_tanh((aNH[0] + bi) + r * (aNH[1] + bn));
                        float hold = hS[ra * 65 + j];
                        hS[ra * 65 + j] = (1.0f - z) * nv + z * hold;
                    }
                    {
                        float r = fast_sigm(aRZ[2] + br), z = fast_sigm(aRZ[3] + bz);
                        float nv = fast_tanh((aNH[2] + bi) + r * (aNH[3] + bn));
                        float hold = hS[(ra + 8) * 65 + j];
                        hS[(ra + 8) * 65 + j] = (1.0f - z) * nv + z * hold;
                    }
                }
            }
        }
        __syncthreads();
    }

    // coalesced writeback
    #pragma unroll
    for (int j = 0; j < 16; ++j) {
        int idx = j * 256 + t;
        int r = idx >> 6, c = idx & 63;
        int n = n0 + r;
        if (n < N) g_out[(size_t)n * 64 + c] = hS[r * 65 + c];
    }
}

// ---------------- Set2Set LSTM step ----------------
__global__ void __launch_bounds__(256) lstm_kernel(
    const float* __restrict__ wih, const float* __restrict__ whh,
    const float* __restrict__ bih, const float* __restrict__ bhh, int B)
{
    __shared__ float wst[256 * 33];
    __shared__ float qsm[8 * 128];
    __shared__ float hsm[8 * 64];
    __shared__ float gsm[8 * 256];
    int t = threadIdx.x;
    int b0 = blockIdx.x * 8;

    for (int i = t; i < 8 * 128; i += 256) {
        int g = i >> 7, k = i & 127;
        qsm[i] = (b0 + g < B) ? g_S[(b0 + g) * 192 + k] : 0.0f;
    }
    for (int i = t; i < 8 * 64; i += 256) {
        int g = i >> 6, k = i & 63;
        hsm[i] = (b0 + g < B) ? g_S[(b0 + g) * 192 + 128 + k] : 0.0f;
    }

    float acc[8];
    float bsum = bih[t] + bhh[t];
    #pragma unroll
    for (int g = 0; g < 8; ++g) acc[g] = bsum;

    for (int c = 0; c < 4; ++c) {
        __syncthreads();
        for (int i = t; i < 8192; i += 256) {
            int j = i >> 5, kk = i & 31;
            wst[j * 33 + kk] = wih[j * 128 + c * 32 + kk];
        }
        __syncthreads();
        #pragma unroll 8
        for (int kk = 0; kk < 32; ++kk) {
            float w = wst[t * 33 + kk];
            #pragma unroll
            for (int g = 0; g < 8; ++g)
                acc[g] = fmaf(w, qsm[g * 128 + c * 32 + kk], acc[g]);
        }
    }
    for (int c = 0; c < 2; ++c) {
        __syncthreads();
        for (int i = t; i < 8192; i += 256) {
            int j = i >> 5, kk = i & 31;
            wst[j * 33 + kk] = whh[j * 64 + c * 32 + kk];
        }
        __syncthreads();
        #pragma unroll 8
        for (int kk = 0; kk < 32; ++kk) {
            float w = wst[t * 33 + kk];
            #pragma unroll
            for (int g = 0; g < 8; ++g)
                acc[g] = fmaf(w, hsm[g * 64 + c * 32 + kk], acc[g]);
        }
    }

    #pragma unroll
    for (int g = 0; g < 8; ++g) gsm[g * 256 + t] = acc[g];
    __syncthreads();

    for (int i = t; i < 8 * 64; i += 256) {
        int g = i >> 6, hh = i & 63;
        int b = b0 + g;
        if (b >= B) continue;
        float ig = fast_sigm(gsm[g * 256 + hh]);
        float fg = fast_sigm(gsm[g * 256 + 64 + hh]);
        float gg = fast_tanh(gsm[g * 256 + 128 + hh]);
        float og = fast_sigm(gsm[g * 256 + 192 + hh]);
        float cnew = fg * g_cl[b * 64 + hh] + ig * gg;
        g_cl[b * 64 + hh] = cnew;
        g_S[b * 192 + 128 + hh] = og * fast_tanh(cnew);
    }
}

// ---------------- Set2Set attention step (128 threads / graph) ----------------
__global__ void __launch_bounds__(128) attn_kernel(int B)
{
    __shared__ float qs[64];
    __shared__ float wm[4], ws[4];
    __shared__ float rgS[64];
    int t = threadIdx.x, b = blockIdx.x;
    if (t < 64) qs[t] = g_S[b * 192 + 128 + t];
    __syncthreads();
    int n0 = g_seg[b], n1 = g_seg[b + 1];
    int w = t >> 5, lid = t & 31;

    float mr = -1e30f, sr = 0.0f;
    for (int n = n0 + w; n < n1; n += 4) {
        const float* orow = g_out + (size_t)n * 64;
        float p = orow[lid] * qs[lid] + orow[32 + lid] * qs[32 + lid];
        #pragma unroll
        for (int off = 16; off; off >>= 1) p += __shfl_xor_sync(0xffffffffu, p, off);
        if (lid == 0) g_cnt[n] = p;
        if (p > mr) { sr *= __expf(mr - p); mr = p; }
        sr += __expf(p - mr);
    }
    if (lid == 0) { wm[w] = mr; ws[w] = sr; }
    __syncthreads();
    float m = fmaxf(fmaxf(wm[0], wm[1]), fmaxf(wm[2], wm[3]));
    float denom = ws[0] * __expf(wm[0] - m) + ws[1] * __expf(wm[1] - m)
                + ws[2] * __expf(wm[2] - m) + ws[3] * __expf(wm[3] - m);

    int col = t & 63, half = t >> 6;
    float rg = 0.0f;
    for (int n = n0 + half; n < n1; n += 2)
        rg = fmaf(__expf(g_cnt[n] - m), g_out[(size_t)n * 64 + col], rg);
    if (half) rgS[col] = rg;
    __syncthreads();
    if (!half) {
        rg += rgS[col];
        if (n1 > n0) rg /= denom;
        g_S[b * 192 + col]      = qs[col];
        g_S[b * 192 + 64 + col] = rg;
    }
}

// ---------------- readout ----------------
__global__ void __launch_bounds__(64) readout_kernel(
    const float* __restrict__ fc1_w, const float* __restrict__ fc1_b,
    const float* __restrict__ fc2_w, const float* __restrict__ fc2_b,
    float* __restrict__ y, int B)
{
    __shared__ float qsm[8 * 128];
    __shared__ float red[2];
    int t = threadIdx.x;
    int b0 = blockIdx.x * 8;
    for (int i = t; i < 1024; i += 64) {
        int g = i >> 7, k = i & 127;
        qsm[i] = (b0 + g < B) ? g_S[(b0 + g) * 192 + k] : 0.0f;
    }
    __syncthreads();
    float w2 = fc2_w[t];
    float b1 = fc1_b[t];
    for (int g = 0; g < 8; ++g) {
        float a = b1;
        #pragma unroll 8
        for (int k = 0; k < 128; ++k) a = fmaf(qsm[g * 128 + k], fc1_w[k * 64 + t], a);
        a = fmaxf(a, 0.0f);
        float p = a * w2;
        #pragma unroll
        for (int off = 16; off; off >>= 1) p += __shfl_xor_sync(0xffffffffu, p, off);
        if ((t & 31) == 0) red[t >> 5] = p;
        __syncthreads();
        if (t == 0 && b0 + g < B) y[b0 + g] = red[0] + red[1] + fc2_b[0];
        __syncthreads();
    }
}

// ---------------- launch ----------------
extern "C" void kernel_launch(void* const* d_in, const int* in_sizes, int n_in,
                              void* d_out, int out_size)
{
    const float* x         = (const float*)d_in[0];
    const float* edge_attr = (const float*)d_in[1];
    const int*   edge_index= (const int*)  d_in[2];
    const int*   batch     = (const int*)  d_in[3];
    const float* w_e1      = (const float*)d_in[4];
    const float* b_e1      = (const float*)d_in[5];
    const float* w_e2      = (const float*)d_in[6];
    const float* b_e2      = (const float*)d_in[7];
    const float* root      = (const float*)d_in[8];
    const float* conv_bias = (const float*)d_in[9];
    const float* gru_wih   = (const float*)d_in[10];
    const float* gru_whh   = (const float*)d_in[11];
    const float* gru_bih   = (const float*)d_in[12];
    const float* gru_bhh   = (const float*)d_in[13];
    const float* lstm_wih  = (const float*)d_in[14];
    const float* lstm_whh  = (const float*)d_in[15];
    const float* lstm_bih  = (const float*)d_in[16];
    const float* lstm_bhh  = (const float*)d_in[17];
    const float* fc1_w     = (const float*)d_in[18];
    const float* fc1_b     = (const float*)d_in[19];
    const float* fc2_w     = (const float*)d_in[20];
    const float* fc2_b     = (const float*)d_in[21];
    float* y = (float*)d_out;

    int N = in_sizes[0] / 16;
    int E = in_sizes[1] / 4;
    int B = out_size;

    static int smem_set = 0;
    if (!smem_set) {
        cudaFuncSetAttribute(edge_kernel3, cudaFuncAttributeMaxDynamicSharedMemorySize, EK3_SMEM);
        cudaFuncSetAttribute(gru_node_kernel, cudaFuncAttributeMaxDynamicSharedMemorySize, GRU_SMEM);
        smem_set = 1;
    }

    // gru_node_kernel stays the 4th launch (ncu capture window).
    prep_kernel<<<577, 256>>>(w_e2, gru_wih, gru_whh, gru_bih, gru_bhh);
    zero_kernel<<<1024, 256>>>(N, B);
    edge_kernel3<<<(E + 127) / 128, 256, EK3_SMEM>>>(x, edge_attr, edge_index, w_e1, b_e1, b_e2, E);
    gru_node_kernel<<<(N + 63) / 64, 256, GRU_SMEM>>>(x, root, conv_bias, N);
    seg_kernel<<<(B + 1 + 127) / 128, 128>>>(batch, N, B);
    for (int i = 0; i < 3; ++i) {
        lstm_kernel<<<(B + 7) / 8, 256>>>(lstm_wih, lstm_whh, lstm_bih, lstm_bhh, B);
        attn_kernel<<<B, 128>>>(B);
    }
    readout_kernel<<<(B + 7) / 8, 64>>>(fc1_w, fc1_b, fc2_w, fc2_b, y, B);
}

// round 12
// speedup vs baseline: 4.4818x; 1.0605x over previous
#include <cuda_runtime.h>
#include <cuda_bf16.h>
#include <cuda_fp16.h>
#include <math.h>

typedef unsigned long long ull;
typedef unsigned int uint;

#define MAXN 131072
#define MAXE 262144
#define MAXB 4096

// ---------------- device scratch ----------------
__device__ float g_msum[(size_t)MAXN * 64];
__device__ float g_cnt[MAXN];              // reused as attention e-buffer later
__device__ float g_out[(size_t)MAXN * 64];
__device__ float g_S[MAXB * 192];          // per graph: [0:128]=q_star, [128:192]=hl
__device__ float g_cl[MAXB * 64];
__device__ int   g_seg[MAXB + 1];
// edge GEMM: fp16 w_e2 (single), per-chunk smem images (16 chunks x 16384 B)
__device__ unsigned char g_W2hi[16 * 16384];
// GRU GEMM: Wg fp16 smem image [256 rows x 128 B], epilogue-friendly col order
__device__ unsigned char g_GBhi[32768];
__device__ float g_gbias[256];

// ---------------- helpers ----------------
__device__ __forceinline__ float fast_sigm(float x) {
    x = fminf(fmaxf(x, -30.0f), 30.0f);
    return __fdividef(1.0f, 1.0f + __expf(-x));
}
__device__ __forceinline__ float fast_tanh(float x) {
    x = fminf(fmaxf(x, -15.0f), 15.0f);
    float t = __expf(2.0f * x);
    return 1.0f - __fdividef(2.0f, 1.0f + t);
}
__device__ __forceinline__ uint smem_u32(const void* p) {
    uint a; asm("{ .reg .u64 t; cvta.to.shared.u64 t, %1; cvt.u32.u64 %0, t; }" : "=r"(a) : "l"(p));
    return a;
}
__device__ __forceinline__ void ldsm4(uint* r, uint addr) {
    asm volatile("ldmatrix.sync.aligned.m8n8.x4.shared.b16 {%0,%1,%2,%3}, [%4];"
        : "=r"(r[0]), "=r"(r[1]), "=r"(r[2]), "=r"(r[3]) : "r"(addr));
}
__device__ __forceinline__ void mma16816(float* d, const uint* a, const uint* b) {
    asm volatile("mma.sync.aligned.m16n8k16.row.col.f32.f16.f16.f32 "
        "{%0,%1,%2,%3}, {%4,%5,%6,%7}, {%8,%9}, {%0,%1,%2,%3};"
        : "+f"(d[0]), "+f"(d[1]), "+f"(d[2]), "+f"(d[3])
        : "r"(a[0]), "r"(a[1]), "r"(a[2]), "r"(a[3]), "r"(b[0]), "r"(b[1]));
}
__device__ __forceinline__ void cp16(uint dst, const void* src) {
    asm volatile("cp.async.ca.shared.global [%0], [%1], 16;" :: "r"(dst), "l"(src));
}
__device__ __forceinline__ void red2(float* p, float a, float b) {
    asm volatile("red.global.add.v2.f32 [%0], {%1, %2};" :: "l"(p), "f"(a), "f"(b) : "memory");
}

// ---------------- zero scratch ----------------
__global__ void zero_kernel(int N, int B) {
    int idx = blockIdx.x * blockDim.x + threadIdx.x;
    int stride = gridDim.x * blockDim.x;
    float4 z4 = make_float4(0.f, 0.f, 0.f, 0.f);
    int nm4 = N * 16;
    float4* m4 = (float4*)g_msum;
    for (int i = idx; i < nm4; i += stride) m4[i] = z4;
    for (int i = idx; i < N; i += stride) g_cnt[i] = 0.0f;
    int ns = B * 192;
    for (int i = idx; i < ns; i += stride) g_S[i] = 0.0f;
    int nc = B * 64;
    for (int i = idx; i < nc; i += stride) g_cl[i] = 0.0f;
}

// ---------------- segment offsets ----------------
__global__ void seg_kernel(const int* __restrict__ batch, int N, int B) {
    int b = blockIdx.x * blockDim.x + threadIdx.x;
    if (b > B) return;
    int lo = 0, hi = N;
    while (lo < hi) { int mid = (lo + hi) >> 1; if (batch[mid] < b) lo = mid + 1; else hi = mid; }
    g_seg[b] = lo;
}

// ---------------- merged prep ----------------
// GRU col mapping (epilogue-friendly): col c -> (j, gate):
//   w=c>>6, rem=c&63, half=rem>>5, within=rem&31, tile=within>>3, colin=within&7
//   j = w*16 + tile*4 + (colin>>1); gate = half*2 + (colin&1)  [0=r,1=z,2=inn,3=hn]
__device__ __forceinline__ void gru_col_decode(int c, int& j, int& gate) {
    int w = c >> 6, rem = c & 63;
    int half = rem >> 5, within = rem & 31;
    int tile = within >> 3, colin = within & 7;
    j = w * 16 + tile * 4 + (colin >> 1);
    gate = half * 2 + (colin & 1);
}

__global__ void prep_kernel(const float* __restrict__ w_e2,
                            const float* __restrict__ wih, const float* __restrict__ whh,
                            const float* __restrict__ bih, const float* __restrict__ bhh) {
    int bid = blockIdx.x;
    if (bid < 512) {
        int idx = bid * 256 + threadIdx.x;
        int m = idx >> 10, j = idx & 1023;     // m = k, j = d*64+h
        __half hi = __float2half_rn(w_e2[idx]);
        int nc = j >> 6, r = j & 63;
        int c = m >> 3;
        int off = r * 256 + ((c ^ (r & 7)) << 4) + (m & 7) * 2;
        *(__half*)(g_W2hi + nc * 16384 + off) = hi;
    } else {
        int idx = (bid - 512) * 256 + threadIdx.x;
        if (idx < 16384) {
            int c = idx >> 6, k = idx & 63;
            int j, gate;
            gru_col_decode(c, j, gate);
            float v;
            if (gate == 0)      v = wih[j * 64 + k] + whh[j * 64 + k];
            else if (gate == 1) v = wih[(64 + j) * 64 + k] + whh[(64 + j) * 64 + k];
            else if (gate == 2) v = wih[(128 + j) * 64 + k];
            else                v = whh[(128 + j) * 64 + k];
            __half hi = __float2half_rn(v);
            int off = c * 128 + (((k >> 3) ^ (c & 7)) << 4) + (k & 7) * 2;
            *(__half*)(g_GBhi + off) = hi;
        } else if (idx < 16640) {
            int c = idx - 16384;
            int j, gate;
            gru_col_decode(c, j, gate);
            float v;
            if (gate == 0)      v = bih[j] + bhh[j];
            else if (gate == 1) v = bih[64 + j] + bhh[64 + j];
            else if (gate == 2) v = bih[128 + j];
            else                v = bhh[128 + j];
            g_gbias[c] = v;
        }
    }
}

// ---------------- edge kernel: HMMA (single-pass fp16) ----------------
#define O_A   0          // 32768 (A hid fp16, 128 rows x 256 B)
#define O_B   32768      // 2 x 16384 double buffer
#define O_XT  65536      // 8192  (xT [16][128] f32)
#define O_B2  73728      // 4096  (b_e2 1024 f32)
#define O_DST 77824      // 512
#define EK3_SMEM 78336

__global__ void __launch_bounds__(256, 2) edge_kernel3(
    const float* __restrict__ x, const float* __restrict__ edge_attr,
    const int* __restrict__ edge_index,
    const float* __restrict__ w_e1, const float* __restrict__ b_e1,
    const float* __restrict__ b_e2, int E)
{
    extern __shared__ char sm[];
    uint smb = smem_u32(sm);
    float* xT  = (float*)(sm + O_XT);
    float* b2S = (float*)(sm + O_B2);
    int*  dstS = (int*)(sm + O_DST);

    int t = threadIdx.x;
    int wid = t >> 5, lane = t & 31;
    int mw = wid & 3, nw = wid >> 2;
    int e0 = blockIdx.x * 128;

    // prefetch B chunk 0 (16 KB)
    {
        uint dst = smb + O_B + t * 16;
        const char* sh = (const char*)g_W2hi + t * 16;
        #pragma unroll
        for (int i = 0; i < 4; ++i) cp16(dst + i * 4096, sh + i * 4096);
        asm volatile("cp.async.commit_group;");
    }

    for (int i = t; i < 1024; i += 256) b2S[i] = b_e2[i];

    if (t < 128) {
        int e = e0 + t;
        int dd = -1;
        if (e < E) {
            int s = edge_index[e];
            dd = edge_index[E + e];
            const float4* xr = reinterpret_cast<const float4*>(x + (size_t)s * 16);
            #pragma unroll
            for (int q = 0; q < 4; ++q) {
                float4 v = xr[q];
                xT[(q * 4 + 0) * 128 + t] = v.x;
                xT[(q * 4 + 1) * 128 + t] = v.y;
                xT[(q * 4 + 2) * 128 + t] = v.z;
                xT[(q * 4 + 3) * 128 + t] = v.w;
            }
            atomicAdd(&g_cnt[dd], 1.0f);
        } else {
            #pragma unroll
            for (int q = 0; q < 16; ++q) xT[q * 128 + t] = 0.0f;
        }
        dstS[t] = dd;
    }

    // form A = fp16(hid)
    {
        int row = t >> 1;
        int cbase = (t & 1) * 8;
        int e = e0 + row;
        float ea0 = 0.f, ea1 = 0.f, ea2 = 0.f, ea3 = 0.f;
        if (e < E) {
            float4 ea = reinterpret_cast<const float4*>(edge_attr)[e];
            ea0 = ea.x; ea1 = ea.y; ea2 = ea.z; ea3 = ea.w;
        }
        #pragma unroll
        for (int c = cbase; c < cbase + 8; ++c) {
            uint h4[4];
            #pragma unroll
            for (int p = 0; p < 4; ++p) {
                int k0 = c * 8 + p * 2;
                float2 w0 = __ldg((const float2*)(w_e1 + k0));
                float2 w1 = __ldg((const float2*)(w_e1 + 128 + k0));
                float2 w2 = __ldg((const float2*)(w_e1 + 256 + k0));
                float2 w3 = __ldg((const float2*)(w_e1 + 384 + k0));
                float2 bb = __ldg((const float2*)(b_e1 + k0));
                float h0 = fmaf(ea3, w3.x, fmaf(ea2, w2.x, fmaf(ea1, w1.x, fmaf(ea0, w0.x, bb.x))));
                float h1 = fmaf(ea3, w3.y, fmaf(ea2, w2.y, fmaf(ea1, w1.y, fmaf(ea0, w0.y, bb.y))));
                __half2 hh = __floats2half2_rn(fmaxf(h0, 0.0f), fmaxf(h1, 0.0f));
                h4[p] = *reinterpret_cast<uint*>(&hh);
            }
            int off = row * 256 + ((c ^ (row & 7)) << 4);
            *(uint4*)(sm + O_A + off) = make_uint4(h4[0], h4[1], h4[2], h4[3]);
        }
    }

    float macc[2][4][4];
    #pragma unroll
    for (int a = 0; a < 2; ++a)
        #pragma unroll
        for (int b = 0; b < 4; ++b)
            #pragma unroll
            for (int r = 0; r < 4; ++r) macc[a][b][r] = 0.0f;

    uint smA = smb + O_A;

    for (int nc = 0; nc < 16; ++nc) {
        asm volatile("cp.async.wait_group 0;" ::: "memory");
        __syncthreads();
        uint smBbuf = smb + O_B + (nc & 1) * 16384;

        if (nc < 15) {
            uint dst = smb + O_B + ((nc + 1) & 1) * 16384 + t * 16;
            const char* sh = (const char*)g_W2hi + (nc + 1) * 16384 + t * 16;
            #pragma unroll
            for (int i = 0; i < 4; ++i) cp16(dst + i * 4096, sh + i * 4096);
            asm volatile("cp.async.commit_group;");
        }

        float dacc[2][4][4];
        #pragma unroll
        for (int a = 0; a < 2; ++a)
            #pragma unroll
            for (int b = 0; b < 4; ++b)
                #pragma unroll
                for (int r = 0; r < 4; ++r) dacc[a][b][r] = 0.0f;

        #pragma unroll
        for (int kt = 0; kt < 8; ++kt) {
            uint a0[4], a1[4];
            {
                int mi = lane >> 3;
                int arow = mw * 32 + (lane & 7) + (mi & 1) * 8;
                int ac = 2 * kt + (mi >> 1);
                uint addr = smA + arow * 256 + ((ac ^ (arow & 7)) << 4);
                ldsm4(a0, addr);
                ldsm4(a1, addr + 16 * 256);
            }
            uint bh[2][4];
            {
                int mi = lane >> 3;
                int nrow = nw * 32 + (mi >> 1) * 8 + (lane & 7);
                int bc = 2 * kt + (mi & 1);
                uint aH = smBbuf + nrow * 256 + ((bc ^ (nrow & 7)) << 4);
                ldsm4(bh[0], aH);
                ldsm4(bh[1], aH + 4096);
            }
            #pragma unroll
            for (int mt = 0; mt < 2; ++mt) {
                const uint* av = mt ? a1 : a0;
                #pragma unroll
                for (int ng = 0; ng < 2; ++ng) {
                    #pragma unroll
                    for (int s = 0; s < 2; ++s)
                        mma16816(dacc[mt][ng * 2 + s], av, &bh[ng][s * 2]);
                }
            }
        }

        // epilogue: msg += x[e,nc] * (D + b_e2)
        {
            int rb = mw * 32 + (lane >> 2);
            float xv00 = xT[nc * 128 + rb];
            float xv01 = xT[nc * 128 + rb + 8];
            float xv10 = xT[nc * 128 + rb + 16];
            float xv11 = xT[nc * 128 + rb + 24];
            #pragma unroll
            for (int mt = 0; mt < 2; ++mt) {
                float xa = mt ? xv10 : xv00;
                float xb = mt ? xv11 : xv01;
                #pragma unroll
                for (int nt = 0; nt < 4; ++nt) {
                    int col = nw * 32 + nt * 8 + 2 * (lane & 3);
                    float b0v = b2S[nc * 64 + col];
                    float b1v = b2S[nc * 64 + col + 1];
                    macc[mt][nt][0] = fmaf(xa, dacc[mt][nt][0] + b0v, macc[mt][nt][0]);
                    macc[mt][nt][1] = fmaf(xa, dacc[mt][nt][1] + b1v, macc[mt][nt][1]);
                    macc[mt][nt][2] = fmaf(xb, dacc[mt][nt][2] + b0v, macc[mt][nt][2]);
                    macc[mt][nt][3] = fmaf(xb, dacc[mt][nt][3] + b1v, macc[mt][nt][3]);
                }
            }
        }
    }

    // scatter: vectorized reductions (red.v2)
    #pragma unroll
    for (int mt = 0; mt < 2; ++mt) {
        #pragma unroll
        for (int half = 0; half < 2; ++half) {
            int row = mw * 32 + mt * 16 + (lane >> 2) + half * 8;
            int dd = dstS[row];
            if (dd < 0) continue;
            float* mr = g_msum + (size_t)dd * 64;
            #pragma unroll
            for (int nt = 0; nt < 4; ++nt) {
                int col = nw * 32 + nt * 8 + 2 * (lane & 3);
                red2(mr + col, macc[mt][nt][half * 2], macc[mt][nt][half * 2 + 1]);
            }
        }
    }
}

// ---------------- fused node + GRU x3 via HMMA (single-pass fp16, 2m x 4n grid) ----------------
#define G_HS   0        // 64 x 65 f32 = 16640 (col 64 = cnt)
#define G_AHI  16640    // 8192 (overlay: root 4096 + xS 4096 during node phase)
#define G_BHI  24832    // 32768
#define G_BIAS 57600    // 1024
#define GRU_SMEM 58624

__global__ void __launch_bounds__(256, 2) gru_node_kernel(
    const float* __restrict__ x, const float* __restrict__ root,
    const float* __restrict__ conv_bias, int N)
{
    extern __shared__ char sm2[];
    uint smb = smem_u32(sm2);
    float* hS    = (float*)(sm2 + G_HS);
    float* biasS = (float*)(sm2 + G_BIAS);
    float* rootS = (float*)(sm2 + G_AHI);          // node-phase overlay
    float* xS    = (float*)(sm2 + G_AHI + 4096);

    int t = threadIdx.x, wid = t >> 5, lane = t & 31;
    int n0 = blockIdx.x * 64;

    // stage B (32 KB) asynchronously — overlaps node phase
    {
        uint dh = smb + G_BHI + t * 16;
        const char* sh = (const char*)g_GBhi + t * 16;
        #pragma unroll
        for (int i = 0; i < 8; ++i) cp16(dh + i * 4096, sh + i * 4096);
        asm volatile("cp.async.commit_group;");
    }
    biasS[t] = g_gbias[t];

    // node-phase staging
    for (int i = t; i < 1024; i += 256) rootS[i] = root[i];
    for (int i = t; i < 1024; i += 256) {
        int r = i >> 4, d = i & 15;
        int n = n0 + r;
        xS[i] = (n < N) ? x[(size_t)n * 16 + d] : 0.0f;
    }
    if (t < 64) {
        int n = n0 + t;
        hS[t * 65 + 64] = (n < N) ? fmaxf(g_cnt[n], 1.0f) : 1.0f;
    }
    __syncthreads();

    // node update: hS = relu(msum/cnt + x@root + conv_bias)
    {
        float cbv = __ldg(conv_bias + (t & 63));
        #pragma unroll
        for (int j = 0; j < 16; ++j) {
            int idx = j * 256 + t;
            int r = idx >> 6, c = idx & 63;
            int n = n0 + r;
            float v = 0.0f;
            if (n < N) {
                float acc = cbv;
                const float* xr = xS + r * 16;
                #pragma unroll
                for (int d = 0; d < 16; ++d) acc = fmaf(xr[d], rootS[d * 64 + c], acc);
                v = fmaxf(g_msum[(size_t)n * 64 + c] / hS[r * 65 + 64] + acc, 0.0f);
            }
            hS[r * 65 + c] = v;
        }
    }
    asm volatile("cp.async.wait_group 0;" ::: "memory");
    __syncthreads();

    int mw = wid & 1, nh = wid >> 1;
    int mi = lane >> 3;
    uint smAhi = smb + G_AHI;
    uint smBh = smb + G_BHI;

    for (int step = 0; step < 3; ++step) {
        // convert hS -> fp16 A
        {
            int r = t >> 2, q = t & 3;
            const float* hr = hS + r * 65 + q * 16;
            #pragma unroll
            for (int c2 = 0; c2 < 2; ++c2) {
                uint hi4[4];
                #pragma unroll
                for (int p = 0; p < 4; ++p) {
                    __half2 hh = __floats2half2_rn(hr[c2 * 8 + p * 2], hr[c2 * 8 + p * 2 + 1]);
                    hi4[p] = *reinterpret_cast<uint*>(&hh);
                }
                int cc = q * 2 + c2;
                int off = r * 128 + ((cc ^ (r & 7)) << 4);
                *(uint4*)(sm2 + G_AHI + off) = make_uint4(hi4[0], hi4[1], hi4[2], hi4[3]);
            }
        }
        __syncthreads();

        float acc[16][4];
        #pragma unroll
        for (int i = 0; i < 16; ++i)
            #pragma unroll
            for (int j = 0; j < 4; ++j) acc[i][j] = 0.0f;

        #pragma unroll
        for (int kt = 0; kt < 4; ++kt) {
            uint a0[4], a1[4];
            {
                int arow = mw * 32 + (lane & 7) + (mi & 1) * 8;
                int ac = 2 * kt + (mi >> 1);
                uint aoff = (uint)(arow * 128 + ((ac ^ (arow & 7)) << 4));
                ldsm4(a0, smAhi + aoff);
                ldsm4(a1, smAhi + aoff + 16 * 128);
            }
            #pragma unroll
            for (int g2 = 0; g2 < 4; ++g2) {
                uint bh[4];
                int nrow = nh * 64 + g2 * 16 + (mi >> 1) * 8 + (lane & 7);
                int bc = 2 * kt + (mi & 1);
                uint boff = (uint)(nrow * 128 + ((bc ^ (nrow & 7)) << 4));
                ldsm4(bh, smBh + boff);
                mma16816(acc[0 * 8 + g2 * 2],     a0, bh);
                mma16816(acc[0 * 8 + g2 * 2 + 1], a0, bh + 2);
                mma16816(acc[1 * 8 + g2 * 2],     a1, bh);
                mma16816(acc[1 * 8 + g2 * 2 + 1], a1, bh + 2);
            }
        }
        __syncthreads();   // A reads complete before h' overwrite

        // gates -> h' (no shuffles: rz tiles 0..3 pair with inhn tiles 4..7, same lane/j)
        {
            int qj = lane & 3;
            int rb = lane >> 2;
            #pragma unroll
            for (int mt = 0; mt < 2; ++mt) {
                #pragma unroll
                for (int tp = 0; tp < 4; ++tp) {
                    float* aRZ = acc[mt * 8 + tp];
                    float* aNH = acc[mt * 8 + tp + 4];
                    int cb = nh * 64 + tp * 8 + 2 * qj;
                    float br = biasS[cb],      bz = biasS[cb + 1];
                    float bi = biasS[cb + 32], bn = biasS[cb + 33];
                    int j = nh * 16 + tp * 4 + qj;
                    int ra = mw * 32 + mt * 16 + rb;
                    {
                        float r = fast_sigm(aRZ[0] + br), z = fast_sigm(aRZ[1] + bz);
                        float nv = fast_tanh((aNH[0] + bi) + r * (aNH[1] + bn));
                        float hold = hS[ra * 65 + j];
                        hS[ra * 65 + j] = (1.0f - z) * nv + z * hold;
                    }
                    {
                        float r = fast_sigm(aRZ[2] + br), z = fast_sigm(aRZ[3] + bz);
                        float nv = fast_tanh((aNH[2] + bi) + r * (aNH[3] + bn));
                        float hold = hS[(ra + 8) * 65 + j];
                        hS[(ra + 8) * 65 + j] = (1.0f - z) * nv + z * hold;
                    }
                }
            }
        }
        __syncthreads();
    }

    // coalesced writeback
    #pragma unroll
    for (int j = 0; j < 16; ++j) {
        int idx = j * 256 + t;
        int r = idx >> 6, c = idx & 63;
        int n = n0 + r;
        if (n < N) g_out[(size_t)n * 64 + c] = hS[r * 65 + c];
    }
}

// ---------------- Set2Set LSTM step ----------------
__global__ void __launch_bounds__(256) lstm_kernel(
    const float* __restrict__ wih, const float* __restrict__ whh,
    const float* __restrict__ bih, const float* __restrict__ bhh, int B)
{
    __shared__ float wst[256 * 33];
    __shared__ float qsm[8 * 128];
    __shared__ float hsm[8 * 64];
    __shared__ float gsm[8 * 256];
    int t = threadIdx.x;
    int b0 = blockIdx.x * 8;

    for (int i = t; i < 8 * 128; i += 256) {
        int g = i >> 7, k = i & 127;
        qsm[i] = (b0 + g < B) ? g_S[(b0 + g) * 192 + k] : 0.0f;
    }
    for (int i = t; i < 8 * 64; i += 256) {
        int g = i >> 6, k = i & 63;
        hsm[i] = (b0 + g < B) ? g_S[(b0 + g) * 192 + 128 + k] : 0.0f;
    }

    float acc[8];
    float bsum = bih[t] + bhh[t];
    #pragma unroll
    for (int g = 0; g < 8; ++g) acc[g] = bsum;

    for (int c = 0; c < 4; ++c) {
        __syncthreads();
        for (int i = t; i < 8192; i += 256) {
            int j = i >> 5, kk = i & 31;
            wst[j * 33 + kk] = wih[j * 128 + c * 32 + kk];
        }
        __syncthreads();
        #pragma unroll 8
        for (int kk = 0; kk < 32; ++kk) {
            float w = wst[t * 33 + kk];
            #pragma unroll
            for (int g = 0; g < 8; ++g)
                acc[g] = fmaf(w, qsm[g * 128 + c * 32 + kk], acc[g]);
        }
    }
    for (int c = 0; c < 2; ++c) {
        __syncthreads();
        for (int i = t; i < 8192; i += 256) {
            int j = i >> 5, kk = i & 31;
            wst[j * 33 + kk] = whh[j * 64 + c * 32 + kk];
        }
        __syncthreads();
        #pragma unroll 8
        for (int kk = 0; kk < 32; ++kk) {
            float w = wst[t * 33 + kk];
            #pragma unroll
            for (int g = 0; g < 8; ++g)
                acc[g] = fmaf(w, hsm[g * 64 + c * 32 + kk], acc[g]);
        }
    }

    #pragma unroll
    for (int g = 0; g < 8; ++g) gsm[g * 256 + t] = acc[g];
    __syncthreads();

    for (int i = t; i < 8 * 64; i += 256) {
        int g = i >> 6, hh = i & 63;
        int b = b0 + g;
        if (b >= B) continue;
        float ig = fast_sigm(gsm[g * 256 + hh]);
        float fg = fast_sigm(gsm[g * 256 + 64 + hh]);
        float gg = fast_tanh(gsm[g * 256 + 128 + hh]);
        float og = fast_sigm(gsm[g * 256 + 192 + hh]);
        float cnew = fg * g_cl[b * 64 + hh] + ig * gg;
        g_cl[b * 64 + hh] = cnew;
        g_S[b * 192 + 128 + hh] = og * fast_tanh(cnew);
    }
}

// ---------------- Set2Set attention step (128 threads / graph) ----------------
__global__ void __launch_bounds__(128) attn_kernel(int B)
{
    __shared__ float qs[64];
    __shared__ float wm[4], ws[4];
    __shared__ float rgS[64];
    int t = threadIdx.x, b = blockIdx.x;
    if (t < 64) qs[t] = g_S[b * 192 + 128 + t];
    __syncthreads();
    int n0 = g_seg[b], n1 = g_seg[b + 1];
    int w = t >> 5, lid = t & 31;

    float mr = -1e30f, sr = 0.0f;
    for (int n = n0 + w; n < n1; n += 4) {
        const float* orow = g_out + (size_t)n * 64;
        float p = orow[lid] * qs[lid] + orow[32 + lid] * qs[32 + lid];
        #pragma unroll
        for (int off = 16; off; off >>= 1) p += __shfl_xor_sync(0xffffffffu, p, off);
        if (lid == 0) g_cnt[n] = p;
        if (p > mr) { sr *= __expf(mr - p); mr = p; }
        sr += __expf(p - mr);
    }
    if (lid == 0) { wm[w] = mr; ws[w] = sr; }
    __syncthreads();
    float m = fmaxf(fmaxf(wm[0], wm[1]), fmaxf(wm[2], wm[3]));
    float denom = ws[0] * __expf(wm[0] - m) + ws[1] * __expf(wm[1] - m)
                + ws[2] * __expf(wm[2] - m) + ws[3] * __expf(wm[3] - m);

    int col = t & 63, half = t >> 6;
    float rg = 0.0f;
    for (int n = n0 + half; n < n1; n += 2)
        rg = fmaf(__expf(g_cnt[n] - m), g_out[(size_t)n * 64 + col], rg);
    if (half) rgS[col] = rg;
    __syncthreads();
    if (!half) {
        rg += rgS[col];
        if (n1 > n0) rg /= denom;
        g_S[b * 192 + col]      = qs[col];
        g_S[b * 192 + 64 + col] = rg;
    }
}

// ---------------- readout ----------------
__global__ void __launch_bounds__(64) readout_kernel(
    const float* __restrict__ fc1_w, const float* __restrict__ fc1_b,
    const float* __restrict__ fc2_w, const float* __restrict__ fc2_b,
    float* __restrict__ y, int B)
{
    __shared__ float qsm[8 * 128];
    __shared__ float red[2];
    int t = threadIdx.x;
    int b0 = blockIdx.x * 8;
    for (int i = t; i < 1024; i += 64) {
        int g = i >> 7, k = i & 127;
        qsm[i] = (b0 + g < B) ? g_S[(b0 + g) * 192 + k] : 0.0f;
    }
    __syncthreads();
    float w2 = fc2_w[t];
    float b1 = fc1_b[t];
    for (int g = 0; g < 8; ++g) {
        float a = b1;
        #pragma unroll 8
        for (int k = 0; k < 128; ++k) a = fmaf(qsm[g * 128 + k], fc1_w[k * 64 + t], a);
        a = fmaxf(a, 0.0f);
        float p = a * w2;
        #pragma unroll
        for (int off = 16; off; off >>= 1) p += __shfl_xor_sync(0xffffffffu, p, off);
        if ((t & 31) == 0) red[t >> 5] = p;
        __syncthreads();
        if (t == 0 && b0 + g < B) y[b0 + g] = red[0] + red[1] + fc2_b[0];
        __syncthreads();
    }
}

// ---------------- launch ----------------
extern "C" void kernel_launch(void* const* d_in, const int* in_sizes, int n_in,
                              void* d_out, int out_size)
{
    const float* x         = (const float*)d_in[0];
    const float* edge_attr = (const float*)d_in[1];
    const int*   edge_index= (const int*)  d_in[2];
    const int*   batch     = (const int*)  d_in[3];
    const float* w_e1      = (const float*)d_in[4];
    const float* b_e1      = (const float*)d_in[5];
    const float* w_e2      = (const float*)d_in[6];
    const float* b_e2      = (const float*)d_in[7];
    const float* root      = (const float*)d_in[8];
    const float* conv_bias = (const float*)d_in[9];
    const float* gru_wih   = (const float*)d_in[10];
    const float* gru_whh   = (const float*)d_in[11];
    const float* gru_bih   = (const float*)d_in[12];
    const float* gru_bhh   = (const float*)d_in[13];
    const float* lstm_wih  = (const float*)d_in[14];
    const float* lstm_whh  = (const float*)d_in[15];
    const float* lstm_bih  = (const float*)d_in[16];
    const float* lstm_bhh  = (const float*)d_in[17];
    const float* fc1_w     = (const float*)d_in[18];
    const float* fc1_b     = (const float*)d_in[19];
    const float* fc2_w     = (const float*)d_in[20];
    const float* fc2_b     = (const float*)d_in[21];
    float* y = (float*)d_out;

    int N = in_sizes[0] / 16;
    int E = in_sizes[1] / 4;
    int B = out_size;

    static int smem_set = 0;
    if (!smem_set) {
        cudaFuncSetAttribute(edge_kernel3, cudaFuncAttributeMaxDynamicSharedMemorySize, EK3_SMEM);
        cudaFuncSetAttribute(gru_node_kernel, cudaFuncAttributeMaxDynamicSharedMemorySize, GRU_SMEM);
        smem_set = 1;
    }

    // gru_node_kernel stays the 4th launch (ncu capture window).
    prep_kernel<<<577, 256>>>(w_e2, gru_wih, gru_whh, gru_bih, gru_bhh);
    zero_kernel<<<1024, 256>>>(N, B);
    edge_kernel3<<<(E + 127) / 128, 256, EK3_SMEM>>>(x, edge_attr, edge_index, w_e1, b_e1, b_e2, E);
    gru_node_kernel<<<(N + 63) / 64, 256, GRU_SMEM>>>(x, root, conv_bias, N);
    seg_kernel<<<(B + 1 + 127) / 128, 128>>>(batch, N, B);
    for (int i = 0; i < 3; ++i) {
        lstm_kernel<<<(B + 7) / 8, 256>>>(lstm_wih, lstm_whh, lstm_bih, lstm_bhh, B);
        attn_kernel<<<B, 128>>>(B);
    }
    readout_kernel<<<(B + 7) / 8, 64>>>(fc1_w, fc1_b, fc2_w, fc2_b, y, B);
}